// round 1
// baseline (speedup 1.0000x reference)
#include <cuda_runtime.h>
#include <math.h>

#define BATCH  2
#define SEQ    2048
#define DMODEL 2048
#define NH     16
#define NKV    4
#define HD     128
#define EQKV   3072
#define TOK    (BATCH*SEQ)

// Scratch (device globals; no allocation allowed)
__device__ float g_qkv[(size_t)TOK * EQKV];      // 48 MB
__device__ float g_q  [(size_t)TOK * NH  * HD];  // 32 MB (post norm+rope, scaled)
__device__ float g_k  [(size_t)TOK * NKV * HD];  //  8 MB (post norm+rope)
__device__ float g_y  [(size_t)TOK * NH  * HD];  // 32 MB (attention output)

// ---------------------------------------------------------------------------
// SGEMM (NT): C[M,N] = A[M,K] * B[N,K]^T, row-major, M%128==N%128==0, K%8==0
// 128x128 block tile, BK=8, 256 threads, 8x8 per thread.
// ---------------------------------------------------------------------------
__global__ __launch_bounds__(256)
void sgemm_nt(const float* __restrict__ A, const float* __restrict__ Bm,
              float* __restrict__ C, int M, int N, int K)
{
    __shared__ float As[8][128];
    __shared__ float Bs[8][128];
    const int tid = threadIdx.x;
    const int tx = tid & 15, ty = tid >> 4;
    const int row0 = blockIdx.y * 128;
    const int col0 = blockIdx.x * 128;
    const int lr = tid >> 1;
    const int lk = (tid & 1) << 2;
    const float* Ap = A + (size_t)(row0 + lr) * K + lk;
    const float* Bp = Bm + (size_t)(col0 + lr) * K + lk;

    float acc[8][8];
#pragma unroll
    for (int i = 0; i < 8; ++i)
#pragma unroll
        for (int j = 0; j < 8; ++j) acc[i][j] = 0.f;

    for (int kt = 0; kt < K; kt += 8) {
        float4 a4 = *(const float4*)(Ap + kt);
        float4 b4 = *(const float4*)(Bp + kt);
        As[lk+0][lr] = a4.x; As[lk+1][lr] = a4.y;
        As[lk+2][lr] = a4.z; As[lk+3][lr] = a4.w;
        Bs[lk+0][lr] = b4.x; Bs[lk+1][lr] = b4.y;
        Bs[lk+2][lr] = b4.z; Bs[lk+3][lr] = b4.w;
        __syncthreads();
#pragma unroll
        for (int k = 0; k < 8; ++k) {
            float ar[8], br[8];
            *(float4*)&ar[0] = *(const float4*)&As[k][ty*8];
            *(float4*)&ar[4] = *(const float4*)&As[k][ty*8+4];
            *(float4*)&br[0] = *(const float4*)&Bs[k][tx*8];
            *(float4*)&br[4] = *(const float4*)&Bs[k][tx*8+4];
#pragma unroll
            for (int i = 0; i < 8; ++i)
#pragma unroll
                for (int j = 0; j < 8; ++j)
                    acc[i][j] = fmaf(ar[i], br[j], acc[i][j]);
        }
        __syncthreads();
    }
#pragma unroll
    for (int i = 0; i < 8; ++i) {
        float* cp = C + (size_t)(row0 + ty*8 + i) * N + col0 + tx*8;
        *(float4*)cp       = make_float4(acc[i][0], acc[i][1], acc[i][2], acc[i][3]);
        *(float4*)(cp + 4) = make_float4(acc[i][4], acc[i][5], acc[i][6], acc[i][7]);
    }
}

// ---------------------------------------------------------------------------
// RMSNorm + RoPE for Q and K heads. One block = (token, head). 128 threads.
// Folds softmax scale (HD^-0.5) and log2(e) into Q.
// ---------------------------------------------------------------------------
__global__ __launch_bounds__(128)
void norm_rope(const float* __restrict__ freqs,
               const float* __restrict__ qw, const float* __restrict__ kw)
{
    const int tok  = blockIdx.x;       // 0..TOK-1
    const int head = blockIdx.y;       // 0..NH+NKV-1 (first NH are Q heads)
    const int d    = threadIdx.x;      // 0..127
    const int s    = tok & (SEQ - 1);
    const bool isq = head < NH;
    const float* src = g_qkv + (size_t)tok * EQKV +
                       (isq ? head * HD : DMODEL + (head - NH) * HD);
    float x = src[d];
    float v = x * x;
#pragma unroll
    for (int o = 16; o; o >>= 1) v += __shfl_xor_sync(0xffffffffu, v, o);
    __shared__ float red[4];
    if ((d & 31) == 0) red[d >> 5] = v;
    __syncthreads();
    v = red[0] + red[1] + red[2] + red[3];
    float rs = rsqrtf(v * (1.f / HD) + 1e-5f);
    float w  = isq ? qw[d] : kw[d];
    float xn = x * rs * w;
    float cr = freqs[s * HD + (d & ~1)];
    float ci = freqs[s * HD + (d & ~1) + 1];
    float other = __shfl_xor_sync(0xffffffffu, xn, 1);
    float out = (d & 1) ? fmaf(xn, cr, other * ci)
                        : fmaf(xn, cr, -other * ci);
    if (isq) {
        const float qscale = 0.08838834764831845f * 1.44269504088896341f; // D^-0.5 * log2(e)
        g_q[(size_t)tok * (NH * HD) + head * HD + d] = out * qscale;
    } else {
        g_k[(size_t)tok * (NKV * HD) + (head - NH) * HD + d] = out;
    }
}

// ---------------------------------------------------------------------------
// Flash attention, fp32. Block = (q_tile 64, head, batch). 256 threads.
// Thread (ty=tid>>3 in 0..31, tx=tid&7): S rows {2ty,2ty+1}, S cols {tx+8cc},
// O cols {tx+8dd}. All inner-loop smem accesses bank-conflict-free.
// ---------------------------------------------------------------------------
#define QSTR 132   // row stride for Q/K/V tiles (padding)
#define SSTR 65    // row stride for P tile

__global__ __launch_bounds__(256)
void attn64()
{
    extern __shared__ float sm[];
    float* Qsm  = sm;                  // [64][QSTR]
    float* KVsm = sm + 64 * QSTR;      // K tile, then reused as V tile
    float* Ssm  = KVsm + 64 * QSTR;    // [64][SSTR] probabilities

    const int qt  = blockIdx.x;
    const int h   = blockIdx.y;
    const int b   = blockIdx.z;
    const int kvh = h >> 2;
    const int q0  = qt * 64;
    const int tid = threadIdx.x;
    const int tx  = tid & 7;
    const int ty  = tid >> 3;          // 0..31

    // Stage Q tile (coalesced float4 loads)
    for (int idx = tid; idx < 64 * 32; idx += 256) {
        int r = idx >> 5, d = (idx & 31) << 2;
        *(float4*)(Qsm + r * QSTR + d) =
            *(const float4*)(g_q + (size_t)(b * SEQ + q0 + r) * (NH * HD) + h * HD + d);
    }

    float m_i[2] = {-1e30f, -1e30f};
    float l_i[2] = {0.f, 0.f};
    float O[2][16];
#pragma unroll
    for (int rr = 0; rr < 2; ++rr)
#pragma unroll
        for (int dd = 0; dd < 16; ++dd) O[rr][dd] = 0.f;

    for (int kt = 0; kt <= qt; ++kt) {
        const int k0 = kt * 64;
        __syncthreads();  // KV buffer free from previous iteration's PV
        for (int idx = tid; idx < 64 * 32; idx += 256) {
            int r = idx >> 5, d = (idx & 31) << 2;
            *(float4*)(KVsm + r * QSTR + d) =
                *(const float4*)(g_k + (size_t)(b * SEQ + k0 + r) * (NKV * HD) + kvh * HD + d);
        }
        __syncthreads();

        // S = Q K^T (Q already carries D^-0.5 * log2e)
        float sv[2][8];
#pragma unroll
        for (int rr = 0; rr < 2; ++rr)
#pragma unroll
            for (int cc = 0; cc < 8; ++cc) sv[rr][cc] = 0.f;

        const float* qp0 = Qsm + (2 * ty + 0) * QSTR;
        const float* qp1 = Qsm + (2 * ty + 1) * QSTR;
#pragma unroll 4
        for (int k = 0; k < HD; ++k) {
            float q0v = qp0[k], q1v = qp1[k];
#pragma unroll
            for (int cc = 0; cc < 8; ++cc) {
                float kv = KVsm[(tx + 8 * cc) * QSTR + k];
                sv[0][cc] = fmaf(q0v, kv, sv[0][cc]);
                sv[1][cc] = fmaf(q1v, kv, sv[1][cc]);
            }
        }

        const bool diag = (kt == qt);
#pragma unroll
        for (int rr = 0; rr < 2; ++rr) {
            int r = 2 * ty + rr;
            float mloc = -1e30f;
#pragma unroll
            for (int cc = 0; cc < 8; ++cc) {
                if (diag && (tx + 8 * cc) > r) sv[rr][cc] = -1e30f;
                mloc = fmaxf(mloc, sv[rr][cc]);
            }
            mloc = fmaxf(mloc, __shfl_xor_sync(0xffffffffu, mloc, 1));
            mloc = fmaxf(mloc, __shfl_xor_sync(0xffffffffu, mloc, 2));
            mloc = fmaxf(mloc, __shfl_xor_sync(0xffffffffu, mloc, 4));
            float mnew = fmaxf(m_i[rr], mloc);
            float corr = exp2f(m_i[rr] - mnew);
            m_i[rr] = mnew;
            float rsum = 0.f;
#pragma unroll
            for (int cc = 0; cc < 8; ++cc) {
                float p = exp2f(sv[rr][cc] - mnew);
                Ssm[r * SSTR + tx + 8 * cc] = p;
                rsum += p;
            }
            rsum += __shfl_xor_sync(0xffffffffu, rsum, 1);
            rsum += __shfl_xor_sync(0xffffffffu, rsum, 2);
            rsum += __shfl_xor_sync(0xffffffffu, rsum, 4);
            l_i[rr] = l_i[rr] * corr + rsum;
#pragma unroll
            for (int dd = 0; dd < 16; ++dd) O[rr][dd] *= corr;
        }
        __syncthreads();  // K reads done, P writes visible

        // Stage V tile over K buffer
        for (int idx = tid; idx < 64 * 32; idx += 256) {
            int r = idx >> 5, d = (idx & 31) << 2;
            *(float4*)(KVsm + r * QSTR + d) =
                *(const float4*)(g_qkv + (size_t)(b * SEQ + k0 + r) * EQKV +
                                 (DMODEL + NKV * HD) + kvh * HD + d);
        }
        __syncthreads();

        // O += P V
        const float* pr0 = Ssm + (2 * ty + 0) * SSTR;
        const float* pr1 = Ssm + (2 * ty + 1) * SSTR;
#pragma unroll 2
        for (int j = 0; j < 64; ++j) {
            float p0 = pr0[j], p1 = pr1[j];
            const float* vp = KVsm + j * QSTR + tx;
#pragma unroll
            for (int dd = 0; dd < 16; ++dd) {
                float v = vp[8 * dd];
                O[0][dd] = fmaf(p0, v, O[0][dd]);
                O[1][dd] = fmaf(p1, v, O[1][dd]);
            }
        }
    }

#pragma unroll
    for (int rr = 0; rr < 2; ++rr) {
        float inv = 1.f / l_i[rr];
        float* yp = g_y + (size_t)(b * SEQ + q0 + 2 * ty + rr) * (NH * HD) + h * HD + tx;
#pragma unroll
        for (int dd = 0; dd < 16; ++dd)
            yp[8 * dd] = O[rr][dd] * inv;
    }
}

// ---------------------------------------------------------------------------
extern "C" void kernel_launch(void* const* d_in, const int* in_sizes, int n_in,
                              void* d_out, int out_size)
{
    const float* x    = (const float*)d_in[0];
    const float* fr   = (const float*)d_in[1];
    // d_in[2] = mask (causal; recomputed analytically)
    const float* wqkv = (const float*)d_in[3];
    const float* wo   = (const float*)d_in[4];
    const float* qw   = (const float*)d_in[5];
    const float* kw   = (const float*)d_in[6];
    float* out = (float*)d_out;

    float *qkv_p = nullptr, *y_p = nullptr;
    cudaGetSymbolAddress((void**)&qkv_p, g_qkv);
    cudaGetSymbolAddress((void**)&y_p,   g_y);

    // 1) QKV projection: [4096,2048] x [3072,2048]^T
    sgemm_nt<<<dim3(EQKV / 128, TOK / 128), 256>>>(x, wqkv, qkv_p, TOK, EQKV, DMODEL);

    // 2) RMSNorm + RoPE for Q and K heads
    norm_rope<<<dim3(TOK, NH + NKV), 128>>>(fr, qw, kw);

    // 3) Causal GQA flash attention
    const int smem = (64 * QSTR * 2 + 64 * SSTR) * (int)sizeof(float);
    cudaFuncSetAttribute(attn64, cudaFuncAttributeMaxDynamicSharedMemorySize, smem);
    attn64<<<dim3(SEQ / 64, NH, BATCH), 256, smem>>>();

    // 4) Output projection: [4096,2048] x [2048,2048]^T
    sgemm_nt<<<dim3(DMODEL / 128, TOK / 128), 256>>>(y_p, wo, out, TOK, DMODEL, DMODEL);
}

// round 2
// speedup vs baseline: 1.4182x; 1.4182x over previous
#include <cuda_runtime.h>
#include <math.h>
#include <stdint.h>

#define BATCH  2
#define SEQ    2048
#define DMODEL 2048
#define NH     16
#define NKV    4
#define HD     128
#define EQKV   3072
#define TOK    (BATCH*SEQ)

// Scratch (device globals; no allocation allowed)
__device__ float g_qkv[(size_t)TOK * EQKV];      // 48 MB
__device__ float g_q  [(size_t)TOK * NH  * HD];  // 32 MB (post norm+rope, scaled)
__device__ float g_k  [(size_t)TOK * NKV * HD];  //  8 MB (post norm+rope)
__device__ float g_y  [(size_t)TOK * NH  * HD];  // 32 MB (attention output)

// ---------------------------------------------------------------------------
// TF32 tensor-core GEMM (NT): C[M,N] = A[M,K] * B[N,K]^T, row-major.
// M%128==0, N%128==0, K%16==0. 128x128x16 tiles, 256 threads (8 warps),
// warp tile 64x32 via mma.sync.m16n8k8. Permuted smem layout so each
// thread's fragment is one LDS.128 (A) / LDS.64 (B), conflict-free.
// ---------------------------------------------------------------------------
__device__ __forceinline__ uint32_t f2tf32(float x) {
    uint32_t r;
    asm("cvt.rna.tf32.f32 %0, %1;" : "=r"(r) : "f"(x));
    return r;
}

__device__ __forceinline__ void mma_tf32(float* c, const uint32_t* a, const uint32_t* b) {
    asm volatile(
        "mma.sync.aligned.m16n8k8.row.col.f32.tf32.tf32.f32 "
        "{%0,%1,%2,%3}, {%4,%5,%6,%7}, {%8,%9}, {%0,%1,%2,%3};"
        : "+f"(c[0]), "+f"(c[1]), "+f"(c[2]), "+f"(c[3])
        : "r"(a[0]), "r"(a[1]), "r"(a[2]), "r"(a[3]),
          "r"(b[0]), "r"(b[1]));
}

__global__ __launch_bounds__(256)
void gemm_tf32(const float* __restrict__ A, const float* __restrict__ Bm,
               float* __restrict__ C, int M, int N, int K)
{
    // Permuted layouts:
    // A tile 128x16 -> [ktile(2)][mtile(8)] blocks of 128 floats:
    //   within 16x8 tile: slot = lane*4 + reg,
    //   lane = (mi&7)*4 + (ki&3), reg = (mi>>3) + ((ki>>2)<<1)
    // B tile 128x16 -> [ktile(2)][ntile(16)] blocks of 64 floats:
    //   within 8x8 tile: slot = lane*2 + reg,
    //   lane = ni*4 + (ki&3), reg = ki>>2
    __shared__ float Asm[2][2048];
    __shared__ float Bsm[2][2048];

    const int tid  = threadIdx.x;
    const int lane = tid & 31;
    const int wid  = tid >> 5;
    const int wm   = wid & 1;   // warp row (2 along M)
    const int wn   = wid >> 1;  // warp col (4 along N)
    const int row0 = blockIdx.y * 128;
    const int col0 = blockIdx.x * 128;

    // Staging: thread handles global float4's f = 2*tid, 2*tid+1.
    // f -> r = f>>2 (tile row 0..127), kq = f&3 (which float4 in the 16-wide k)
    const int r0 = (2 * tid + 0) >> 2, kq0 = (2 * tid + 0) & 3;
    const int r1 = (2 * tid + 1) >> 2, kq1 = (2 * tid + 1) & 3;
    const float* Ag0 = A  + (size_t)(row0 + r0) * K + kq0 * 4;
    const float* Ag1 = A  + (size_t)(row0 + r1) * K + kq1 * 4;
    const float* Bg0 = Bm + (size_t)(col0 + r0) * K + kq0 * 4;
    const float* Bg1 = Bm + (size_t)(col0 + r1) * K + kq1 * 4;

    float acc[4][4][4];
#pragma unroll
    for (int i = 0; i < 4; ++i)
#pragma unroll
        for (int j = 0; j < 4; ++j)
#pragma unroll
            for (int v = 0; v < 4; ++v) acc[i][j][v] = 0.f;

    const int nk = K >> 4;
    float4 av0, av1, bv0, bv1;

    // prologue: load tile 0
    av0 = *(const float4*)Ag0; av1 = *(const float4*)Ag1;
    bv0 = *(const float4*)Bg0; bv1 = *(const float4*)Bg1;

    int p = 0;
    for (int kt = 0; kt < nk; ++kt) {
        // Store staged regs (tf32-rounded) into buffer p... first iteration
        // stores into p directly; later iterations store into p before compute.
        {
            const float va0[4] = {av0.x, av0.y, av0.z, av0.w};
            const float va1[4] = {av1.x, av1.y, av1.z, av1.w};
            const float vb0[4] = {bv0.x, bv0.y, bv0.z, bv0.w};
            const float vb1[4] = {bv1.x, bv1.y, bv1.z, bv1.w};
#pragma unroll
            for (int b = 0; b < 4; ++b) {
                { // element (r0, k=kq0*4+b)
                    int k = kq0 * 4 + b, kt2 = k >> 3, ki = k & 7;
                    int mi = r0 & 15;
                    int ai = ((kt2 * 8 + (r0 >> 4)) << 7) +
                             (((mi & 7) * 4 + (ki & 3)) << 2) + (mi >> 3) + ((ki >> 2) << 1);
                    Asm[p][ai] = __uint_as_float(f2tf32(va0[b]));
                    int bi = ((kt2 * 16 + (r0 >> 3)) << 6) +
                             (((r0 & 7) * 4 + (ki & 3)) << 1) + (ki >> 2);
                    Bsm[p][bi] = __uint_as_float(f2tf32(vb0[b]));
                }
                { // element (r1, k=kq1*4+b)
                    int k = kq1 * 4 + b, kt2 = k >> 3, ki = k & 7;
                    int mi = r1 & 15;
                    int ai = ((kt2 * 8 + (r1 >> 4)) << 7) +
                             (((mi & 7) * 4 + (ki & 3)) << 2) + (mi >> 3) + ((ki >> 2) << 1);
                    Asm[p][ai] = __uint_as_float(f2tf32(va1[b]));
                    int bi = ((kt2 * 16 + (r1 >> 3)) << 6) +
                             (((r1 & 7) * 4 + (ki & 3)) << 1) + (ki >> 2);
                    Bsm[p][bi] = __uint_as_float(f2tf32(vb1[b]));
                }
            }
        }
        __syncthreads();

        // Prefetch next tile from global while computing this one
        if (kt + 1 < nk) {
            const int off = (kt + 1) << 4;
            av0 = *(const float4*)(Ag0 + off); av1 = *(const float4*)(Ag1 + off);
            bv0 = *(const float4*)(Bg0 + off); bv1 = *(const float4*)(Bg1 + off);
        }

        // Compute 2 k-steps of 8
#pragma unroll
        for (int kk = 0; kk < 2; ++kk) {
            uint32_t a[4][4], b[4][2];
#pragma unroll
            for (int i = 0; i < 4; ++i)
                *(uint4*)a[i] = *(const uint4*)&Asm[p][((kk * 8 + wm * 4 + i) << 7) + lane * 4];
#pragma unroll
            for (int j = 0; j < 4; ++j)
                *(uint2*)b[j] = *(const uint2*)&Bsm[p][((kk * 16 + wn * 4 + j) << 6) + lane * 2];
#pragma unroll
            for (int i = 0; i < 4; ++i)
#pragma unroll
                for (int j = 0; j < 4; ++j)
                    mma_tf32(acc[i][j], a[i], b[j]);
        }
        __syncthreads();   // everyone done reading buffer p before overwrite
        p ^= 1;
    }

    // Epilogue
    const int gr = lane >> 2, gc = (lane & 3) * 2;
#pragma unroll
    for (int i = 0; i < 4; ++i) {
#pragma unroll
        for (int j = 0; j < 4; ++j) {
            float* cp = C + (size_t)(row0 + wm * 64 + i * 16 + gr) * N +
                        col0 + wn * 32 + j * 8 + gc;
            *(float2*)cp            = make_float2(acc[i][j][0], acc[i][j][1]);
            *(float2*)(cp + 8 * (size_t)N) = make_float2(acc[i][j][2], acc[i][j][3]);
        }
    }
}

// ---------------------------------------------------------------------------
// RMSNorm + RoPE for Q and K heads. One block = (token, head). 128 threads.
// Folds softmax scale (HD^-0.5) and log2(e) into Q.
// ---------------------------------------------------------------------------
__global__ __launch_bounds__(128)
void norm_rope(const float* __restrict__ freqs,
               const float* __restrict__ qw, const float* __restrict__ kw)
{
    const int tok  = blockIdx.x;
    const int head = blockIdx.y;
    const int d    = threadIdx.x;
    const int s    = tok & (SEQ - 1);
    const bool isq = head < NH;
    const float* src = g_qkv + (size_t)tok * EQKV +
                       (isq ? head * HD : DMODEL + (head - NH) * HD);
    float x = src[d];
    float v = x * x;
#pragma unroll
    for (int o = 16; o; o >>= 1) v += __shfl_xor_sync(0xffffffffu, v, o);
    __shared__ float red[4];
    if ((d & 31) == 0) red[d >> 5] = v;
    __syncthreads();
    v = red[0] + red[1] + red[2] + red[3];
    float rs = rsqrtf(v * (1.f / HD) + 1e-5f);
    float w  = isq ? qw[d] : kw[d];
    float xn = x * rs * w;
    float cr = freqs[s * HD + (d & ~1)];
    float ci = freqs[s * HD + (d & ~1) + 1];
    float other = __shfl_xor_sync(0xffffffffu, xn, 1);
    float out = (d & 1) ? fmaf(xn, cr, other * ci)
                        : fmaf(xn, cr, -other * ci);
    if (isq) {
        const float qscale = 0.08838834764831845f * 1.44269504088896341f; // D^-0.5 * log2(e)
        g_q[(size_t)tok * (NH * HD) + head * HD + d] = out * qscale;
    } else {
        g_k[(size_t)tok * (NKV * HD) + (head - NH) * HD + d] = out;
    }
}

// ---------------------------------------------------------------------------
// Flash attention, fp32 (unchanged this round).
// ---------------------------------------------------------------------------
#define QSTR 132
#define SSTR 65

__global__ __launch_bounds__(256)
void attn64()
{
    extern __shared__ float sm[];
    float* Qsm  = sm;
    float* KVsm = sm + 64 * QSTR;
    float* Ssm  = KVsm + 64 * QSTR;

    const int qt  = blockIdx.x;
    const int h   = blockIdx.y;
    const int b   = blockIdx.z;
    const int kvh = h >> 2;
    const int q0  = qt * 64;
    const int tid = threadIdx.x;
    const int tx  = tid & 7;
    const int ty  = tid >> 3;

    for (int idx = tid; idx < 64 * 32; idx += 256) {
        int r = idx >> 5, d = (idx & 31) << 2;
        *(float4*)(Qsm + r * QSTR + d) =
            *(const float4*)(g_q + (size_t)(b * SEQ + q0 + r) * (NH * HD) + h * HD + d);
    }

    float m_i[2] = {-1e30f, -1e30f};
    float l_i[2] = {0.f, 0.f};
    float O[2][16];
#pragma unroll
    for (int rr = 0; rr < 2; ++rr)
#pragma unroll
        for (int dd = 0; dd < 16; ++dd) O[rr][dd] = 0.f;

    for (int kt = 0; kt <= qt; ++kt) {
        const int k0 = kt * 64;
        __syncthreads();
        for (int idx = tid; idx < 64 * 32; idx += 256) {
            int r = idx >> 5, d = (idx & 31) << 2;
            *(float4*)(KVsm + r * QSTR + d) =
                *(const float4*)(g_k + (size_t)(b * SEQ + k0 + r) * (NKV * HD) + kvh * HD + d);
        }
        __syncthreads();

        float sv[2][8];
#pragma unroll
        for (int rr = 0; rr < 2; ++rr)
#pragma unroll
            for (int cc = 0; cc < 8; ++cc) sv[rr][cc] = 0.f;

        const float* qp0 = Qsm + (2 * ty + 0) * QSTR;
        const float* qp1 = Qsm + (2 * ty + 1) * QSTR;
#pragma unroll 4
        for (int k = 0; k < HD; ++k) {
            float q0v = qp0[k], q1v = qp1[k];
#pragma unroll
            for (int cc = 0; cc < 8; ++cc) {
                float kv = KVsm[(tx + 8 * cc) * QSTR + k];
                sv[0][cc] = fmaf(q0v, kv, sv[0][cc]);
                sv[1][cc] = fmaf(q1v, kv, sv[1][cc]);
            }
        }

        const bool diag = (kt == qt);
#pragma unroll
        for (int rr = 0; rr < 2; ++rr) {
            int r = 2 * ty + rr;
            float mloc = -1e30f;
#pragma unroll
            for (int cc = 0; cc < 8; ++cc) {
                if (diag && (tx + 8 * cc) > r) sv[rr][cc] = -1e30f;
                mloc = fmaxf(mloc, sv[rr][cc]);
            }
            mloc = fmaxf(mloc, __shfl_xor_sync(0xffffffffu, mloc, 1));
            mloc = fmaxf(mloc, __shfl_xor_sync(0xffffffffu, mloc, 2));
            mloc = fmaxf(mloc, __shfl_xor_sync(0xffffffffu, mloc, 4));
            float mnew = fmaxf(m_i[rr], mloc);
            float corr = exp2f(m_i[rr] - mnew);
            m_i[rr] = mnew;
            float rsum = 0.f;
#pragma unroll
            for (int cc = 0; cc < 8; ++cc) {
                float pv = exp2f(sv[rr][cc] - mnew);
                Ssm[r * SSTR + tx + 8 * cc] = pv;
                rsum += pv;
            }
            rsum += __shfl_xor_sync(0xffffffffu, rsum, 1);
            rsum += __shfl_xor_sync(0xffffffffu, rsum, 2);
            rsum += __shfl_xor_sync(0xffffffffu, rsum, 4);
            l_i[rr] = l_i[rr] * corr + rsum;
#pragma unroll
            for (int dd = 0; dd < 16; ++dd) O[rr][dd] *= corr;
        }
        __syncthreads();

        for (int idx = tid; idx < 64 * 32; idx += 256) {
            int r = idx >> 5, d = (idx & 31) << 2;
            *(float4*)(KVsm + r * QSTR + d) =
                *(const float4*)(g_qkv + (size_t)(b * SEQ + k0 + r) * EQKV +
                                 (DMODEL + NKV * HD) + kvh * HD + d);
        }
        __syncthreads();

        const float* pr0 = Ssm + (2 * ty + 0) * SSTR;
        const float* pr1 = Ssm + (2 * ty + 1) * SSTR;
#pragma unroll 2
        for (int j = 0; j < 64; ++j) {
            float p0 = pr0[j], p1 = pr1[j];
            const float* vp = KVsm + j * QSTR + tx;
#pragma unroll
            for (int dd = 0; dd < 16; ++dd) {
                float v = vp[8 * dd];
                O[0][dd] = fmaf(p0, v, O[0][dd]);
                O[1][dd] = fmaf(p1, v, O[1][dd]);
            }
        }
    }

#pragma unroll
    for (int rr = 0; rr < 2; ++rr) {
        float inv = 1.f / l_i[rr];
        float* yp = g_y + (size_t)(b * SEQ + q0 + 2 * ty + rr) * (NH * HD) + h * HD + tx;
#pragma unroll
        for (int dd = 0; dd < 16; ++dd)
            yp[8 * dd] = O[rr][dd] * inv;
    }
}

// ---------------------------------------------------------------------------
extern "C" void kernel_launch(void* const* d_in, const int* in_sizes, int n_in,
                              void* d_out, int out_size)
{
    const float* x    = (const float*)d_in[0];
    const float* fr   = (const float*)d_in[1];
    // d_in[2] = mask (causal; recomputed analytically)
    const float* wqkv = (const float*)d_in[3];
    const float* wo   = (const float*)d_in[4];
    const float* qw   = (const float*)d_in[5];
    const float* kw   = (const float*)d_in[6];
    float* out = (float*)d_out;

    float *qkv_p = nullptr, *y_p = nullptr;
    cudaGetSymbolAddress((void**)&qkv_p, g_qkv);
    cudaGetSymbolAddress((void**)&y_p,   g_y);

    // 1) QKV projection: [4096,2048] x [3072,2048]^T  (tf32 tensor cores)
    gemm_tf32<<<dim3(EQKV / 128, TOK / 128), 256>>>(x, wqkv, qkv_p, TOK, EQKV, DMODEL);

    // 2) RMSNorm + RoPE
    norm_rope<<<dim3(TOK, NH + NKV), 128>>>(fr, qw, kw);

    // 3) Causal GQA flash attention (fp32, unchanged)
    const int smem = (64 * QSTR * 2 + 64 * SSTR) * (int)sizeof(float);
    cudaFuncSetAttribute(attn64, cudaFuncAttributeMaxDynamicSharedMemorySize, smem);
    attn64<<<dim3(SEQ / 64, NH, BATCH), 256, smem>>>();

    // 4) Output projection: [4096,2048] x [2048,2048]^T  (tf32 tensor cores)
    gemm_tf32<<<dim3(DMODEL / 128, TOK / 128), 256>>>(y_p, wo, out, TOK, DMODEL, DMODEL);
}

// round 3
// speedup vs baseline: 2.2065x; 1.5558x over previous
#include <cuda_runtime.h>
#include <math.h>
#include <stdint.h>

#define BATCH  2
#define SEQ    2048
#define DMODEL 2048
#define NH     16
#define NKV    4
#define HD     128
#define EQKV   3072
#define TOK    (BATCH*SEQ)

// Scratch (device globals; no allocation allowed)
__device__ float g_qkv[(size_t)TOK * EQKV];      // 48 MB
__device__ float g_q  [(size_t)TOK * NH  * HD];  // 32 MB (tf32-rounded, scaled)
__device__ float g_k  [(size_t)TOK * NKV * HD];  //  8 MB (tf32-rounded)
__device__ float g_y  [(size_t)TOK * NH  * HD];  // 32 MB (attention output)

__device__ __forceinline__ uint32_t f2tf32(float x) {
    uint32_t r;
    asm("cvt.rna.tf32.f32 %0, %1;" : "=r"(r) : "f"(x));
    return r;
}
__device__ __forceinline__ float rnd_tf32(float x) {
    return __uint_as_float(f2tf32(x));
}

__device__ __forceinline__ void mma_tf32(float* c, const uint32_t* a, const uint32_t* b) {
    asm volatile(
        "mma.sync.aligned.m16n8k8.row.col.f32.tf32.tf32.f32 "
        "{%0,%1,%2,%3}, {%4,%5,%6,%7}, {%8,%9}, {%0,%1,%2,%3};"
        : "+f"(c[0]), "+f"(c[1]), "+f"(c[2]), "+f"(c[3])
        : "r"(a[0]), "r"(a[1]), "r"(a[2]), "r"(a[3]),
          "r"(b[0]), "r"(b[1]));
}

// ---------------------------------------------------------------------------
// TF32 tensor-core GEMM (NT) — unchanged from R2.
// ---------------------------------------------------------------------------
__global__ __launch_bounds__(256)
void gemm_tf32(const float* __restrict__ A, const float* __restrict__ Bm,
               float* __restrict__ C, int M, int N, int K)
{
    __shared__ float Asm[2][2048];
    __shared__ float Bsm[2][2048];

    const int tid  = threadIdx.x;
    const int lane = tid & 31;
    const int wid  = tid >> 5;
    const int wm   = wid & 1;
    const int wn   = wid >> 1;
    const int row0 = blockIdx.y * 128;
    const int col0 = blockIdx.x * 128;

    const int r0 = (2 * tid + 0) >> 2, kq0 = (2 * tid + 0) & 3;
    const int r1 = (2 * tid + 1) >> 2, kq1 = (2 * tid + 1) & 3;
    const float* Ag0 = A  + (size_t)(row0 + r0) * K + kq0 * 4;
    const float* Ag1 = A  + (size_t)(row0 + r1) * K + kq1 * 4;
    const float* Bg0 = Bm + (size_t)(col0 + r0) * K + kq0 * 4;
    const float* Bg1 = Bm + (size_t)(col0 + r1) * K + kq1 * 4;

    float acc[4][4][4];
#pragma unroll
    for (int i = 0; i < 4; ++i)
#pragma unroll
        for (int j = 0; j < 4; ++j)
#pragma unroll
            for (int v = 0; v < 4; ++v) acc[i][j][v] = 0.f;

    const int nk = K >> 4;
    float4 av0, av1, bv0, bv1;
    av0 = *(const float4*)Ag0; av1 = *(const float4*)Ag1;
    bv0 = *(const float4*)Bg0; bv1 = *(const float4*)Bg1;

    int p = 0;
    for (int kt = 0; kt < nk; ++kt) {
        {
            const float va0[4] = {av0.x, av0.y, av0.z, av0.w};
            const float va1[4] = {av1.x, av1.y, av1.z, av1.w};
            const float vb0[4] = {bv0.x, bv0.y, bv0.z, bv0.w};
            const float vb1[4] = {bv1.x, bv1.y, bv1.z, bv1.w};
#pragma unroll
            for (int b = 0; b < 4; ++b) {
                {
                    int k = kq0 * 4 + b, kt2 = k >> 3, ki = k & 7;
                    int mi = r0 & 15;
                    int ai = ((kt2 * 8 + (r0 >> 4)) << 7) +
                             (((mi & 7) * 4 + (ki & 3)) << 2) + (mi >> 3) + ((ki >> 2) << 1);
                    Asm[p][ai] = rnd_tf32(va0[b]);
                    int bi = ((kt2 * 16 + (r0 >> 3)) << 6) +
                             (((r0 & 7) * 4 + (ki & 3)) << 1) + (ki >> 2);
                    Bsm[p][bi] = rnd_tf32(vb0[b]);
                }
                {
                    int k = kq1 * 4 + b, kt2 = k >> 3, ki = k & 7;
                    int mi = r1 & 15;
                    int ai = ((kt2 * 8 + (r1 >> 4)) << 7) +
                             (((mi & 7) * 4 + (ki & 3)) << 2) + (mi >> 3) + ((ki >> 2) << 1);
                    Asm[p][ai] = rnd_tf32(va1[b]);
                    int bi = ((kt2 * 16 + (r1 >> 3)) << 6) +
                             (((r1 & 7) * 4 + (ki & 3)) << 1) + (ki >> 2);
                    Bsm[p][bi] = rnd_tf32(vb1[b]);
                }
            }
        }
        __syncthreads();

        if (kt + 1 < nk) {
            const int off = (kt + 1) << 4;
            av0 = *(const float4*)(Ag0 + off); av1 = *(const float4*)(Ag1 + off);
            bv0 = *(const float4*)(Bg0 + off); bv1 = *(const float4*)(Bg1 + off);
        }

#pragma unroll
        for (int kk = 0; kk < 2; ++kk) {
            uint32_t a[4][4], b[4][2];
#pragma unroll
            for (int i = 0; i < 4; ++i)
                *(uint4*)a[i] = *(const uint4*)&Asm[p][((kk * 8 + wm * 4 + i) << 7) + lane * 4];
#pragma unroll
            for (int j = 0; j < 4; ++j)
                *(uint2*)b[j] = *(const uint2*)&Bsm[p][((kk * 16 + wn * 4 + j) << 6) + lane * 2];
#pragma unroll
            for (int i = 0; i < 4; ++i)
#pragma unroll
                for (int j = 0; j < 4; ++j)
                    mma_tf32(acc[i][j], a[i], b[j]);
        }
        __syncthreads();
        p ^= 1;
    }

    const int gr = lane >> 2, gc = (lane & 3) * 2;
#pragma unroll
    for (int i = 0; i < 4; ++i) {
#pragma unroll
        for (int j = 0; j < 4; ++j) {
            float* cp = C + (size_t)(row0 + wm * 64 + i * 16 + gr) * N +
                        col0 + wn * 32 + j * 8 + gc;
            *(float2*)cp                   = make_float2(acc[i][j][0], acc[i][j][1]);
            *(float2*)(cp + 8 * (size_t)N) = make_float2(acc[i][j][2], acc[i][j][3]);
        }
    }
}

// ---------------------------------------------------------------------------
// RMSNorm + RoPE. Now stores tf32-rounded outputs (attention consumes via MMA).
// ---------------------------------------------------------------------------
__global__ __launch_bounds__(128)
void norm_rope(const float* __restrict__ freqs,
               const float* __restrict__ qw, const float* __restrict__ kw)
{
    const int tok  = blockIdx.x;
    const int head = blockIdx.y;
    const int d    = threadIdx.x;
    const int s    = tok & (SEQ - 1);
    const bool isq = head < NH;
    const float* src = g_qkv + (size_t)tok * EQKV +
                       (isq ? head * HD : DMODEL + (head - NH) * HD);
    float x = src[d];
    float v = x * x;
#pragma unroll
    for (int o = 16; o; o >>= 1) v += __shfl_xor_sync(0xffffffffu, v, o);
    __shared__ float red[4];
    if ((d & 31) == 0) red[d >> 5] = v;
    __syncthreads();
    v = red[0] + red[1] + red[2] + red[3];
    float rs = rsqrtf(v * (1.f / HD) + 1e-5f);
    float w  = isq ? qw[d] : kw[d];
    float xn = x * rs * w;
    float cr = freqs[s * HD + (d & ~1)];
    float ci = freqs[s * HD + (d & ~1) + 1];
    float other = __shfl_xor_sync(0xffffffffu, xn, 1);
    float out = (d & 1) ? fmaf(xn, cr, other * ci)
                        : fmaf(xn, cr, -other * ci);
    if (isq) {
        const float qscale = 0.08838834764831845f * 1.44269504088896341f; // D^-0.5 * log2e
        g_q[(size_t)tok * (NH * HD) + head * HD + d] = rnd_tf32(out * qscale);
    } else {
        g_k[(size_t)tok * (NKV * HD) + (head - NH) * HD + d] = rnd_tf32(out);
    }
}

// ---------------------------------------------------------------------------
// Flash attention on tf32 mma.sync. 128 threads (4 warps), 64-q tile.
// Warp w owns q-rows [w*16, w*16+16). S: 8 accum tiles (64 cols).
// O: 16 accum tiles (128 hd cols). K/V share one smem buffer (pad 140:
// 140 ≡ 12 mod 32 makes both 12*gr+qq (K-phase) and 12*qq+gr (V-phase)
// bijective mod 32 -> conflict-free fragment loads in both phases).
// ---------------------------------------------------------------------------
#define PADQ 132
#define PADKV 140
#define PADP 68

__global__ __launch_bounds__(128, 2)
void attn_mma()
{
    extern __shared__ float sm[];
    float* Qsm  = sm;                    // [64][PADQ]
    float* KVsm = Qsm + 64 * PADQ;       // [64][PADKV]  (K, then V)
    float* Psm  = KVsm + 64 * PADKV;     // [64][PADP]

    const int qt  = (int)gridDim.x - 1 - (int)blockIdx.x;  // big tiles first
    const int h   = blockIdx.y;
    const int b   = blockIdx.z;
    const int kvh = h >> 2;
    const int q0  = qt * 64;
    const int tid = threadIdx.x;
    const int w   = tid >> 5;
    const int lane = tid & 31;
    const int gr  = lane >> 2;    // group row 0..7
    const int qq  = lane & 3;     // quad pos 0..3
    const int r0l = w * 16 + gr;  // local q-row of c0/c1
    const int r1l = r0l + 8;      // local q-row of c2/c3

    // Stage Q (already tf32-rounded & scaled)
    for (int idx = tid; idx < 2048; idx += 128) {
        int r = idx >> 5, c = (idx & 31) << 2;
        *(float4*)(Qsm + r * PADQ + c) =
            *(const float4*)(g_q + (size_t)(b * SEQ + q0 + r) * (NH * HD) + h * HD + c);
    }

    float m0 = -1e30f, m1 = -1e30f, l0 = 0.f, l1 = 0.f;
    float O[16][4];
#pragma unroll
    for (int nt = 0; nt < 16; ++nt)
#pragma unroll
        for (int v = 0; v < 4; ++v) O[nt][v] = 0.f;

    for (int kt = 0; kt <= qt; ++kt) {
        const int k0 = kt * 64;
        __syncthreads();  // prev PV done reading KV/P
        // Stage K (tf32-rounded)
        for (int idx = tid; idx < 2048; idx += 128) {
            int r = idx >> 5, c = (idx & 31) << 2;
            *(float4*)(KVsm + r * PADKV + c) =
                *(const float4*)(g_k + (size_t)(b * SEQ + k0 + r) * (NKV * HD) + kvh * HD + c);
        }
        __syncthreads();

        // S = Q K^T
        float s[8][4];
#pragma unroll
        for (int nt = 0; nt < 8; ++nt)
#pragma unroll
            for (int v = 0; v < 4; ++v) s[nt][v] = 0.f;

#pragma unroll
        for (int kk = 0; kk < 16; ++kk) {
            uint32_t a[4];
            a[0] = __float_as_uint(Qsm[r0l * PADQ + kk * 8 + qq]);
            a[1] = __float_as_uint(Qsm[r1l * PADQ + kk * 8 + qq]);
            a[2] = __float_as_uint(Qsm[r0l * PADQ + kk * 8 + qq + 4]);
            a[3] = __float_as_uint(Qsm[r1l * PADQ + kk * 8 + qq + 4]);
#pragma unroll
            for (int nt = 0; nt < 8; ++nt) {
                uint32_t bb[2];
                bb[0] = __float_as_uint(KVsm[(nt * 8 + gr) * PADKV + kk * 8 + qq]);
                bb[1] = __float_as_uint(KVsm[(nt * 8 + gr) * PADKV + kk * 8 + qq + 4]);
                mma_tf32(s[nt], a, bb);
            }
        }
        __syncthreads();  // K consumed; buffer free for V

        // Stage V (convert to tf32)
        for (int idx = tid; idx < 2048; idx += 128) {
            int r = idx >> 5, c = (idx & 31) << 2;
            float4 vv = *(const float4*)(g_qkv + (size_t)(b * SEQ + k0 + r) * EQKV +
                                         (DMODEL + NKV * HD) + kvh * HD + c);
            vv.x = rnd_tf32(vv.x); vv.y = rnd_tf32(vv.y);
            vv.z = rnd_tf32(vv.z); vv.w = rnd_tf32(vv.w);
            *(float4*)(KVsm + r * PADKV + c) = vv;
        }

        // Softmax on S fragments (registers) while V streams in
        if (kt == qt) {
#pragma unroll
            for (int nt = 0; nt < 8; ++nt) {
                int cb = nt * 8 + 2 * qq;
                if (cb     > r0l) s[nt][0] = -1e30f;
                if (cb + 1 > r0l) s[nt][1] = -1e30f;
                if (cb     > r1l) s[nt][2] = -1e30f;
                if (cb + 1 > r1l) s[nt][3] = -1e30f;
            }
        }
        float ml0 = -1e30f, ml1 = -1e30f;
#pragma unroll
        for (int nt = 0; nt < 8; ++nt) {
            ml0 = fmaxf(ml0, fmaxf(s[nt][0], s[nt][1]));
            ml1 = fmaxf(ml1, fmaxf(s[nt][2], s[nt][3]));
        }
        ml0 = fmaxf(ml0, __shfl_xor_sync(0xffffffffu, ml0, 1));
        ml0 = fmaxf(ml0, __shfl_xor_sync(0xffffffffu, ml0, 2));
        ml1 = fmaxf(ml1, __shfl_xor_sync(0xffffffffu, ml1, 1));
        ml1 = fmaxf(ml1, __shfl_xor_sync(0xffffffffu, ml1, 2));
        float mn0 = fmaxf(m0, ml0), mn1 = fmaxf(m1, ml1);
        float c0f = exp2f(m0 - mn0), c1f = exp2f(m1 - mn1);
        m0 = mn0; m1 = mn1;
        float rs0 = 0.f, rs1 = 0.f;
#pragma unroll
        for (int nt = 0; nt < 8; ++nt) {
            float p00 = rnd_tf32(exp2f(s[nt][0] - mn0));
            float p01 = rnd_tf32(exp2f(s[nt][1] - mn0));
            float p10 = rnd_tf32(exp2f(s[nt][2] - mn1));
            float p11 = rnd_tf32(exp2f(s[nt][3] - mn1));
            rs0 += p00 + p01; rs1 += p10 + p11;
            *(float2*)(Psm + r0l * PADP + nt * 8 + 2 * qq) = make_float2(p00, p01);
            *(float2*)(Psm + r1l * PADP + nt * 8 + 2 * qq) = make_float2(p10, p11);
        }
        rs0 += __shfl_xor_sync(0xffffffffu, rs0, 1);
        rs0 += __shfl_xor_sync(0xffffffffu, rs0, 2);
        rs1 += __shfl_xor_sync(0xffffffffu, rs1, 1);
        rs1 += __shfl_xor_sync(0xffffffffu, rs1, 2);
        l0 = l0 * c0f + rs0;
        l1 = l1 * c1f + rs1;
#pragma unroll
        for (int nt = 0; nt < 16; ++nt) {
            O[nt][0] *= c0f; O[nt][1] *= c0f;
            O[nt][2] *= c1f; O[nt][3] *= c1f;
        }
        __syncthreads();  // V + P ready

        // O += P V
#pragma unroll
        for (int kk = 0; kk < 8; ++kk) {
            uint32_t a[4];
            a[0] = __float_as_uint(Psm[r0l * PADP + kk * 8 + qq]);
            a[1] = __float_as_uint(Psm[r1l * PADP + kk * 8 + qq]);
            a[2] = __float_as_uint(Psm[r0l * PADP + kk * 8 + qq + 4]);
            a[3] = __float_as_uint(Psm[r1l * PADP + kk * 8 + qq + 4]);
#pragma unroll
            for (int nt = 0; nt < 16; ++nt) {
                uint32_t bb[2];
                bb[0] = __float_as_uint(KVsm[(kk * 8 + qq) * PADKV + nt * 8 + gr]);
                bb[1] = __float_as_uint(KVsm[(kk * 8 + qq + 4) * PADKV + nt * 8 + gr]);
                mma_tf32(O[nt], a, bb);
            }
        }
    }

    // Epilogue: normalize and store
    float inv0 = 1.f / l0, inv1 = 1.f / l1;
    float* y0 = g_y + (size_t)(b * SEQ + q0 + r0l) * (NH * HD) + h * HD;
    float* y1 = g_y + (size_t)(b * SEQ + q0 + r1l) * (NH * HD) + h * HD;
#pragma unroll
    for (int nt = 0; nt < 16; ++nt) {
        *(float2*)(y0 + nt * 8 + 2 * qq) = make_float2(O[nt][0] * inv0, O[nt][1] * inv0);
        *(float2*)(y1 + nt * 8 + 2 * qq) = make_float2(O[nt][2] * inv1, O[nt][3] * inv1);
    }
}

// ---------------------------------------------------------------------------
extern "C" void kernel_launch(void* const* d_in, const int* in_sizes, int n_in,
                              void* d_out, int out_size)
{
    const float* x    = (const float*)d_in[0];
    const float* fr   = (const float*)d_in[1];
    // d_in[2] = mask (causal; recomputed analytically)
    const float* wqkv = (const float*)d_in[3];
    const float* wo   = (const float*)d_in[4];
    const float* qw   = (const float*)d_in[5];
    const float* kw   = (const float*)d_in[6];
    float* out = (float*)d_out;

    float *qkv_p = nullptr, *y_p = nullptr;
    cudaGetSymbolAddress((void**)&qkv_p, g_qkv);
    cudaGetSymbolAddress((void**)&y_p,   g_y);

    // 1) QKV projection (tf32 tensor cores)
    gemm_tf32<<<dim3(EQKV / 128, TOK / 128), 256>>>(x, wqkv, qkv_p, TOK, EQKV, DMODEL);

    // 2) RMSNorm + RoPE (outputs tf32-rounded)
    norm_rope<<<dim3(TOK, NH + NKV), 128>>>(fr, qw, kw);

    // 3) Causal GQA flash attention (tf32 tensor cores)
    const int smem = (64 * PADQ + 64 * PADKV + 64 * PADP) * (int)sizeof(float);
    cudaFuncSetAttribute(attn_mma, cudaFuncAttributeMaxDynamicSharedMemorySize, smem);
    attn_mma<<<dim3(SEQ / 64, NH, BATCH), 128, smem>>>();

    // 4) Output projection (tf32 tensor cores)
    gemm_tf32<<<dim3(DMODEL / 128, TOK / 128), 256>>>(y_p, wo, out, TOK, DMODEL, DMODEL);
}

// round 5
// speedup vs baseline: 3.3614x; 1.5234x over previous
#include <cuda_runtime.h>
#include <math.h>
#include <stdint.h>

#define BATCH  2
#define SEQ    2048
#define DMODEL 2048
#define NH     16
#define NKV    4
#define HD     128
#define EQKV   3072
#define TOK    (BATCH*SEQ)

// Scratch (device globals; no allocation allowed)
__device__ float g_qkv [(size_t)TOK * EQKV];     // 48 MB
__device__ float g_q   [(size_t)TOK * NH  * HD]; // 32 MB
__device__ float g_k   [(size_t)TOK * NKV * HD]; //  8 MB
__device__ float g_y   [(size_t)TOK * NH  * HD]; // 32 MB (tf32-rounded)
__device__ float g_xr  [(size_t)TOK * DMODEL];   // 32 MB (tf32-rounded x)
__device__ float g_wqkvr[(size_t)EQKV * DMODEL]; // 24 MB
__device__ float g_wor [(size_t)DMODEL * NH * HD]; // 16 MB

__device__ __forceinline__ uint32_t f2tf32(float x) {
    uint32_t r;
    asm("cvt.rna.tf32.f32 %0, %1;" : "=r"(r) : "f"(x));
    return r;
}
__device__ __forceinline__ float rnd_tf32(float x) {
    return __uint_as_float(f2tf32(x));
}
__device__ __forceinline__ uint32_t s2u(const void* p) {
    uint32_t a;
    asm("{ .reg .u64 t; cvta.to.shared.u64 t, %1; cvt.u32.u64 %0, t; }"
        : "=r"(a) : "l"(p));
    return a;
}
__device__ __forceinline__ void mma_tf32(float* c, const uint32_t* a, const uint32_t* b) {
    asm volatile(
        "mma.sync.aligned.m16n8k8.row.col.f32.tf32.tf32.f32 "
        "{%0,%1,%2,%3}, {%4,%5,%6,%7}, {%8,%9}, {%0,%1,%2,%3};"
        : "+f"(c[0]), "+f"(c[1]), "+f"(c[2]), "+f"(c[3])
        : "r"(a[0]), "r"(a[1]), "r"(a[2]), "r"(a[3]),
          "r"(b[0]), "r"(b[1]));
}
__device__ __forceinline__ void cp16(uint32_t smem_dst, const float* gptr) {
    asm volatile("cp.async.cg.shared.global [%0], [%1], 16;"
                 :: "r"(smem_dst), "l"(gptr) : "memory");
}
#define CP_COMMIT() asm volatile("cp.async.commit_group;" ::: "memory")
#define CP_WAIT1()  asm volatile("cp.async.wait_group 1;" ::: "memory")

// ---------------------------------------------------------------------------
// Elementwise tf32 pre-round: dst[i] = rna_tf32(src[i]). n % 1024 == 0.
// ---------------------------------------------------------------------------
__global__ __launch_bounds__(256)
void pre_round(const float* __restrict__ src, float* __restrict__ dst)
{
    size_t i = ((size_t)blockIdx.x * 256 + threadIdx.x) * 4;
    float4 v = *(const float4*)(src + i);
    v.x = rnd_tf32(v.x); v.y = rnd_tf32(v.y);
    v.z = rnd_tf32(v.z); v.w = rnd_tf32(v.w);
    *(float4*)(dst + i) = v;
}

// ---------------------------------------------------------------------------
// TF32 mma.sync GEMM (NT) with cp.async 3-stage pipeline.
// C[M,N] = A[M,K]*B[N,K]^T, all row-major, A/B PRE-ROUNDED to tf32.
// 128x128 CTA tile, BK=16, 256 threads (8 warps), warp tile 64x32.
// smem row stride 20 words -> conflict-free scalar fragment LDS.
// ---------------------------------------------------------------------------
#define GSTR 20
#define GTILE (128 * GSTR)       // 2560 floats per stage per matrix
#define NSTAGE 3
#define GSM_TOTAL (NSTAGE * 2 * GTILE * 4)   // 61440 B

__global__ __launch_bounds__(256)
void gemm_cp(const float* __restrict__ A, const float* __restrict__ Bm,
             float* __restrict__ C, int M, int N, int K)
{
    extern __shared__ float sm[];
    float* As = sm;                      // [NSTAGE][GTILE]
    float* Bs = sm + NSTAGE * GTILE;

    const int tid  = threadIdx.x;
    const int lane = tid & 31;
    const int wid  = tid >> 5;
    const int wm   = wid & 1;
    const int wn   = wid >> 1;
    const int gr   = lane >> 2;
    const int qq   = lane & 3;
    const int row0 = blockIdx.y * 128;
    const int col0 = blockIdx.x * 128;

    // staging: thread covers f = tid and f = tid+256; r = f>>2, kq = f&3
    const int r0 = tid >> 2,        kq0 = tid & 3;
    const int r1 = (tid + 256) >> 2, kq1 = tid & 3;  // same kq, r+64
    const float* Ag0 = A  + (size_t)(row0 + r0) * K + kq0 * 4;
    const float* Ag1 = A  + (size_t)(row0 + r1) * K + kq1 * 4;
    const float* Bg0 = Bm + (size_t)(col0 + r0) * K + kq0 * 4;
    const float* Bg1 = Bm + (size_t)(col0 + r1) * K + kq1 * 4;
    const uint32_t sA = s2u(As), sB = s2u(Bs);
    const uint32_t soff0 = (uint32_t)(r0 * GSTR + kq0 * 4) * 4;
    const uint32_t soff1 = (uint32_t)(r1 * GSTR + kq1 * 4) * 4;

    float acc[4][4][4];
#pragma unroll
    for (int i = 0; i < 4; ++i)
#pragma unroll
        for (int j = 0; j < 4; ++j)
#pragma unroll
            for (int v = 0; v < 4; ++v) acc[i][j][v] = 0.f;

    const int nk = K >> 4;

    // prologue: stages 0 and 1
#pragma unroll
    for (int s = 0; s < 2; ++s) {
        const int kc = s << 4;
        const uint32_t ba = sA + s * GTILE * 4, bb = sB + s * GTILE * 4;
        cp16(ba + soff0, Ag0 + kc); cp16(ba + soff1, Ag1 + kc);
        cp16(bb + soff0, Bg0 + kc); cp16(bb + soff1, Bg1 + kc);
        CP_COMMIT();
    }

    int buf = 0;
    for (int kt = 0; kt < nk; ++kt) {
        CP_WAIT1();
        __syncthreads();

        const float* Ab = As + buf * GTILE;
        const float* Bb = Bs + buf * GTILE;
#pragma unroll
        for (int kk = 0; kk < 2; ++kk) {
            const int kb = kk * 8;
            uint32_t a[4][4], b[4][2];
#pragma unroll
            for (int i = 0; i < 4; ++i) {
                int m0 = wm * 64 + i * 16 + gr;
                a[i][0] = __float_as_uint(Ab[m0 * GSTR + kb + qq]);
                a[i][1] = __float_as_uint(Ab[(m0 + 8) * GSTR + kb + qq]);
                a[i][2] = __float_as_uint(Ab[m0 * GSTR + kb + qq + 4]);
                a[i][3] = __float_as_uint(Ab[(m0 + 8) * GSTR + kb + qq + 4]);
            }
#pragma unroll
            for (int j = 0; j < 4; ++j) {
                int n0 = wn * 32 + j * 8 + gr;
                b[j][0] = __float_as_uint(Bb[n0 * GSTR + kb + qq]);
                b[j][1] = __float_as_uint(Bb[n0 * GSTR + kb + qq + 4]);
            }
#pragma unroll
            for (int i = 0; i < 4; ++i)
#pragma unroll
                for (int j = 0; j < 4; ++j)
                    mma_tf32(acc[i][j], a[i], b[j]);
        }
        __syncthreads();   // all warps done with buf before overwrite

        if (kt + 2 < nk) {
            const int s = (kt + 2) % NSTAGE;
            const int kc = (kt + 2) << 4;
            const uint32_t ba = sA + s * GTILE * 4, bb = sB + s * GTILE * 4;
            cp16(ba + soff0, Ag0 + kc); cp16(ba + soff1, Ag1 + kc);
            cp16(bb + soff0, Bg0 + kc); cp16(bb + soff1, Bg1 + kc);
        }
        CP_COMMIT();
        buf = (buf + 1) % NSTAGE;
    }

    const int egr = lane >> 2, egc = (lane & 3) * 2;
#pragma unroll
    for (int i = 0; i < 4; ++i) {
#pragma unroll
        for (int j = 0; j < 4; ++j) {
            float* cp = C + (size_t)(row0 + wm * 64 + i * 16 + egr) * N +
                        col0 + wn * 32 + j * 8 + egc;
            *(float2*)cp                   = make_float2(acc[i][j][0], acc[i][j][1]);
            *(float2*)(cp + 8 * (size_t)N) = make_float2(acc[i][j][2], acc[i][j][3]);
        }
    }
}

// ---------------------------------------------------------------------------
// RMSNorm + RoPE (tf32-rounded outputs).
// ---------------------------------------------------------------------------
__global__ __launch_bounds__(128)
void norm_rope(const float* __restrict__ freqs,
               const float* __restrict__ qw, const float* __restrict__ kw)
{
    const int tok  = blockIdx.x;
    const int head = blockIdx.y;
    const int d    = threadIdx.x;
    const int s    = tok & (SEQ - 1);
    const bool isq = head < NH;
    const float* src = g_qkv + (size_t)tok * EQKV +
                       (isq ? head * HD : DMODEL + (head - NH) * HD);
    float x = src[d];
    float v = x * x;
#pragma unroll
    for (int o = 16; o; o >>= 1) v += __shfl_xor_sync(0xffffffffu, v, o);
    __shared__ float red[4];
    if ((d & 31) == 0) red[d >> 5] = v;
    __syncthreads();
    v = red[0] + red[1] + red[2] + red[3];
    float rs = rsqrtf(v * (1.f / HD) + 1e-5f);
    float w  = isq ? qw[d] : kw[d];
    float xn = x * rs * w;
    float cr = freqs[s * HD + (d & ~1)];
    float ci = freqs[s * HD + (d & ~1) + 1];
    float other = __shfl_xor_sync(0xffffffffu, xn, 1);
    float out = (d & 1) ? fmaf(xn, cr, other * ci)
                        : fmaf(xn, cr, -other * ci);
    if (isq) {
        const float qscale = 0.08838834764831845f * 1.44269504088896341f;
        g_q[(size_t)tok * (NH * HD) + head * HD + d] = rnd_tf32(out * qscale);
    } else {
        g_k[(size_t)tok * (NKV * HD) + (head - NH) * HD + d] = rnd_tf32(out);
    }
}

// ---------------------------------------------------------------------------
// Flash attention on tf32 mma.sync (R3 design; epilogue now tf32-rounds y).
// ---------------------------------------------------------------------------
#define PADQ 132
#define PADKV 140
#define PADP 68

__global__ __launch_bounds__(128, 2)
void attn_mma()
{
    extern __shared__ float smf[];
    float* Qsm  = smf;
    float* KVsm = Qsm + 64 * PADQ;
    float* Psm  = KVsm + 64 * PADKV;

    const int qt  = (int)gridDim.x - 1 - (int)blockIdx.x;
    const int h   = blockIdx.y;
    const int b   = blockIdx.z;
    const int kvh = h >> 2;
    const int q0  = qt * 64;
    const int tid = threadIdx.x;
    const int w   = tid >> 5;
    const int lane = tid & 31;
    const int gr  = lane >> 2;
    const int qq  = lane & 3;
    const int r0l = w * 16 + gr;
    const int r1l = r0l + 8;

    for (int idx = tid; idx < 2048; idx += 128) {
        int r = idx >> 5, c = (idx & 31) << 2;
        *(float4*)(Qsm + r * PADQ + c) =
            *(const float4*)(g_q + (size_t)(b * SEQ + q0 + r) * (NH * HD) + h * HD + c);
    }

    float m0 = -1e30f, m1 = -1e30f, l0 = 0.f, l1 = 0.f;
    float O[16][4];
#pragma unroll
    for (int nt = 0; nt < 16; ++nt)
#pragma unroll
        for (int v = 0; v < 4; ++v) O[nt][v] = 0.f;

    for (int kt = 0; kt <= qt; ++kt) {
        const int k0 = kt * 64;
        __syncthreads();
        for (int idx = tid; idx < 2048; idx += 128) {
            int r = idx >> 5, c = (idx & 31) << 2;
            *(float4*)(KVsm + r * PADKV + c) =
                *(const float4*)(g_k + (size_t)(b * SEQ + k0 + r) * (NKV * HD) + kvh * HD + c);
        }
        __syncthreads();

        float s[8][4];
#pragma unroll
        for (int nt = 0; nt < 8; ++nt)
#pragma unroll
            for (int v = 0; v < 4; ++v) s[nt][v] = 0.f;

#pragma unroll
        for (int kk = 0; kk < 16; ++kk) {
            uint32_t a[4];
            a[0] = __float_as_uint(Qsm[r0l * PADQ + kk * 8 + qq]);
            a[1] = __float_as_uint(Qsm[r1l * PADQ + kk * 8 + qq]);
            a[2] = __float_as_uint(Qsm[r0l * PADQ + kk * 8 + qq + 4]);
            a[3] = __float_as_uint(Qsm[r1l * PADQ + kk * 8 + qq + 4]);
#pragma unroll
            for (int nt = 0; nt < 8; ++nt) {
                uint32_t bb[2];
                bb[0] = __float_as_uint(KVsm[(nt * 8 + gr) * PADKV + kk * 8 + qq]);
                bb[1] = __float_as_uint(KVsm[(nt * 8 + gr) * PADKV + kk * 8 + qq + 4]);
                mma_tf32(s[nt], a, bb);
            }
        }
        __syncthreads();

        for (int idx = tid; idx < 2048; idx += 128) {
            int r = idx >> 5, c = (idx & 31) << 2;
            float4 vv = *(const float4*)(g_qkv + (size_t)(b * SEQ + k0 + r) * EQKV +
                                         (DMODEL + NKV * HD) + kvh * HD + c);
            vv.x = rnd_tf32(vv.x); vv.y = rnd_tf32(vv.y);
            vv.z = rnd_tf32(vv.z); vv.w = rnd_tf32(vv.w);
            *(float4*)(KVsm + r * PADKV + c) = vv;
        }

        if (kt == qt) {
#pragma unroll
            for (int nt = 0; nt < 8; ++nt) {
                int cb = nt * 8 + 2 * qq;
                if (cb     > r0l) s[nt][0] = -1e30f;
                if (cb + 1 > r0l) s[nt][1] = -1e30f;
                if (cb     > r1l) s[nt][2] = -1e30f;
                if (cb + 1 > r1l) s[nt][3] = -1e30f;
            }
        }
        float ml0 = -1e30f, ml1 = -1e30f;
#pragma unroll
        for (int nt = 0; nt < 8; ++nt) {
            ml0 = fmaxf(ml0, fmaxf(s[nt][0], s[nt][1]));
            ml1 = fmaxf(ml1, fmaxf(s[nt][2], s[nt][3]));
        }
        ml0 = fmaxf(ml0, __shfl_xor_sync(0xffffffffu, ml0, 1));
        ml0 = fmaxf(ml0, __shfl_xor_sync(0xffffffffu, ml0, 2));
        ml1 = fmaxf(ml1, __shfl_xor_sync(0xffffffffu, ml1, 1));
        ml1 = fmaxf(ml1, __shfl_xor_sync(0xffffffffu, ml1, 2));
        float mn0 = fmaxf(m0, ml0), mn1 = fmaxf(m1, ml1);
        float c0f = exp2f(m0 - mn0), c1f = exp2f(m1 - mn1);
        m0 = mn0; m1 = mn1;
        float rs0 = 0.f, rs1 = 0.f;
#pragma unroll
        for (int nt = 0; nt < 8; ++nt) {
            float p00 = rnd_tf32(exp2f(s[nt][0] - mn0));
            float p01 = rnd_tf32(exp2f(s[nt][1] - mn0));
            float p10 = rnd_tf32(exp2f(s[nt][2] - mn1));
            float p11 = rnd_tf32(exp2f(s[nt][3] - mn1));
            rs0 += p00 + p01; rs1 += p10 + p11;
            *(float2*)(Psm + r0l * PADP + nt * 8 + 2 * qq) = make_float2(p00, p01);
            *(float2*)(Psm + r1l * PADP + nt * 8 + 2 * qq) = make_float2(p10, p11);
        }
        rs0 += __shfl_xor_sync(0xffffffffu, rs0, 1);
        rs0 += __shfl_xor_sync(0xffffffffu, rs0, 2);
        rs1 += __shfl_xor_sync(0xffffffffu, rs1, 1);
        rs1 += __shfl_xor_sync(0xffffffffu, rs1, 2);
        l0 = l0 * c0f + rs0;
        l1 = l1 * c1f + rs1;
#pragma unroll
        for (int nt = 0; nt < 16; ++nt) {
            O[nt][0] *= c0f; O[nt][1] *= c0f;
            O[nt][2] *= c1f; O[nt][3] *= c1f;
        }
        __syncthreads();

#pragma unroll
        for (int kk = 0; kk < 8; ++kk) {
            uint32_t a[4];
            a[0] = __float_as_uint(Psm[r0l * PADP + kk * 8 + qq]);
            a[1] = __float_as_uint(Psm[r1l * PADP + kk * 8 + qq]);
            a[2] = __float_as_uint(Psm[r0l * PADP + kk * 8 + qq + 4]);
            a[3] = __float_as_uint(Psm[r1l * PADP + kk * 8 + qq + 4]);
#pragma unroll
            for (int nt = 0; nt < 16; ++nt) {
                uint32_t bb[2];
                bb[0] = __float_as_uint(KVsm[(kk * 8 + qq) * PADKV + nt * 8 + gr]);
                bb[1] = __float_as_uint(KVsm[(kk * 8 + qq + 4) * PADKV + nt * 8 + gr]);
                mma_tf32(O[nt], a, bb);
            }
        }
    }

    float inv0 = 1.f / l0, inv1 = 1.f / l1;
    float* y0 = g_y + (size_t)(b * SEQ + q0 + r0l) * (NH * HD) + h * HD;
    float* y1 = g_y + (size_t)(b * SEQ + q0 + r1l) * (NH * HD) + h * HD;
#pragma unroll
    for (int nt = 0; nt < 16; ++nt) {
        *(float2*)(y0 + nt * 8 + 2 * qq) =
            make_float2(rnd_tf32(O[nt][0] * inv0), rnd_tf32(O[nt][1] * inv0));
        *(float2*)(y1 + nt * 8 + 2 * qq) =
            make_float2(rnd_tf32(O[nt][2] * inv1), rnd_tf32(O[nt][3] * inv1));
    }
}

// ---------------------------------------------------------------------------
extern "C" void kernel_launch(void* const* d_in, const int* in_sizes, int n_in,
                              void* d_out, int out_size)
{
    const float* x    = (const float*)d_in[0];
    const float* fr   = (const float*)d_in[1];
    const float* wqkv = (const float*)d_in[3];
    const float* wo   = (const float*)d_in[4];
    const float* qw   = (const float*)d_in[5];
    const float* kw   = (const float*)d_in[6];
    float* out = (float*)d_out;

    float *qkv_p, *y_p, *xr_p, *wqkvr_p, *wor_p;
    cudaGetSymbolAddress((void**)&qkv_p,   g_qkv);
    cudaGetSymbolAddress((void**)&y_p,     g_y);
    cudaGetSymbolAddress((void**)&xr_p,    g_xr);
    cudaGetSymbolAddress((void**)&wqkvr_p, g_wqkvr);
    cudaGetSymbolAddress((void**)&wor_p,   g_wor);

    // 0) Pre-round inputs/weights to tf32 (enables cp.async hot loops)
    pre_round<<<(TOK * DMODEL) / 1024, 256>>>(x, xr_p);
    pre_round<<<(EQKV * DMODEL) / 1024, 256>>>(wqkv, wqkvr_p);
    pre_round<<<(DMODEL * NH * HD) / 1024, 256>>>(wo, wor_p);

    cudaFuncSetAttribute(gemm_cp, cudaFuncAttributeMaxDynamicSharedMemorySize, GSM_TOTAL);

    // 1) QKV projection
    gemm_cp<<<dim3(EQKV / 128, TOK / 128), 256, GSM_TOTAL>>>(xr_p, wqkvr_p, qkv_p, TOK, EQKV, DMODEL);

    // 2) RMSNorm + RoPE
    norm_rope<<<dim3(TOK, NH + NKV), 128>>>(fr, qw, kw);

    // 3) Causal GQA flash attention
    const int asmem = (64 * PADQ + 64 * PADKV + 64 * PADP) * (int)sizeof(float);
    cudaFuncSetAttribute(attn_mma, cudaFuncAttributeMaxDynamicSharedMemorySize, asmem);
    attn_mma<<<dim3(SEQ / 64, NH, BATCH), 128, asmem>>>();

    // 4) Output projection
    gemm_cp<<<dim3(DMODEL / 128, TOK / 128), 256, GSM_TOTAL>>>(y_p, wor_p, out, TOK, DMODEL, DMODEL);
}

// round 6
// speedup vs baseline: 3.7833x; 1.1255x over previous
#include <cuda_runtime.h>
#include <math.h>
#include <stdint.h>

#define BATCH  2
#define SEQ    2048
#define DMODEL 2048
#define NH     16
#define NKV    4
#define HD     128
#define EQKV   3072
#define TOK    (BATCH*SEQ)

// Scratch (device globals; no allocation allowed)
__device__ float g_qkv [(size_t)TOK * EQKV];       // 48 MB (plain layout)
__device__ float g_q   [(size_t)TOK * NH  * HD];   // 32 MB (tf32, k-pair-permuted hd)
__device__ float g_k   [(size_t)TOK * NKV * HD];   //  8 MB (tf32, k-pair-permuted hd)
__device__ float g_y   [(size_t)TOK * NH  * HD];   // 32 MB (tf32, k-pair-permuted)
__device__ float g_xr  [(size_t)TOK * DMODEL];     // 32 MB (tf32, k-pair-permuted)
__device__ float g_wqkvr[(size_t)EQKV * DMODEL];   // 24 MB (tf32, k-pair-permuted)
__device__ float g_wor [(size_t)DMODEL * NH * HD]; // 16 MB (tf32, k-pair-permuted)

__device__ __forceinline__ uint32_t f2tf32(float x) {
    uint32_t r;
    asm("cvt.rna.tf32.f32 %0, %1;" : "=r"(r) : "f"(x));
    return r;
}
__device__ __forceinline__ float rnd_tf32(float x) {
    return __uint_as_float(f2tf32(x));
}
__device__ __forceinline__ uint32_t s2u(const void* p) {
    uint32_t a;
    asm("{ .reg .u64 t; cvta.to.shared.u64 t, %1; cvt.u32.u64 %0, t; }"
        : "=r"(a) : "l"(p));
    return a;
}
__device__ __forceinline__ void mma_tf32(float* c, const uint32_t* a, const uint32_t* b) {
    asm volatile(
        "mma.sync.aligned.m16n8k8.row.col.f32.tf32.tf32.f32 "
        "{%0,%1,%2,%3}, {%4,%5,%6,%7}, {%8,%9}, {%0,%1,%2,%3};"
        : "+f"(c[0]), "+f"(c[1]), "+f"(c[2]), "+f"(c[3])
        : "r"(a[0]), "r"(a[1]), "r"(a[2]), "r"(a[3]),
          "r"(b[0]), "r"(b[1]));
}
__device__ __forceinline__ void cp16(uint32_t smem_dst, const float* gptr) {
    asm volatile("cp.async.cg.shared.global [%0], [%1], 16;"
                 :: "r"(smem_dst), "l"(gptr) : "memory");
}
#define CP_COMMIT() asm volatile("cp.async.commit_group;" ::: "memory")
#define CP_WAIT1()  asm volatile("cp.async.wait_group 1;" ::: "memory")

// ---------------------------------------------------------------------------
// Pre-round to tf32 AND k-pair-permute each 8-wide group of the last dim:
// source col r in group -> dest ((r&3)*2 + (r>>2)). n % 1024 == 0, rows %8==0.
// ---------------------------------------------------------------------------
__global__ __launch_bounds__(256)
void pre_round_perm(const float* __restrict__ src, float* __restrict__ dst)
{
    size_t i = ((size_t)blockIdx.x * 256 + threadIdx.x) * 4;
    float4 v = *(const float4*)(src + i);
    size_t base = i & ~(size_t)7;
    int odd = (int)((i >> 2) & 1);   // second half of 8-group -> odd slots
    dst[base + odd + 0] = rnd_tf32(v.x);
    dst[base + odd + 2] = rnd_tf32(v.y);
    dst[base + odd + 4] = rnd_tf32(v.z);
    dst[base + odd + 6] = rnd_tf32(v.w);
}

// ---------------------------------------------------------------------------
// TF32 mma.sync GEMM (NT), cp.async 3-stage, pair-permuted K layout.
// C[M,N] = A[M,K]*B[N,K]^T (both operands pre-permuted along K identically).
// 128x128 CTA tile, BK=16, 256 threads, warp tile 64x32.
// smem stride 24 words -> conflict-free LDS.64 fragment loads.
// ---------------------------------------------------------------------------
#define GSTR 24
#define GTILE (128 * GSTR)
#define NSTAGE 3
#define GSM_TOTAL (NSTAGE * 2 * GTILE * 4)   // 73728 B

__global__ __launch_bounds__(256)
void gemm_cp(const float* __restrict__ A, const float* __restrict__ Bm,
             float* __restrict__ C, int M, int N, int K)
{
    extern __shared__ float sm[];
    float* As = sm;
    float* Bs = sm + NSTAGE * GTILE;

    const int tid  = threadIdx.x;
    const int lane = tid & 31;
    const int wid  = tid >> 5;
    const int wm   = wid & 1;
    const int wn   = wid >> 1;
    const int gr   = lane >> 2;
    const int qq   = lane & 3;
    const int row0 = blockIdx.y * 128;
    const int col0 = blockIdx.x * 128;

    const int r0 = tid >> 2,         kq0 = tid & 3;
    const int r1 = (tid + 256) >> 2, kq1 = tid & 3;
    const float* Ag0 = A  + (size_t)(row0 + r0) * K + kq0 * 4;
    const float* Ag1 = A  + (size_t)(row0 + r1) * K + kq1 * 4;
    const float* Bg0 = Bm + (size_t)(col0 + r0) * K + kq0 * 4;
    const float* Bg1 = Bm + (size_t)(col0 + r1) * K + kq1 * 4;
    const uint32_t sA = s2u(As), sB = s2u(Bs);
    const uint32_t soff0 = (uint32_t)(r0 * GSTR + kq0 * 4) * 4;
    const uint32_t soff1 = (uint32_t)(r1 * GSTR + kq1 * 4) * 4;

    float acc[4][4][4];
#pragma unroll
    for (int i = 0; i < 4; ++i)
#pragma unroll
        for (int j = 0; j < 4; ++j)
#pragma unroll
            for (int v = 0; v < 4; ++v) acc[i][j][v] = 0.f;

    const int nk = K >> 4;

#pragma unroll
    for (int s = 0; s < 2; ++s) {
        const int kc = s << 4;
        const uint32_t ba = sA + s * GTILE * 4, bb = sB + s * GTILE * 4;
        cp16(ba + soff0, Ag0 + kc); cp16(ba + soff1, Ag1 + kc);
        cp16(bb + soff0, Bg0 + kc); cp16(bb + soff1, Bg1 + kc);
        CP_COMMIT();
    }

    int buf = 0;
    for (int kt = 0; kt < nk; ++kt) {
        CP_WAIT1();
        __syncthreads();   // single barrier: buffer (kt+2)%3 fully consumed

        if (kt + 2 < nk) {
            const int s = (kt + 2) % NSTAGE;
            const int kc = (kt + 2) << 4;
            const uint32_t ba = sA + s * GTILE * 4, bb = sB + s * GTILE * 4;
            cp16(ba + soff0, Ag0 + kc); cp16(ba + soff1, Ag1 + kc);
            cp16(bb + soff0, Bg0 + kc); cp16(bb + soff1, Bg1 + kc);
        }
        CP_COMMIT();

        const float* Ab = As + buf * GTILE;
        const float* Bb = Bs + buf * GTILE;
#pragma unroll
        for (int kk = 0; kk < 2; ++kk) {
            const int kb = kk * 8;
            uint32_t a[4][4], b[4][2];
#pragma unroll
            for (int i = 0; i < 4; ++i) {
                int m0 = wm * 64 + i * 16 + gr;
                float2 f0 = *(const float2*)(Ab + m0 * GSTR + kb + 2 * qq);
                float2 f1 = *(const float2*)(Ab + (m0 + 8) * GSTR + kb + 2 * qq);
                a[i][0] = __float_as_uint(f0.x); a[i][1] = __float_as_uint(f1.x);
                a[i][2] = __float_as_uint(f0.y); a[i][3] = __float_as_uint(f1.y);
            }
#pragma unroll
            for (int j = 0; j < 4; ++j) {
                int n0 = wn * 32 + j * 8 + gr;
                float2 g = *(const float2*)(Bb + n0 * GSTR + kb + 2 * qq);
                b[j][0] = __float_as_uint(g.x); b[j][1] = __float_as_uint(g.y);
            }
#pragma unroll
            for (int i = 0; i < 4; ++i)
#pragma unroll
                for (int j = 0; j < 4; ++j)
                    mma_tf32(acc[i][j], a[i], b[j]);
        }
        buf = (buf + 1) % NSTAGE;
    }

    const int egr = lane >> 2, egc = (lane & 3) * 2;
#pragma unroll
    for (int i = 0; i < 4; ++i) {
#pragma unroll
        for (int j = 0; j < 4; ++j) {
            float* cp = C + (size_t)(row0 + wm * 64 + i * 16 + egr) * N +
                        col0 + wn * 32 + j * 8 + egc;
            *(float2*)cp                   = make_float2(acc[i][j][0], acc[i][j][1]);
            *(float2*)(cp + 8 * (size_t)N) = make_float2(acc[i][j][2], acc[i][j][3]);
        }
    }
}

// ---------------------------------------------------------------------------
// RMSNorm + RoPE; stores tf32-rounded, k-pair-permuted along hd.
// ---------------------------------------------------------------------------
__global__ __launch_bounds__(128)
void norm_rope(const float* __restrict__ freqs,
               const float* __restrict__ qw, const float* __restrict__ kw)
{
    const int tok  = blockIdx.x;
    const int head = blockIdx.y;
    const int d    = threadIdx.x;
    const int s    = tok & (SEQ - 1);
    const bool isq = head < NH;
    const float* src = g_qkv + (size_t)tok * EQKV +
                       (isq ? head * HD : DMODEL + (head - NH) * HD);
    float x = src[d];
    float v = x * x;
#pragma unroll
    for (int o = 16; o; o >>= 1) v += __shfl_xor_sync(0xffffffffu, v, o);
    __shared__ float red[4];
    if ((d & 31) == 0) red[d >> 5] = v;
    __syncthreads();
    v = red[0] + red[1] + red[2] + red[3];
    float rs = rsqrtf(v * (1.f / HD) + 1e-5f);
    float w  = isq ? qw[d] : kw[d];
    float xn = x * rs * w;
    float cr = freqs[s * HD + (d & ~1)];
    float ci = freqs[s * HD + (d & ~1) + 1];
    float other = __shfl_xor_sync(0xffffffffu, xn, 1);
    float out = (d & 1) ? fmaf(xn, cr, other * ci)
                        : fmaf(xn, cr, -other * ci);
    const int dp = (d & ~7) | ((d & 3) << 1) | ((d & 4) >> 2);  // pair-permute
    if (isq) {
        const float qscale = 0.08838834764831845f * 1.44269504088896341f;
        g_q[(size_t)tok * (NH * HD) + head * HD + dp] = rnd_tf32(out * qscale);
    } else {
        g_k[(size_t)tok * (NKV * HD) + (head - NH) * HD + dp] = rnd_tf32(out);
    }
}

// ---------------------------------------------------------------------------
// Flash attention, tf32 mma.sync. Q/K hd-dim pair-permuted (S unchanged).
// PADQ/PADKV = 136 -> conflict-free LDS.64 (S) and LDS.32 (PV) patterns.
// Epilogue stores g_y pair-permuted for the out-projection.
// ---------------------------------------------------------------------------
#define PADQ 136
#define PADKV 136
#define PADP 68

__global__ __launch_bounds__(128, 2)
void attn_mma()
{
    extern __shared__ float smf[];
    float* Qsm  = smf;
    float* KVsm = Qsm + 64 * PADQ;
    float* Psm  = KVsm + 64 * PADKV;

    const int qt  = (int)gridDim.x - 1 - (int)blockIdx.x;
    const int h   = blockIdx.y;
    const int b   = blockIdx.z;
    const int kvh = h >> 2;
    const int q0  = qt * 64;
    const int tid = threadIdx.x;
    const int w   = tid >> 5;
    const int lane = tid & 31;
    const int gr  = lane >> 2;
    const int qq  = lane & 3;
    const int r0l = w * 16 + gr;
    const int r1l = r0l + 8;

    for (int idx = tid; idx < 2048; idx += 128) {
        int r = idx >> 5, c = (idx & 31) << 2;
        *(float4*)(Qsm + r * PADQ + c) =
            *(const float4*)(g_q + (size_t)(b * SEQ + q0 + r) * (NH * HD) + h * HD + c);
    }

    float m0 = -1e30f, m1 = -1e30f, l0 = 0.f, l1 = 0.f;
    float O[16][4];
#pragma unroll
    for (int nt = 0; nt < 16; ++nt)
#pragma unroll
        for (int v = 0; v < 4; ++v) O[nt][v] = 0.f;

    for (int kt = 0; kt <= qt; ++kt) {
        const int k0 = kt * 64;
        __syncthreads();
        for (int idx = tid; idx < 2048; idx += 128) {
            int r = idx >> 5, c = (idx & 31) << 2;
            *(float4*)(KVsm + r * PADKV + c) =
                *(const float4*)(g_k + (size_t)(b * SEQ + k0 + r) * (NKV * HD) + kvh * HD + c);
        }
        __syncthreads();

        float s[8][4];
#pragma unroll
        for (int nt = 0; nt < 8; ++nt)
#pragma unroll
            for (int v = 0; v < 4; ++v) s[nt][v] = 0.f;

#pragma unroll
        for (int kk = 0; kk < 16; ++kk) {
            uint32_t a[4];
            float2 fa0 = *(const float2*)(Qsm + r0l * PADQ + kk * 8 + 2 * qq);
            float2 fa1 = *(const float2*)(Qsm + r1l * PADQ + kk * 8 + 2 * qq);
            a[0] = __float_as_uint(fa0.x); a[1] = __float_as_uint(fa1.x);
            a[2] = __float_as_uint(fa0.y); a[3] = __float_as_uint(fa1.y);
#pragma unroll
            for (int nt = 0; nt < 8; ++nt) {
                float2 fb = *(const float2*)(KVsm + (nt * 8 + gr) * PADKV + kk * 8 + 2 * qq);
                uint32_t bb[2] = {__float_as_uint(fb.x), __float_as_uint(fb.y)};
                mma_tf32(s[nt], a, bb);
            }
        }
        __syncthreads();

        for (int idx = tid; idx < 2048; idx += 128) {
            int r = idx >> 5, c = (idx & 31) << 2;
            float4 vv = *(const float4*)(g_qkv + (size_t)(b * SEQ + k0 + r) * EQKV +
                                         (DMODEL + NKV * HD) + kvh * HD + c);
            vv.x = rnd_tf32(vv.x); vv.y = rnd_tf32(vv.y);
            vv.z = rnd_tf32(vv.z); vv.w = rnd_tf32(vv.w);
            *(float4*)(KVsm + r * PADKV + c) = vv;
        }

        if (kt == qt) {
#pragma unroll
            for (int nt = 0; nt < 8; ++nt) {
                int cb = nt * 8 + 2 * qq;
                if (cb     > r0l) s[nt][0] = -1e30f;
                if (cb + 1 > r0l) s[nt][1] = -1e30f;
                if (cb     > r1l) s[nt][2] = -1e30f;
                if (cb + 1 > r1l) s[nt][3] = -1e30f;
            }
        }
        float ml0 = -1e30f, ml1 = -1e30f;
#pragma unroll
        for (int nt = 0; nt < 8; ++nt) {
            ml0 = fmaxf(ml0, fmaxf(s[nt][0], s[nt][1]));
            ml1 = fmaxf(ml1, fmaxf(s[nt][2], s[nt][3]));
        }
        ml0 = fmaxf(ml0, __shfl_xor_sync(0xffffffffu, ml0, 1));
        ml0 = fmaxf(ml0, __shfl_xor_sync(0xffffffffu, ml0, 2));
        ml1 = fmaxf(ml1, __shfl_xor_sync(0xffffffffu, ml1, 1));
        ml1 = fmaxf(ml1, __shfl_xor_sync(0xffffffffu, ml1, 2));
        float mn0 = fmaxf(m0, ml0), mn1 = fmaxf(m1, ml1);
        float c0f = exp2f(m0 - mn0), c1f = exp2f(m1 - mn1);
        m0 = mn0; m1 = mn1;
        float rs0 = 0.f, rs1 = 0.f;
#pragma unroll
        for (int nt = 0; nt < 8; ++nt) {
            float p00 = rnd_tf32(exp2f(s[nt][0] - mn0));
            float p01 = rnd_tf32(exp2f(s[nt][1] - mn0));
            float p10 = rnd_tf32(exp2f(s[nt][2] - mn1));
            float p11 = rnd_tf32(exp2f(s[nt][3] - mn1));
            rs0 += p00 + p01; rs1 += p10 + p11;
            *(float2*)(Psm + r0l * PADP + nt * 8 + 2 * qq) = make_float2(p00, p01);
            *(float2*)(Psm + r1l * PADP + nt * 8 + 2 * qq) = make_float2(p10, p11);
        }
        rs0 += __shfl_xor_sync(0xffffffffu, rs0, 1);
        rs0 += __shfl_xor_sync(0xffffffffu, rs0, 2);
        rs1 += __shfl_xor_sync(0xffffffffu, rs1, 1);
        rs1 += __shfl_xor_sync(0xffffffffu, rs1, 2);
        l0 = l0 * c0f + rs0;
        l1 = l1 * c1f + rs1;
#pragma unroll
        for (int nt = 0; nt < 16; ++nt) {
            O[nt][0] *= c0f; O[nt][1] *= c0f;
            O[nt][2] *= c1f; O[nt][3] *= c1f;
        }
        __syncthreads();

#pragma unroll
        for (int kk = 0; kk < 8; ++kk) {
            uint32_t a[4];
            a[0] = __float_as_uint(Psm[r0l * PADP + kk * 8 + qq]);
            a[1] = __float_as_uint(Psm[r1l * PADP + kk * 8 + qq]);
            a[2] = __float_as_uint(Psm[r0l * PADP + kk * 8 + qq + 4]);
            a[3] = __float_as_uint(Psm[r1l * PADP + kk * 8 + qq + 4]);
#pragma unroll
            for (int nt = 0; nt < 16; ++nt) {
                uint32_t bb[2];
                bb[0] = __float_as_uint(KVsm[(kk * 8 + qq) * PADKV + nt * 8 + gr]);
                bb[1] = __float_as_uint(KVsm[(kk * 8 + qq + 4) * PADKV + nt * 8 + gr]);
                mma_tf32(O[nt], a, bb);
            }
        }
    }

    // Epilogue: pair-permuted columns for the out-projection K layout.
    // cols (2qq, 2qq+1) -> (pe, pe+2), pe = (qq&1)*4 + (qq>>1).
    const int pe = (qq & 1) * 4 + (qq >> 1);
    float inv0 = 1.f / l0, inv1 = 1.f / l1;
    float* y0 = g_y + (size_t)(b * SEQ + q0 + r0l) * (NH * HD) + h * HD;
    float* y1 = g_y + (size_t)(b * SEQ + q0 + r1l) * (NH * HD) + h * HD;
#pragma unroll
    for (int nt = 0; nt < 16; ++nt) {
        y0[nt * 8 + pe]     = rnd_tf32(O[nt][0] * inv0);
        y0[nt * 8 + pe + 2] = rnd_tf32(O[nt][1] * inv0);
        y1[nt * 8 + pe]     = rnd_tf32(O[nt][2] * inv1);
        y1[nt * 8 + pe + 2] = rnd_tf32(O[nt][3] * inv1);
    }
}

// ---------------------------------------------------------------------------
extern "C" void kernel_launch(void* const* d_in, const int* in_sizes, int n_in,
                              void* d_out, int out_size)
{
    const float* x    = (const float*)d_in[0];
    const float* fr   = (const float*)d_in[1];
    const float* wqkv = (const float*)d_in[3];
    const float* wo   = (const float*)d_in[4];
    const float* qw   = (const float*)d_in[5];
    const float* kw   = (const float*)d_in[6];
    float* out = (float*)d_out;

    float *qkv_p, *y_p, *xr_p, *wqkvr_p, *wor_p;
    cudaGetSymbolAddress((void**)&qkv_p,   g_qkv);
    cudaGetSymbolAddress((void**)&y_p,     g_y);
    cudaGetSymbolAddress((void**)&xr_p,    g_xr);
    cudaGetSymbolAddress((void**)&wqkvr_p, g_wqkvr);
    cudaGetSymbolAddress((void**)&wor_p,   g_wor);

    // 0) Pre-round + pair-permute inputs/weights
    pre_round_perm<<<(TOK * DMODEL) / 1024, 256>>>(x, xr_p);
    pre_round_perm<<<(EQKV * DMODEL) / 1024, 256>>>(wqkv, wqkvr_p);
    pre_round_perm<<<(DMODEL * NH * HD) / 1024, 256>>>(wo, wor_p);

    cudaFuncSetAttribute(gemm_cp, cudaFuncAttributeMaxDynamicSharedMemorySize, GSM_TOTAL);

    // 1) QKV projection
    gemm_cp<<<dim3(EQKV / 128, TOK / 128), 256, GSM_TOTAL>>>(xr_p, wqkvr_p, qkv_p, TOK, EQKV, DMODEL);

    // 2) RMSNorm + RoPE
    norm_rope<<<dim3(TOK, NH + NKV), 128>>>(fr, qw, kw);

    // 3) Causal GQA flash attention
    const int asmem = (64 * PADQ + 64 * PADKV + 64 * PADP) * (int)sizeof(float);
    cudaFuncSetAttribute(attn_mma, cudaFuncAttributeMaxDynamicSharedMemorySize, asmem);
    attn_mma<<<dim3(SEQ / 64, NH, BATCH), 128, asmem>>>();

    // 4) Output projection
    gemm_cp<<<dim3(DMODEL / 128, TOK / 128), 256, GSM_TOTAL>>>(y_p, wor_p, out, TOK, DMODEL, DMODEL);
}

// round 7
// speedup vs baseline: 3.9011x; 1.0311x over previous
#include <cuda_runtime.h>
#include <math.h>
#include <stdint.h>

#define BATCH  2
#define SEQ    2048
#define DMODEL 2048
#define NH     16
#define NKV    4
#define HD     128
#define EQKV   3072
#define TOK    (BATCH*SEQ)

// Scratch (device globals; no allocation allowed)
__device__ float g_qkv [(size_t)TOK * EQKV];       // 48 MB (plain layout)
__device__ float g_q   [(size_t)TOK * NH  * HD];   // 32 MB (tf32, k-pair-permuted hd)
__device__ float g_k   [(size_t)TOK * NKV * HD];   //  8 MB (tf32, k-pair-permuted hd)
__device__ float g_y   [(size_t)TOK * NH  * HD];   // 32 MB (tf32, k-pair-permuted)
__device__ float g_xr  [(size_t)TOK * DMODEL];     // 32 MB (tf32, k-pair-permuted)
__device__ float g_wqkvr[(size_t)EQKV * DMODEL];   // 24 MB (tf32, k-pair-permuted)
__device__ float g_wor [(size_t)DMODEL * NH * HD]; // 16 MB (tf32, k-pair-permuted)

__device__ __forceinline__ uint32_t f2tf32(float x) {
    uint32_t r;
    asm("cvt.rna.tf32.f32 %0, %1;" : "=r"(r) : "f"(x));
    return r;
}
__device__ __forceinline__ float rnd_tf32(float x) {
    return __uint_as_float(f2tf32(x));
}
__device__ __forceinline__ uint32_t s2u(const void* p) {
    uint32_t a;
    asm("{ .reg .u64 t; cvta.to.shared.u64 t, %1; cvt.u32.u64 %0, t; }"
        : "=r"(a) : "l"(p));
    return a;
}
__device__ __forceinline__ void mma_tf32(float* c, const uint32_t* a, const uint32_t* b) {
    asm volatile(
        "mma.sync.aligned.m16n8k8.row.col.f32.tf32.tf32.f32 "
        "{%0,%1,%2,%3}, {%4,%5,%6,%7}, {%8,%9}, {%0,%1,%2,%3};"
        : "+f"(c[0]), "+f"(c[1]), "+f"(c[2]), "+f"(c[3])
        : "r"(a[0]), "r"(a[1]), "r"(a[2]), "r"(a[3]),
          "r"(b[0]), "r"(b[1]));
}
__device__ __forceinline__ void cp16(uint32_t smem_dst, const float* gptr) {
    asm volatile("cp.async.cg.shared.global [%0], [%1], 16;"
                 :: "r"(smem_dst), "l"(gptr) : "memory");
}
#define CP_COMMIT() asm volatile("cp.async.commit_group;" ::: "memory")
#define CP_WAIT1()  asm volatile("cp.async.wait_group 1;" ::: "memory")

// ---------------------------------------------------------------------------
// Pre-round to tf32 AND k-pair-permute each 8-wide group of the last dim.
// ---------------------------------------------------------------------------
__global__ __launch_bounds__(256)
void pre_round_perm(const float* __restrict__ src, float* __restrict__ dst)
{
    size_t i = ((size_t)blockIdx.x * 256 + threadIdx.x) * 4;
    float4 v = *(const float4*)(src + i);
    size_t base = i & ~(size_t)7;
    int odd = (int)((i >> 2) & 1);
    dst[base + odd + 0] = rnd_tf32(v.x);
    dst[base + odd + 2] = rnd_tf32(v.y);
    dst[base + odd + 4] = rnd_tf32(v.z);
    dst[base + odd + 6] = rnd_tf32(v.w);
}

// ---------------------------------------------------------------------------
// TF32 mma.sync GEMM (NT), cp.async 3-stage, pair-permuted K layout.
// 128x128 CTA tile, BK=16, 128 threads (4 warps), warp tile 64x64.
// Per warp-ktile: 32 LDS.64 + 64 MMA (ratio 2.0).
// ---------------------------------------------------------------------------
#define GSTR 24
#define GTILE (128 * GSTR)
#define NSTAGE 3
#define GSM_TOTAL (NSTAGE * 2 * GTILE * 4)   // 73728 B

__global__ __launch_bounds__(128)
void gemm_cp(const float* __restrict__ A, const float* __restrict__ Bm,
             float* __restrict__ C, int M, int N, int K)
{
    extern __shared__ float sm[];
    float* As = sm;
    float* Bs = sm + NSTAGE * GTILE;

    const int tid  = threadIdx.x;
    const int lane = tid & 31;
    const int wid  = tid >> 5;
    const int wm   = wid & 1;    // 2 warps along M
    const int wn   = wid >> 1;   // 2 warps along N
    const int gr   = lane >> 2;
    const int qq   = lane & 3;
    const int row0 = blockIdx.y * 128;
    const int col0 = blockIdx.x * 128;

    // staging: thread covers float4 f = tid + 128*j, j=0..3
    const int rB = tid >> 2;          // base row; +32 per j
    const int kq = tid & 3;
    const float* AgB = A  + (size_t)(row0 + rB) * K + kq * 4;
    const float* BgB = Bm + (size_t)(col0 + rB) * K + kq * 4;
    const uint32_t sA = s2u(As), sB = s2u(Bs);
    const uint32_t soffB = (uint32_t)(rB * GSTR + kq * 4) * 4;

    float acc[4][8][4];
#pragma unroll
    for (int i = 0; i < 4; ++i)
#pragma unroll
        for (int j = 0; j < 8; ++j)
#pragma unroll
            for (int v = 0; v < 4; ++v) acc[i][j][v] = 0.f;

    const int nk = K >> 4;

#pragma unroll
    for (int s = 0; s < 2; ++s) {
        const int kc = s << 4;
        const uint32_t ba = sA + s * GTILE * 4, bb = sB + s * GTILE * 4;
#pragma unroll
        for (int j = 0; j < 4; ++j) {
            const size_t go = (size_t)(32 * j) * K + kc;
            const uint32_t so = (uint32_t)(32 * j * GSTR) * 4;
            cp16(ba + soffB + so, AgB + go);
            cp16(bb + soffB + so, BgB + go);
        }
        CP_COMMIT();
    }

    int buf = 0;
    for (int kt = 0; kt < nk; ++kt) {
        CP_WAIT1();
        __syncthreads();

        if (kt + 2 < nk) {
            const int s = (kt + 2) % NSTAGE;
            const int kc = (kt + 2) << 4;
            const uint32_t ba = sA + s * GTILE * 4, bb = sB + s * GTILE * 4;
#pragma unroll
            for (int j = 0; j < 4; ++j) {
                const size_t go = (size_t)(32 * j) * K + kc;
                const uint32_t so = (uint32_t)(32 * j * GSTR) * 4;
                cp16(ba + soffB + so, AgB + go);
                cp16(bb + soffB + so, BgB + go);
            }
        }
        CP_COMMIT();

        const float* Ab = As + buf * GTILE;
        const float* Bb = Bs + buf * GTILE;
#pragma unroll
        for (int kk = 0; kk < 2; ++kk) {
            const int kb = kk * 8;
            uint32_t a[4][4], b[8][2];
#pragma unroll
            for (int i = 0; i < 4; ++i) {
                int m0 = wm * 64 + i * 16 + gr;
                float2 f0 = *(const float2*)(Ab + m0 * GSTR + kb + 2 * qq);
                float2 f1 = *(const float2*)(Ab + (m0 + 8) * GSTR + kb + 2 * qq);
                a[i][0] = __float_as_uint(f0.x); a[i][1] = __float_as_uint(f1.x);
                a[i][2] = __float_as_uint(f0.y); a[i][3] = __float_as_uint(f1.y);
            }
#pragma unroll
            for (int j = 0; j < 8; ++j) {
                int n0 = wn * 64 + j * 8 + gr;
                float2 g = *(const float2*)(Bb + n0 * GSTR + kb + 2 * qq);
                b[j][0] = __float_as_uint(g.x); b[j][1] = __float_as_uint(g.y);
            }
#pragma unroll
            for (int i = 0; i < 4; ++i)
#pragma unroll
                for (int j = 0; j < 8; ++j)
                    mma_tf32(acc[i][j], a[i], b[j]);
        }
        buf = (buf + 1) % NSTAGE;
    }

    const int egr = lane >> 2, egc = (lane & 3) * 2;
#pragma unroll
    for (int i = 0; i < 4; ++i) {
#pragma unroll
        for (int j = 0; j < 8; ++j) {
            float* cp = C + (size_t)(row0 + wm * 64 + i * 16 + egr) * N +
                        col0 + wn * 64 + j * 8 + egc;
            *(float2*)cp                   = make_float2(acc[i][j][0], acc[i][j][1]);
            *(float2*)(cp + 8 * (size_t)N) = make_float2(acc[i][j][2], acc[i][j][3]);
        }
    }
}

// ---------------------------------------------------------------------------
// RMSNorm + RoPE; stores tf32-rounded, k-pair-permuted along hd.
// ---------------------------------------------------------------------------
__global__ __launch_bounds__(128)
void norm_rope(const float* __restrict__ freqs,
               const float* __restrict__ qw, const float* __restrict__ kw)
{
    const int tok  = blockIdx.x;
    const int head = blockIdx.y;
    const int d    = threadIdx.x;
    const int s    = tok & (SEQ - 1);
    const bool isq = head < NH;
    const float* src = g_qkv + (size_t)tok * EQKV +
                       (isq ? head * HD : DMODEL + (head - NH) * HD);
    float x = src[d];
    float v = x * x;
#pragma unroll
    for (int o = 16; o; o >>= 1) v += __shfl_xor_sync(0xffffffffu, v, o);
    __shared__ float red[4];
    if ((d & 31) == 0) red[d >> 5] = v;
    __syncthreads();
    v = red[0] + red[1] + red[2] + red[3];
    float rs = rsqrtf(v * (1.f / HD) + 1e-5f);
    float w  = isq ? qw[d] : kw[d];
    float xn = x * rs * w;
    float cr = freqs[s * HD + (d & ~1)];
    float ci = freqs[s * HD + (d & ~1) + 1];
    float other = __shfl_xor_sync(0xffffffffu, xn, 1);
    float out = (d & 1) ? fmaf(xn, cr, other * ci)
                        : fmaf(xn, cr, -other * ci);
    const int dp = (d & ~7) | ((d & 3) << 1) | ((d & 4) >> 2);
    if (isq) {
        const float qscale = 0.08838834764831845f * 1.44269504088896341f;
        g_q[(size_t)tok * (NH * HD) + head * HD + dp] = rnd_tf32(out * qscale);
    } else {
        g_k[(size_t)tok * (NKV * HD) + (head - NH) * HD + dp] = rnd_tf32(out);
    }
}

// ---------------------------------------------------------------------------
// Flash attention, tf32 mma.sync (unchanged from R6).
// ---------------------------------------------------------------------------
#define PADQ 136
#define PADKV 136
#define PADP 68

__global__ __launch_bounds__(128, 2)
void attn_mma()
{
    extern __shared__ float smf[];
    float* Qsm  = smf;
    float* KVsm = Qsm + 64 * PADQ;
    float* Psm  = KVsm + 64 * PADKV;

    const int qt  = (int)gridDim.x - 1 - (int)blockIdx.x;
    const int h   = blockIdx.y;
    const int b   = blockIdx.z;
    const int kvh = h >> 2;
    const int q0  = qt * 64;
    const int tid = threadIdx.x;
    const int w   = tid >> 5;
    const int lane = tid & 31;
    const int gr  = lane >> 2;
    const int qq  = lane & 3;
    const int r0l = w * 16 + gr;
    const int r1l = r0l + 8;

    for (int idx = tid; idx < 2048; idx += 128) {
        int r = idx >> 5, c = (idx & 31) << 2;
        *(float4*)(Qsm + r * PADQ + c) =
            *(const float4*)(g_q + (size_t)(b * SEQ + q0 + r) * (NH * HD) + h * HD + c);
    }

    float m0 = -1e30f, m1 = -1e30f, l0 = 0.f, l1 = 0.f;
    float O[16][4];
#pragma unroll
    for (int nt = 0; nt < 16; ++nt)
#pragma unroll
        for (int v = 0; v < 4; ++v) O[nt][v] = 0.f;

    for (int kt = 0; kt <= qt; ++kt) {
        const int k0 = kt * 64;
        __syncthreads();
        for (int idx = tid; idx < 2048; idx += 128) {
            int r = idx >> 5, c = (idx & 31) << 2;
            *(float4*)(KVsm + r * PADKV + c) =
                *(const float4*)(g_k + (size_t)(b * SEQ + k0 + r) * (NKV * HD) + kvh * HD + c);
        }
        __syncthreads();

        float s[8][4];
#pragma unroll
        for (int nt = 0; nt < 8; ++nt)
#pragma unroll
            for (int v = 0; v < 4; ++v) s[nt][v] = 0.f;

#pragma unroll
        for (int kk = 0; kk < 16; ++kk) {
            uint32_t a[4];
            float2 fa0 = *(const float2*)(Qsm + r0l * PADQ + kk * 8 + 2 * qq);
            float2 fa1 = *(const float2*)(Qsm + r1l * PADQ + kk * 8 + 2 * qq);
            a[0] = __float_as_uint(fa0.x); a[1] = __float_as_uint(fa1.x);
            a[2] = __float_as_uint(fa0.y); a[3] = __float_as_uint(fa1.y);
#pragma unroll
            for (int nt = 0; nt < 8; ++nt) {
                float2 fb = *(const float2*)(KVsm + (nt * 8 + gr) * PADKV + kk * 8 + 2 * qq);
                uint32_t bb[2] = {__float_as_uint(fb.x), __float_as_uint(fb.y)};
                mma_tf32(s[nt], a, bb);
            }
        }
        __syncthreads();

        for (int idx = tid; idx < 2048; idx += 128) {
            int r = idx >> 5, c = (idx & 31) << 2;
            float4 vv = *(const float4*)(g_qkv + (size_t)(b * SEQ + k0 + r) * EQKV +
                                         (DMODEL + NKV * HD) + kvh * HD + c);
            vv.x = rnd_tf32(vv.x); vv.y = rnd_tf32(vv.y);
            vv.z = rnd_tf32(vv.z); vv.w = rnd_tf32(vv.w);
            *(float4*)(KVsm + r * PADKV + c) = vv;
        }

        if (kt == qt) {
#pragma unroll
            for (int nt = 0; nt < 8; ++nt) {
                int cb = nt * 8 + 2 * qq;
                if (cb     > r0l) s[nt][0] = -1e30f;
                if (cb + 1 > r0l) s[nt][1] = -1e30f;
                if (cb     > r1l) s[nt][2] = -1e30f;
                if (cb + 1 > r1l) s[nt][3] = -1e30f;
            }
        }
        float ml0 = -1e30f, ml1 = -1e30f;
#pragma unroll
        for (int nt = 0; nt < 8; ++nt) {
            ml0 = fmaxf(ml0, fmaxf(s[nt][0], s[nt][1]));
            ml1 = fmaxf(ml1, fmaxf(s[nt][2], s[nt][3]));
        }
        ml0 = fmaxf(ml0, __shfl_xor_sync(0xffffffffu, ml0, 1));
        ml0 = fmaxf(ml0, __shfl_xor_sync(0xffffffffu, ml0, 2));
        ml1 = fmaxf(ml1, __shfl_xor_sync(0xffffffffu, ml1, 1));
        ml1 = fmaxf(ml1, __shfl_xor_sync(0xffffffffu, ml1, 2));
        float mn0 = fmaxf(m0, ml0), mn1 = fmaxf(m1, ml1);
        float c0f = exp2f(m0 - mn0), c1f = exp2f(m1 - mn1);
        m0 = mn0; m1 = mn1;
        float rs0 = 0.f, rs1 = 0.f;
#pragma unroll
        for (int nt = 0; nt < 8; ++nt) {
            float p00 = rnd_tf32(exp2f(s[nt][0] - mn0));
            float p01 = rnd_tf32(exp2f(s[nt][1] - mn0));
            float p10 = rnd_tf32(exp2f(s[nt][2] - mn1));
            float p11 = rnd_tf32(exp2f(s[nt][3] - mn1));
            rs0 += p00 + p01; rs1 += p10 + p11;
            *(float2*)(Psm + r0l * PADP + nt * 8 + 2 * qq) = make_float2(p00, p01);
            *(float2*)(Psm + r1l * PADP + nt * 8 + 2 * qq) = make_float2(p10, p11);
        }
        rs0 += __shfl_xor_sync(0xffffffffu, rs0, 1);
        rs0 += __shfl_xor_sync(0xffffffffu, rs0, 2);
        rs1 += __shfl_xor_sync(0xffffffffu, rs1, 1);
        rs1 += __shfl_xor_sync(0xffffffffu, rs1, 2);
        l0 = l0 * c0f + rs0;
        l1 = l1 * c1f + rs1;
#pragma unroll
        for (int nt = 0; nt < 16; ++nt) {
            O[nt][0] *= c0f; O[nt][1] *= c0f;
            O[nt][2] *= c1f; O[nt][3] *= c1f;
        }
        __syncthreads();

#pragma unroll
        for (int kk = 0; kk < 8; ++kk) {
            uint32_t a[4];
            a[0] = __float_as_uint(Psm[r0l * PADP + kk * 8 + qq]);
            a[1] = __float_as_uint(Psm[r1l * PADP + kk * 8 + qq]);
            a[2] = __float_as_uint(Psm[r0l * PADP + kk * 8 + qq + 4]);
            a[3] = __float_as_uint(Psm[r1l * PADP + kk * 8 + qq + 4]);
#pragma unroll
            for (int nt = 0; nt < 16; ++nt) {
                uint32_t bb[2];
                bb[0] = __float_as_uint(KVsm[(kk * 8 + qq) * PADKV + nt * 8 + gr]);
                bb[1] = __float_as_uint(KVsm[(kk * 8 + qq + 4) * PADKV + nt * 8 + gr]);
                mma_tf32(O[nt], a, bb);
            }
        }
    }

    const int pe = (qq & 1) * 4 + (qq >> 1);
    float inv0 = 1.f / l0, inv1 = 1.f / l1;
    float* y0 = g_y + (size_t)(b * SEQ + q0 + r0l) * (NH * HD) + h * HD;
    float* y1 = g_y + (size_t)(b * SEQ + q0 + r1l) * (NH * HD) + h * HD;
#pragma unroll
    for (int nt = 0; nt < 16; ++nt) {
        y0[nt * 8 + pe]     = rnd_tf32(O[nt][0] * inv0);
        y0[nt * 8 + pe + 2] = rnd_tf32(O[nt][1] * inv0);
        y1[nt * 8 + pe]     = rnd_tf32(O[nt][2] * inv1);
        y1[nt * 8 + pe + 2] = rnd_tf32(O[nt][3] * inv1);
    }
}

// ---------------------------------------------------------------------------
extern "C" void kernel_launch(void* const* d_in, const int* in_sizes, int n_in,
                              void* d_out, int out_size)
{
    const float* x    = (const float*)d_in[0];
    const float* fr   = (const float*)d_in[1];
    const float* wqkv = (const float*)d_in[3];
    const float* wo   = (const float*)d_in[4];
    const float* qw   = (const float*)d_in[5];
    const float* kw   = (const float*)d_in[6];
    float* out = (float*)d_out;

    float *qkv_p, *y_p, *xr_p, *wqkvr_p, *wor_p;
    cudaGetSymbolAddress((void**)&qkv_p,   g_qkv);
    cudaGetSymbolAddress((void**)&y_p,     g_y);
    cudaGetSymbolAddress((void**)&xr_p,    g_xr);
    cudaGetSymbolAddress((void**)&wqkvr_p, g_wqkvr);
    cudaGetSymbolAddress((void**)&wor_p,   g_wor);

    // 0) Pre-round + pair-permute inputs/weights
    pre_round_perm<<<(TOK * DMODEL) / 1024, 256>>>(x, xr_p);
    pre_round_perm<<<(EQKV * DMODEL) / 1024, 256>>>(wqkv, wqkvr_p);
    pre_round_perm<<<(DMODEL * NH * HD) / 1024, 256>>>(wo, wor_p);

    cudaFuncSetAttribute(gemm_cp, cudaFuncAttributeMaxDynamicSharedMemorySize, GSM_TOTAL);

    // 1) QKV projection
    gemm_cp<<<dim3(EQKV / 128, TOK / 128), 128, GSM_TOTAL>>>(xr_p, wqkvr_p, qkv_p, TOK, EQKV, DMODEL);

    // 2) RMSNorm + RoPE
    norm_rope<<<dim3(TOK, NH + NKV), 128>>>(fr, qw, kw);

    // 3) Causal GQA flash attention
    const int asmem = (64 * PADQ + 64 * PADKV + 64 * PADP) * (int)sizeof(float);
    cudaFuncSetAttribute(attn_mma, cudaFuncAttributeMaxDynamicSharedMemorySize, asmem);
    attn_mma<<<dim3(SEQ / 64, NH, BATCH), 128, asmem>>>();

    // 4) Output projection
    gemm_cp<<<dim3(DMODEL / 128, TOK / 128), 128, GSM_TOTAL>>>(y_p, wor_p, out, TOK, DMODEL, DMODEL);
}

// round 8
// speedup vs baseline: 4.6723x; 1.1977x over previous
#include <cuda_runtime.h>
#include <math.h>
#include <stdint.h>

#define BATCH  2
#define SEQ    2048
#define DMODEL 2048
#define NH     16
#define NKV    4
#define HD     128
#define EQKV   3072
#define TOK    (BATCH*SEQ)

// Scratch (device globals; no allocation allowed)
__device__ float g_qkv [(size_t)TOK * EQKV];       // 48 MB (tf32-rounded by GEMM1)
__device__ float g_q   [(size_t)TOK * NH  * HD];   // 32 MB (tf32, pair-permuted hd)
__device__ float g_k   [(size_t)TOK * NKV * HD];   //  8 MB (tf32, pair-permuted hd)
__device__ float g_y   [(size_t)TOK * NH  * HD];   // 32 MB (tf32, pair-permuted)
__device__ float g_xr  [(size_t)TOK * DMODEL];     // 32 MB (tf32, pair-permuted)
__device__ float g_wqkvr[(size_t)EQKV * DMODEL];   // 24 MB (tf32, pair-permuted)
__device__ float g_wor [(size_t)DMODEL * NH * HD]; // 16 MB (tf32, pair-permuted)

__device__ __forceinline__ uint32_t f2tf32(float x) {
    uint32_t r;
    asm("cvt.rna.tf32.f32 %0, %1;" : "=r"(r) : "f"(x));
    return r;
}
__device__ __forceinline__ float rnd_tf32(float x) {
    return __uint_as_float(f2tf32(x));
}
__device__ __forceinline__ uint32_t s2u(const void* p) {
    uint32_t a;
    asm("{ .reg .u64 t; cvta.to.shared.u64 t, %1; cvt.u32.u64 %0, t; }"
        : "=r"(a) : "l"(p));
    return a;
}
__device__ __forceinline__ void mma_tf32(float* c, const uint32_t* a, const uint32_t* b) {
    asm volatile(
        "mma.sync.aligned.m16n8k8.row.col.f32.tf32.tf32.f32 "
        "{%0,%1,%2,%3}, {%4,%5,%6,%7}, {%8,%9}, {%0,%1,%2,%3};"
        : "+f"(c[0]), "+f"(c[1]), "+f"(c[2]), "+f"(c[3])
        : "r"(a[0]), "r"(a[1]), "r"(a[2]), "r"(a[3]),
          "r"(b[0]), "r"(b[1]));
}
__device__ __forceinline__ void cp16(uint32_t smem_dst, const float* gptr) {
    asm volatile("cp.async.cg.shared.global [%0], [%1], 16;"
                 :: "r"(smem_dst), "l"(gptr) : "memory");
}
#define CP_COMMIT() asm volatile("cp.async.commit_group;" ::: "memory")
#define CP_WAIT0()  asm volatile("cp.async.wait_group 0;" ::: "memory")

// ---------------------------------------------------------------------------
// Pre-round to tf32 AND k-pair-permute each 8-wide group of the last dim.
// ---------------------------------------------------------------------------
__global__ __launch_bounds__(256)
void pre_round_perm(const float* __restrict__ src, float* __restrict__ dst)
{
    size_t i = ((size_t)blockIdx.x * 256 + threadIdx.x) * 4;
    float4 v = *(const float4*)(src + i);
    size_t base = i & ~(size_t)7;
    int odd = (int)((i >> 2) & 1);
    dst[base + odd + 0] = rnd_tf32(v.x);
    dst[base + odd + 2] = rnd_tf32(v.y);
    dst[base + odd + 4] = rnd_tf32(v.z);
    dst[base + odd + 6] = rnd_tf32(v.w);
}

// ---------------------------------------------------------------------------
// TF32 mma.sync GEMM (NT), cp.async 2-stage, BK=32, pair-permuted K layout.
// 128x128 CTA tile, 128 threads (4 warps), warp tile 64x64.
// smem stride 40 words: conflict-free STS.128 staging and LDS.64 fragments.
// round_out=1 -> store tf32-rounded C (for qkv feeding attention).
// ---------------------------------------------------------------------------
#define GSTR 40
#define GTILE (128 * GSTR)                 // 5120 floats / stage / matrix
#define NSTAGE 2
#define GSM_TOTAL (NSTAGE * 2 * GTILE * 4) // 81920 B

__global__ __launch_bounds__(128)
void gemm_cp(const float* __restrict__ A, const float* __restrict__ Bm,
             float* __restrict__ C, int M, int N, int K, int round_out)
{
    extern __shared__ float sm[];
    float* As = sm;
    float* Bs = sm + NSTAGE * GTILE;

    const int tid  = threadIdx.x;
    const int lane = tid & 31;
    const int wid  = tid >> 5;
    const int wm   = wid & 1;
    const int wn   = wid >> 1;
    const int gr   = lane >> 2;
    const int qq   = lane & 3;
    const int row0 = blockIdx.y * 128;
    const int col0 = blockIdx.x * 128;

    // staging: thread covers rows rS+16j (j=0..7), fixed kq float4 column
    const int rS = tid >> 3;
    const int kq = tid & 7;
    const float* AgB = A  + (size_t)(row0 + rS) * K + kq * 4;
    const float* BgB = Bm + (size_t)(col0 + rS) * K + kq * 4;
    const uint32_t sA = s2u(As), sB = s2u(Bs);
    const uint32_t soffB = (uint32_t)(rS * GSTR + kq * 4) * 4;

    float acc[4][8][4];
#pragma unroll
    for (int i = 0; i < 4; ++i)
#pragma unroll
        for (int j = 0; j < 8; ++j)
#pragma unroll
            for (int v = 0; v < 4; ++v) acc[i][j][v] = 0.f;

    const int nk = K >> 5;   // BK=32

    // prologue: stage 0
#pragma unroll
    for (int j = 0; j < 8; ++j) {
        const size_t go = (size_t)(16 * j) * K;
        const uint32_t so = (uint32_t)(16 * j * GSTR) * 4;
        cp16(sA + soffB + so, AgB + go);
        cp16(sB + soffB + so, BgB + go);
    }
    CP_COMMIT();

    for (int it = 0; it < nk; ++it) {
        CP_WAIT0();
        __syncthreads();

        if (it + 1 < nk) {
            const int s = (it + 1) & 1;
            const int kc = (it + 1) << 5;
            const uint32_t ba = sA + s * GTILE * 4, bb = sB + s * GTILE * 4;
#pragma unroll
            for (int j = 0; j < 8; ++j) {
                const size_t go = (size_t)(16 * j) * K + kc;
                const uint32_t so = (uint32_t)(16 * j * GSTR) * 4;
                cp16(ba + soffB + so, AgB + go);
                cp16(bb + soffB + so, BgB + go);
            }
            CP_COMMIT();
        }

        const float* Ab = As + (it & 1) * GTILE;
        const float* Bb = Bs + (it & 1) * GTILE;
#pragma unroll
        for (int kk = 0; kk < 4; ++kk) {
            const int kb = kk * 8;
            uint32_t a[4][4], b[8][2];
#pragma unroll
            for (int i = 0; i < 4; ++i) {
                int m0 = wm * 64 + i * 16 + gr;
                float2 f0 = *(const float2*)(Ab + m0 * GSTR + kb + 2 * qq);
                float2 f1 = *(const float2*)(Ab + (m0 + 8) * GSTR + kb + 2 * qq);
                a[i][0] = __float_as_uint(f0.x); a[i][1] = __float_as_uint(f1.x);
                a[i][2] = __float_as_uint(f0.y); a[i][3] = __float_as_uint(f1.y);
            }
#pragma unroll
            for (int j = 0; j < 8; ++j) {
                int n0 = wn * 64 + j * 8 + gr;
                float2 g = *(const float2*)(Bb + n0 * GSTR + kb + 2 * qq);
                b[j][0] = __float_as_uint(g.x); b[j][1] = __float_as_uint(g.y);
            }
#pragma unroll
            for (int i = 0; i < 4; ++i)
#pragma unroll
                for (int j = 0; j < 8; ++j)
                    mma_tf32(acc[i][j], a[i], b[j]);
        }
    }

    const int egr = lane >> 2, egc = (lane & 3) * 2;
#pragma unroll
    for (int i = 0; i < 4; ++i) {
#pragma unroll
        for (int j = 0; j < 8; ++j) {
            float4 v;
            if (round_out) {
                v = make_float4(rnd_tf32(acc[i][j][0]), rnd_tf32(acc[i][j][1]),
                                rnd_tf32(acc[i][j][2]), rnd_tf32(acc[i][j][3]));
            } else {
                v = make_float4(acc[i][j][0], acc[i][j][1], acc[i][j][2], acc[i][j][3]);
            }
            float* cp = C + (size_t)(row0 + wm * 64 + i * 16 + egr) * N +
                        col0 + wn * 64 + j * 8 + egc;
            *(float2*)cp                   = make_float2(v.x, v.y);
            *(float2*)(cp + 8 * (size_t)N) = make_float2(v.z, v.w);
        }
    }
}

// ---------------------------------------------------------------------------
// RMSNorm + RoPE; stores tf32-rounded, k-pair-permuted along hd.
// (reads tf32-rounded qkv — harmless extra rounding)
// ---------------------------------------------------------------------------
__global__ __launch_bounds__(128)
void norm_rope(const float* __restrict__ freqs,
               const float* __restrict__ qw, const float* __restrict__ kw)
{
    const int tok  = blockIdx.x;
    const int head = blockIdx.y;
    const int d    = threadIdx.x;
    const int s    = tok & (SEQ - 1);
    const bool isq = head < NH;
    const float* src = g_qkv + (size_t)tok * EQKV +
                       (isq ? head * HD : DMODEL + (head - NH) * HD);
    float x = src[d];
    float v = x * x;
#pragma unroll
    for (int o = 16; o; o >>= 1) v += __shfl_xor_sync(0xffffffffu, v, o);
    __shared__ float red[4];
    if ((d & 31) == 0) red[d >> 5] = v;
    __syncthreads();
    v = red[0] + red[1] + red[2] + red[3];
    float rs = rsqrtf(v * (1.f / HD) + 1e-5f);
    float w  = isq ? qw[d] : kw[d];
    float xn = x * rs * w;
    float cr = freqs[s * HD + (d & ~1)];
    float ci = freqs[s * HD + (d & ~1) + 1];
    float other = __shfl_xor_sync(0xffffffffu, xn, 1);
    float out = (d & 1) ? fmaf(xn, cr, other * ci)
                        : fmaf(xn, cr, -other * ci);
    const int dp = (d & ~7) | ((d & 3) << 1) | ((d & 4) >> 2);
    if (isq) {
        const float qscale = 0.08838834764831845f * 1.44269504088896341f;
        g_q[(size_t)tok * (NH * HD) + head * HD + dp] = rnd_tf32(out * qscale);
    } else {
        g_k[(size_t)tok * (NKV * HD) + (head - NH) * HD + dp] = rnd_tf32(out);
    }
}

// ---------------------------------------------------------------------------
// Flash attention, tf32 mma.sync. cp.async staging for K and V (V pre-rounded
// in g_qkv); softmax register work hoisted before the K-done barrier.
// ---------------------------------------------------------------------------
#define PADQ 136
#define PADKV 136
#define PADP 68

__global__ __launch_bounds__(128, 2)
void attn_mma()
{
    extern __shared__ float smf[];
    float* Qsm  = smf;
    float* KVsm = Qsm + 64 * PADQ;
    float* Psm  = KVsm + 64 * PADKV;
    const uint32_t kvB = s2u(KVsm);

    const int qt  = (int)gridDim.x - 1 - (int)blockIdx.x;
    const int h   = blockIdx.y;
    const int b   = blockIdx.z;
    const int kvh = h >> 2;
    const int q0  = qt * 64;
    const int tid = threadIdx.x;
    const int w   = tid >> 5;
    const int lane = tid & 31;
    const int gr  = lane >> 2;
    const int qq  = lane & 3;
    const int r0l = w * 16 + gr;
    const int r1l = r0l + 8;

    // Stage Q (rounded/scaled already)
    for (int idx = tid; idx < 2048; idx += 128) {
        int r = idx >> 5, c = (idx & 31) << 2;
        *(float4*)(Qsm + r * PADQ + c) =
            *(const float4*)(g_q + (size_t)(b * SEQ + q0 + r) * (NH * HD) + h * HD + c);
    }

    float m0 = -1e30f, m1 = -1e30f, l0 = 0.f, l1 = 0.f;
    float O[16][4];
#pragma unroll
    for (int nt = 0; nt < 16; ++nt)
#pragma unroll
        for (int v = 0; v < 4; ++v) O[nt][v] = 0.f;

    for (int kt = 0; kt <= qt; ++kt) {
        const int k0 = kt * 64;
        __syncthreads();  // prev PV done with KV buffer
        // Stage K via cp.async (pure copy)
        {
            const float* src = g_k + (size_t)(b * SEQ + k0) * (NKV * HD) + kvh * HD;
#pragma unroll
            for (int it = 0; it < 16; ++it) {
                int idx = tid + 128 * it;
                int r = idx >> 5, c = (idx & 31) << 2;
                cp16(kvB + (uint32_t)(r * PADKV + c) * 4,
                     src + (size_t)r * (NKV * HD) + c);
            }
            CP_COMMIT();
            CP_WAIT0();
        }
        __syncthreads();

        // S = Q K^T
        float s[8][4];
#pragma unroll
        for (int nt = 0; nt < 8; ++nt)
#pragma unroll
            for (int v = 0; v < 4; ++v) s[nt][v] = 0.f;

#pragma unroll
        for (int kk = 0; kk < 16; ++kk) {
            uint32_t a[4];
            float2 fa0 = *(const float2*)(Qsm + r0l * PADQ + kk * 8 + 2 * qq);
            float2 fa1 = *(const float2*)(Qsm + r1l * PADQ + kk * 8 + 2 * qq);
            a[0] = __float_as_uint(fa0.x); a[1] = __float_as_uint(fa1.x);
            a[2] = __float_as_uint(fa0.y); a[3] = __float_as_uint(fa1.y);
#pragma unroll
            for (int nt = 0; nt < 8; ++nt) {
                float2 fb = *(const float2*)(KVsm + (nt * 8 + gr) * PADKV + kk * 8 + 2 * qq);
                uint32_t bb[2] = {__float_as_uint(fb.x), __float_as_uint(fb.y)};
                mma_tf32(s[nt], a, bb);
            }
        }

        // Softmax register work (overlaps other warps' S-MMA tail)
        if (kt == qt) {
#pragma unroll
            for (int nt = 0; nt < 8; ++nt) {
                int cb = nt * 8 + 2 * qq;
                if (cb     > r0l) s[nt][0] = -1e30f;
                if (cb + 1 > r0l) s[nt][1] = -1e30f;
                if (cb     > r1l) s[nt][2] = -1e30f;
                if (cb + 1 > r1l) s[nt][3] = -1e30f;
            }
        }
        float ml0 = -1e30f, ml1 = -1e30f;
#pragma unroll
        for (int nt = 0; nt < 8; ++nt) {
            ml0 = fmaxf(ml0, fmaxf(s[nt][0], s[nt][1]));
            ml1 = fmaxf(ml1, fmaxf(s[nt][2], s[nt][3]));
        }
        ml0 = fmaxf(ml0, __shfl_xor_sync(0xffffffffu, ml0, 1));
        ml0 = fmaxf(ml0, __shfl_xor_sync(0xffffffffu, ml0, 2));
        ml1 = fmaxf(ml1, __shfl_xor_sync(0xffffffffu, ml1, 1));
        ml1 = fmaxf(ml1, __shfl_xor_sync(0xffffffffu, ml1, 2));
        float mn0 = fmaxf(m0, ml0), mn1 = fmaxf(m1, ml1);
        float c0f = exp2f(m0 - mn0), c1f = exp2f(m1 - mn1);
        m0 = mn0; m1 = mn1;
        float p0r[8][2], p1r[8][2];
        float rs0 = 0.f, rs1 = 0.f;
#pragma unroll
        for (int nt = 0; nt < 8; ++nt) {
            p0r[nt][0] = rnd_tf32(exp2f(s[nt][0] - mn0));
            p0r[nt][1] = rnd_tf32(exp2f(s[nt][1] - mn0));
            p1r[nt][0] = rnd_tf32(exp2f(s[nt][2] - mn1));
            p1r[nt][1] = rnd_tf32(exp2f(s[nt][3] - mn1));
            rs0 += p0r[nt][0] + p0r[nt][1];
            rs1 += p1r[nt][0] + p1r[nt][1];
        }
        rs0 += __shfl_xor_sync(0xffffffffu, rs0, 1);
        rs0 += __shfl_xor_sync(0xffffffffu, rs0, 2);
        rs1 += __shfl_xor_sync(0xffffffffu, rs1, 1);
        rs1 += __shfl_xor_sync(0xffffffffu, rs1, 2);
        l0 = l0 * c0f + rs0;
        l1 = l1 * c1f + rs1;
#pragma unroll
        for (int nt = 0; nt < 16; ++nt) {
            O[nt][0] *= c0f; O[nt][1] *= c0f;
            O[nt][2] *= c1f; O[nt][3] *= c1f;
        }

        __syncthreads();  // all warps done reading K

        // Stage V via cp.async (pure copy, qkv pre-rounded) — overlaps P writes
        {
            const float* src = g_qkv + (size_t)(b * SEQ + k0) * EQKV +
                               (DMODEL + NKV * HD) + kvh * HD;
#pragma unroll
            for (int it = 0; it < 16; ++it) {
                int idx = tid + 128 * it;
                int r = idx >> 5, c = (idx & 31) << 2;
                cp16(kvB + (uint32_t)(r * PADKV + c) * 4,
                     src + (size_t)r * EQKV + c);
            }
            CP_COMMIT();
        }
#pragma unroll
        for (int nt = 0; nt < 8; ++nt) {
            *(float2*)(Psm + r0l * PADP + nt * 8 + 2 * qq) = make_float2(p0r[nt][0], p0r[nt][1]);
            *(float2*)(Psm + r1l * PADP + nt * 8 + 2 * qq) = make_float2(p1r[nt][0], p1r[nt][1]);
        }
        CP_WAIT0();
        __syncthreads();  // V + P visible

        // O += P V
#pragma unroll
        for (int kk = 0; kk < 8; ++kk) {
            uint32_t a[4];
            a[0] = __float_as_uint(Psm[r0l * PADP + kk * 8 + qq]);
            a[1] = __float_as_uint(Psm[r1l * PADP + kk * 8 + qq]);
            a[2] = __float_as_uint(Psm[r0l * PADP + kk * 8 + qq + 4]);
            a[3] = __float_as_uint(Psm[r1l * PADP + kk * 8 + qq + 4]);
#pragma unroll
            for (int nt = 0; nt < 16; ++nt) {
                uint32_t bb[2];
                bb[0] = __float_as_uint(KVsm[(kk * 8 + qq) * PADKV + nt * 8 + gr]);
                bb[1] = __float_as_uint(KVsm[(kk * 8 + qq + 4) * PADKV + nt * 8 + gr]);
                mma_tf32(O[nt], a, bb);
            }
        }
    }

    const int pe = (qq & 1) * 4 + (qq >> 1);
    float inv0 = 1.f / l0, inv1 = 1.f / l1;
    float* y0 = g_y + (size_t)(b * SEQ + q0 + r0l) * (NH * HD) + h * HD;
    float* y1 = g_y + (size_t)(b * SEQ + q0 + r1l) * (NH * HD) + h * HD;
#pragma unroll
    for (int nt = 0; nt < 16; ++nt) {
        y0[nt * 8 + pe]     = rnd_tf32(O[nt][0] * inv0);
        y0[nt * 8 + pe + 2] = rnd_tf32(O[nt][1] * inv0);
        y1[nt * 8 + pe]     = rnd_tf32(O[nt][2] * inv1);
        y1[nt * 8 + pe + 2] = rnd_tf32(O[nt][3] * inv1);
    }
}

// ---------------------------------------------------------------------------
extern "C" void kernel_launch(void* const* d_in, const int* in_sizes, int n_in,
                              void* d_out, int out_size)
{
    const float* x    = (const float*)d_in[0];
    const float* fr   = (const float*)d_in[1];
    const float* wqkv = (const float*)d_in[3];
    const float* wo   = (const float*)d_in[4];
    const float* qw   = (const float*)d_in[5];
    const float* kw   = (const float*)d_in[6];
    float* out = (float*)d_out;

    float *qkv_p, *y_p, *xr_p, *wqkvr_p, *wor_p;
    cudaGetSymbolAddress((void**)&qkv_p,   g_qkv);
    cudaGetSymbolAddress((void**)&y_p,     g_y);
    cudaGetSymbolAddress((void**)&xr_p,    g_xr);
    cudaGetSymbolAddress((void**)&wqkvr_p, g_wqkvr);
    cudaGetSymbolAddress((void**)&wor_p,   g_wor);

    // 0) Pre-round + pair-permute inputs/weights
    pre_round_perm<<<(TOK * DMODEL) / 1024, 256>>>(x, xr_p);
    pre_round_perm<<<(EQKV * DMODEL) / 1024, 256>>>(wqkv, wqkvr_p);
    pre_round_perm<<<(DMODEL * NH * HD) / 1024, 256>>>(wo, wor_p);

    cudaFuncSetAttribute(gemm_cp, cudaFuncAttributeMaxDynamicSharedMemorySize, GSM_TOTAL);

    // 1) QKV projection (stores tf32-rounded)
    gemm_cp<<<dim3(EQKV / 128, TOK / 128), 128, GSM_TOTAL>>>(xr_p, wqkvr_p, qkv_p, TOK, EQKV, DMODEL, 1);

    // 2) RMSNorm + RoPE
    norm_rope<<<dim3(TOK, NH + NKV), 128>>>(fr, qw, kw);

    // 3) Causal GQA flash attention
    const int asmem = (64 * PADQ + 64 * PADKV + 64 * PADP) * (int)sizeof(float);
    cudaFuncSetAttribute(attn_mma, cudaFuncAttributeMaxDynamicSharedMemorySize, asmem);
    attn_mma<<<dim3(SEQ / 64, NH, BATCH), 128, asmem>>>();

    // 4) Output projection (raw fp32 output)
    gemm_cp<<<dim3(DMODEL / 128, TOK / 128), 128, GSM_TOTAL>>>(y_p, wor_p, out, TOK, DMODEL, DMODEL, 0);
}

// round 9
// speedup vs baseline: 8.3005x; 1.7766x over previous
#include <cuda_runtime.h>
#include <cuda_fp16.h>
#include <math.h>
#include <stdint.h>

#define BATCH  2
#define SEQ    2048
#define DMODEL 2048
#define NH     16
#define NKV    4
#define HD     128
#define EQKV   3072
#define TOK    (BATCH*SEQ)

// Scratch (device globals; no allocation allowed) — all fp16 now
__device__ __half g_qkvh [(size_t)TOK * EQKV];       // 24 MB
__device__ __half g_qh   [(size_t)TOK * NH  * HD];   // 16 MB
__device__ __half g_kh   [(size_t)TOK * NKV * HD];   //  4 MB
__device__ __half g_yh   [(size_t)TOK * NH  * HD];   // 16 MB
__device__ __half g_xh   [(size_t)TOK * DMODEL];     // 16 MB
__device__ __half g_wqkvh[(size_t)EQKV * DMODEL];    // 12 MB
__device__ __half g_woh  [(size_t)DMODEL * NH * HD]; //  8 MB

__device__ __forceinline__ uint32_t s2u(const void* p) {
    uint32_t a;
    asm("{ .reg .u64 t; cvta.to.shared.u64 t, %1; cvt.u32.u64 %0, t; }"
        : "=r"(a) : "l"(p));
    return a;
}
__device__ __forceinline__ void mma_f16(float* c, const uint32_t* a, const uint32_t* b) {
    asm volatile(
        "mma.sync.aligned.m16n8k16.row.col.f32.f16.f16.f32 "
        "{%0,%1,%2,%3}, {%4,%5,%6,%7}, {%8,%9}, {%0,%1,%2,%3};"
        : "+f"(c[0]), "+f"(c[1]), "+f"(c[2]), "+f"(c[3])
        : "r"(a[0]), "r"(a[1]), "r"(a[2]), "r"(a[3]),
          "r"(b[0]), "r"(b[1]));
}
__device__ __forceinline__ void ldsm4(uint32_t* r, uint32_t a) {
    asm volatile("ldmatrix.sync.aligned.m8n8.x4.shared.b16 {%0,%1,%2,%3}, [%4];"
        : "=r"(r[0]), "=r"(r[1]), "=r"(r[2]), "=r"(r[3]) : "r"(a));
}
__device__ __forceinline__ void ldsm4t(uint32_t* r, uint32_t a) {
    asm volatile("ldmatrix.sync.aligned.m8n8.x4.trans.shared.b16 {%0,%1,%2,%3}, [%4];"
        : "=r"(r[0]), "=r"(r[1]), "=r"(r[2]), "=r"(r[3]) : "r"(a));
}
__device__ __forceinline__ void cp16(uint32_t smem_dst, const void* gptr) {
    asm volatile("cp.async.cg.shared.global [%0], [%1], 16;"
                 :: "r"(smem_dst), "l"(gptr) : "memory");
}
#define CP_COMMIT() asm volatile("cp.async.commit_group;" ::: "memory")
#define CP_WAIT0()  asm volatile("cp.async.wait_group 0;" ::: "memory")

// ---------------------------------------------------------------------------
// fp32 -> fp16 convert (plain layout). n % 1024 == 0.
// ---------------------------------------------------------------------------
__global__ __launch_bounds__(256)
void to_half(const float* __restrict__ src, __half* __restrict__ dst)
{
    size_t i = ((size_t)blockIdx.x * 256 + threadIdx.x) * 4;
    float4 v = *(const float4*)(src + i);
    __half2* d = (__half2*)(dst + i);
    d[0] = __floats2half2_rn(v.x, v.y);
    d[1] = __floats2half2_rn(v.z, v.w);
}

// ---------------------------------------------------------------------------
// fp16 mma.sync GEMM (NT), cp.async 2-stage, BK=64, ldmatrix fragments.
// C[M,N] = A[M,K]*B[N,K]^T. 128x128 CTA tile, 128 threads, warp tile 64x64.
// smem stride 72 halves (144B): conflict-free cp.async stores + ldmatrix.
// Ch != null -> fp16 output (qkv); else fp32 output to Cf.
// ---------------------------------------------------------------------------
#define GS 72
#define GTILEH (128 * GS)                  // halves per stage per matrix
#define GSMEM (2 * 2 * GTILEH * 2)         // 73728 B

__global__ __launch_bounds__(128)
void gemm_hp(const __half* __restrict__ A, const __half* __restrict__ Bm,
             float* __restrict__ Cf, __half* __restrict__ Ch,
             int M, int N, int K)
{
    extern __shared__ __half smh[];
    __half* As = smh;
    __half* Bs = smh + 2 * GTILEH;

    const int tid  = threadIdx.x;
    const int lane = tid & 31;
    const int wid  = tid >> 5;
    const int wm   = wid & 1;
    const int wn   = wid >> 1;
    const int gr   = lane >> 2;
    const int qq   = lane & 3;
    const int row0 = blockIdx.y * 128;
    const int col0 = blockIdx.x * 128;

    // staging: thread covers rows rS+16j (j=0..7), 8-half chunk kq
    const int rS = tid >> 3;
    const int kq = tid & 7;
    const __half* AgB = A  + (size_t)(row0 + rS) * K + kq * 8;
    const __half* BgB = Bm + (size_t)(col0 + rS) * K + kq * 8;
    const uint32_t sA = s2u(As), sB = s2u(Bs);
    const uint32_t soffB = (uint32_t)(rS * GS + kq * 8) * 2;

    // ldmatrix lane address components
    const int rowA = lane & 15, colA = 8 * (lane >> 4);               // A-type
    const int rowB = (lane & 7) + 8 * (lane >> 4), colB = 8 * ((lane >> 3) & 1); // B-type
    const uint32_t aBase = sA + (uint32_t)((wm * 64 + rowA) * GS + colA) * 2;
    const uint32_t bBase = sB + (uint32_t)((wn * 64 + rowB) * GS + colB) * 2;

    float acc[4][8][4];
#pragma unroll
    for (int i = 0; i < 4; ++i)
#pragma unroll
        for (int j = 0; j < 8; ++j)
#pragma unroll
            for (int v = 0; v < 4; ++v) acc[i][j][v] = 0.f;

    const int nk = K >> 6;   // BK=64

    // prologue: stage 0
#pragma unroll
    for (int j = 0; j < 8; ++j) {
        cp16(sA + soffB + (uint32_t)(16 * j * GS) * 2, AgB + (size_t)(16 * j) * K);
        cp16(sB + soffB + (uint32_t)(16 * j * GS) * 2, BgB + (size_t)(16 * j) * K);
    }
    CP_COMMIT();

    for (int it = 0; it < nk; ++it) {
        CP_WAIT0();
        __syncthreads();

        if (it + 1 < nk) {
            const uint32_t so = (uint32_t)(((it + 1) & 1) * GTILEH) * 2;
            const int kc = (it + 1) << 6;
#pragma unroll
            for (int j = 0; j < 8; ++j) {
                cp16(sA + so + soffB + (uint32_t)(16 * j * GS) * 2,
                     AgB + (size_t)(16 * j) * K + kc);
                cp16(sB + so + soffB + (uint32_t)(16 * j * GS) * 2,
                     BgB + (size_t)(16 * j) * K + kc);
            }
            CP_COMMIT();
        }

        const uint32_t aB = aBase + (uint32_t)((it & 1) * GTILEH) * 2;
        const uint32_t bB = bBase + (uint32_t)((it & 1) * GTILEH) * 2;
#pragma unroll
        for (int kk = 0; kk < 4; ++kk) {
            uint32_t af[4][4], bf[4][4];
#pragma unroll
            for (int i = 0; i < 4; ++i)
                ldsm4(af[i], aB + (uint32_t)(i * 16 * GS + kk * 16) * 2);
#pragma unroll
            for (int p = 0; p < 4; ++p)
                ldsm4(bf[p], bB + (uint32_t)(p * 16 * GS + kk * 16) * 2);
#pragma unroll
            for (int i = 0; i < 4; ++i)
#pragma unroll
                for (int j = 0; j < 8; ++j)
                    mma_f16(acc[i][j], af[i], &bf[j >> 1][(j & 1) * 2]);
        }
    }

    const int egc = qq * 2;
#pragma unroll
    for (int i = 0; i < 4; ++i) {
#pragma unroll
        for (int j = 0; j < 8; ++j) {
            const size_t base = (size_t)(row0 + wm * 64 + i * 16 + gr) * N +
                                col0 + wn * 64 + j * 8 + egc;
            if (Ch) {
                *(__half2*)(Ch + base) = __floats2half2_rn(acc[i][j][0], acc[i][j][1]);
                *(__half2*)(Ch + base + 8 * (size_t)N) = __floats2half2_rn(acc[i][j][2], acc[i][j][3]);
            } else {
                *(float2*)(Cf + base) = make_float2(acc[i][j][0], acc[i][j][1]);
                *(float2*)(Cf + base + 8 * (size_t)N) = make_float2(acc[i][j][2], acc[i][j][3]);
            }
        }
    }
}

// ---------------------------------------------------------------------------
// RMSNorm + RoPE: reads fp16 qkv, fp32 math, writes fp16 q/k (plain layout).
// Folds softmax scale and log2(e) into Q.
// ---------------------------------------------------------------------------
__global__ __launch_bounds__(128)
void norm_rope(const float* __restrict__ freqs,
               const float* __restrict__ qw, const float* __restrict__ kw)
{
    const int tok  = blockIdx.x;
    const int head = blockIdx.y;
    const int d    = threadIdx.x;
    const int s    = tok & (SEQ - 1);
    const bool isq = head < NH;
    const __half* src = g_qkvh + (size_t)tok * EQKV +
                        (isq ? head * HD : DMODEL + (head - NH) * HD);
    float x = __half2float(src[d]);
    float v = x * x;
#pragma unroll
    for (int o = 16; o; o >>= 1) v += __shfl_xor_sync(0xffffffffu, v, o);
    __shared__ float red[4];
    if ((d & 31) == 0) red[d >> 5] = v;
    __syncthreads();
    v = red[0] + red[1] + red[2] + red[3];
    float rs = rsqrtf(v * (1.f / HD) + 1e-5f);
    float w  = isq ? qw[d] : kw[d];
    float xn = x * rs * w;
    float cr = freqs[s * HD + (d & ~1)];
    float ci = freqs[s * HD + (d & ~1) + 1];
    float other = __shfl_xor_sync(0xffffffffu, xn, 1);
    float out = (d & 1) ? fmaf(xn, cr, other * ci)
                        : fmaf(xn, cr, -other * ci);
    if (isq) {
        const float qscale = 0.08838834764831845f * 1.44269504088896341f; // D^-0.5 * log2e
        g_qh[(size_t)tok * (NH * HD) + head * HD + d] = __float2half_rn(out * qscale);
    } else {
        g_kh[(size_t)tok * (NKV * HD) + (head - NH) * HD + d] = __float2half_rn(out);
    }
}

// ---------------------------------------------------------------------------
// Flash attention, fp16 mma.sync + ldmatrix (V via ldmatrix.trans).
// 128 threads (4 warps), 64-q tile; K/V share one smem buffer.
// ---------------------------------------------------------------------------
#define QS 136
#define KS 136
#define PS 72
#define ASMEM ((64 * QS + 64 * KS + 64 * PS) * 2)   // 44032 B

__global__ __launch_bounds__(128, 2)
void attn_hp()
{
    extern __shared__ __half smh[];
    __half* Qsm  = smh;
    __half* KVsm = Qsm + 64 * QS;
    __half* Psm  = KVsm + 64 * KS;
    const uint32_t qB = s2u(Qsm), kvB = s2u(KVsm), pB = s2u(Psm);

    const int qt  = (int)gridDim.x - 1 - (int)blockIdx.x;   // big tiles first
    const int h   = blockIdx.y;
    const int b   = blockIdx.z;
    const int kvh = h >> 2;
    const int q0  = qt * 64;
    const int tid = threadIdx.x;
    const int w   = tid >> 5;
    const int lane = tid & 31;
    const int gr  = lane >> 2;
    const int qq  = lane & 3;
    const int r0l = w * 16 + gr;
    const int r1l = r0l + 8;

    // ldmatrix lane address components
    const int rowA = lane & 15, colA = 8 * (lane >> 4);
    const int rowB = (lane & 7) + 8 * (lane >> 4), colB = 8 * ((lane >> 3) & 1);
    const uint32_t qAddr = qB + (uint32_t)((w * 16 + rowA) * QS + colA) * 2;
    const uint32_t kAddr = kvB + (uint32_t)(rowB * KS + colB) * 2;
    const uint32_t pAddr = pB + (uint32_t)((w * 16 + rowA) * PS + colA) * 2;
    const uint32_t vAddr = kvB + (uint32_t)((lane & 15) * KS + 8 * (lane >> 4)) * 2;

    // Stage Q via cp.async
    {
        const __half* src = g_qh + (size_t)(b * SEQ + q0) * (NH * HD) + h * HD;
#pragma unroll
        for (int it = 0; it < 8; ++it) {
            int idx = tid + 128 * it;
            int r = idx >> 4, c = (idx & 15) * 8;
            cp16(qB + (uint32_t)(r * QS + c) * 2, src + (size_t)r * (NH * HD) + c);
        }
        CP_COMMIT();
    }

    float m0 = -1e30f, m1 = -1e30f, l0 = 0.f, l1 = 0.f;
    float O[16][4];
#pragma unroll
    for (int nt = 0; nt < 16; ++nt)
#pragma unroll
        for (int v = 0; v < 4; ++v) O[nt][v] = 0.f;

    for (int kt = 0; kt <= qt; ++kt) {
        const int k0 = kt * 64;
        __syncthreads();  // prev PV done with KV buffer
        // Stage K via cp.async
        {
            const __half* src = g_kh + (size_t)(b * SEQ + k0) * (NKV * HD) + kvh * HD;
#pragma unroll
            for (int it = 0; it < 8; ++it) {
                int idx = tid + 128 * it;
                int r = idx >> 4, c = (idx & 15) * 8;
                cp16(kvB + (uint32_t)(r * KS + c) * 2, src + (size_t)r * (NKV * HD) + c);
            }
            CP_COMMIT();
            CP_WAIT0();
        }
        __syncthreads();

        // S = Q K^T
        float s[8][4];
#pragma unroll
        for (int nt = 0; nt < 8; ++nt)
#pragma unroll
            for (int v = 0; v < 4; ++v) s[nt][v] = 0.f;

#pragma unroll
        for (int kk = 0; kk < 8; ++kk) {
            uint32_t af[4], bf[4][4];
            ldsm4(af, qAddr + (uint32_t)(kk * 16) * 2);
#pragma unroll
            for (int p = 0; p < 4; ++p)
                ldsm4(bf[p], kAddr + (uint32_t)(p * 16 * KS + kk * 16) * 2);
#pragma unroll
            for (int nt = 0; nt < 8; ++nt)
                mma_f16(s[nt], af, &bf[nt >> 1][(nt & 1) * 2]);
        }

        // Softmax (registers)
        if (kt == qt) {
#pragma unroll
            for (int nt = 0; nt < 8; ++nt) {
                int cb = nt * 8 + 2 * qq;
                if (cb     > r0l) s[nt][0] = -1e30f;
                if (cb + 1 > r0l) s[nt][1] = -1e30f;
                if (cb     > r1l) s[nt][2] = -1e30f;
                if (cb + 1 > r1l) s[nt][3] = -1e30f;
            }
        }
        float ml0 = -1e30f, ml1 = -1e30f;
#pragma unroll
        for (int nt = 0; nt < 8; ++nt) {
            ml0 = fmaxf(ml0, fmaxf(s[nt][0], s[nt][1]));
            ml1 = fmaxf(ml1, fmaxf(s[nt][2], s[nt][3]));
        }
        ml0 = fmaxf(ml0, __shfl_xor_sync(0xffffffffu, ml0, 1));
        ml0 = fmaxf(ml0, __shfl_xor_sync(0xffffffffu, ml0, 2));
        ml1 = fmaxf(ml1, __shfl_xor_sync(0xffffffffu, ml1, 1));
        ml1 = fmaxf(ml1, __shfl_xor_sync(0xffffffffu, ml1, 2));
        float mn0 = fmaxf(m0, ml0), mn1 = fmaxf(m1, ml1);
        float c0f = exp2f(m0 - mn0), c1f = exp2f(m1 - mn1);
        m0 = mn0; m1 = mn1;
        __half2 ph0[8], ph1[8];
        float rs0 = 0.f, rs1 = 0.f;
#pragma unroll
        for (int nt = 0; nt < 8; ++nt) {
            ph0[nt] = __floats2half2_rn(exp2f(s[nt][0] - mn0), exp2f(s[nt][1] - mn0));
            ph1[nt] = __floats2half2_rn(exp2f(s[nt][2] - mn1), exp2f(s[nt][3] - mn1));
            rs0 += __low2float(ph0[nt]) + __high2float(ph0[nt]);
            rs1 += __low2float(ph1[nt]) + __high2float(ph1[nt]);
        }
        rs0 += __shfl_xor_sync(0xffffffffu, rs0, 1);
        rs0 += __shfl_xor_sync(0xffffffffu, rs0, 2);
        rs1 += __shfl_xor_sync(0xffffffffu, rs1, 1);
        rs1 += __shfl_xor_sync(0xffffffffu, rs1, 2);
        l0 = l0 * c0f + rs0;
        l1 = l1 * c1f + rs1;
#pragma unroll
        for (int nt = 0; nt < 16; ++nt) {
            O[nt][0] *= c0f; O[nt][1] *= c0f;
            O[nt][2] *= c1f; O[nt][3] *= c1f;
        }

        __syncthreads();  // all warps done reading K

        // Stage V via cp.async (overlaps P writes)
        {
            const __half* src = g_qkvh + (size_t)(b * SEQ + k0) * EQKV +
                                (DMODEL + NKV * HD) + kvh * HD;
#pragma unroll
            for (int it = 0; it < 8; ++it) {
                int idx = tid + 128 * it;
                int r = idx >> 4, c = (idx & 15) * 8;
                cp16(kvB + (uint32_t)(r * KS + c) * 2, src + (size_t)r * EQKV + c);
            }
            CP_COMMIT();
        }
#pragma unroll
        for (int nt = 0; nt < 8; ++nt) {
            *(__half2*)(Psm + r0l * PS + nt * 8 + 2 * qq) = ph0[nt];
            *(__half2*)(Psm + r1l * PS + nt * 8 + 2 * qq) = ph1[nt];
        }
        CP_WAIT0();
        __syncthreads();  // V + P visible

        // O += P V   (V fragments via ldmatrix.trans)
#pragma unroll
        for (int kk = 0; kk < 4; ++kk) {
            uint32_t af[4], bf[8][4];
            ldsm4(af, pAddr + (uint32_t)(kk * 16) * 2);
#pragma unroll
            for (int p = 0; p < 8; ++p)
                ldsm4t(bf[p], vAddr + (uint32_t)(kk * 16 * KS + p * 16) * 2);
#pragma unroll
            for (int nt = 0; nt < 16; ++nt)
                mma_f16(O[nt], af, &bf[nt >> 1][(nt & 1) * 2]);
        }
    }

    float inv0 = 1.f / l0, inv1 = 1.f / l1;
    __half* y0 = g_yh + (size_t)(b * SEQ + q0 + r0l) * (NH * HD) + h * HD;
    __half* y1 = g_yh + (size_t)(b * SEQ + q0 + r1l) * (NH * HD) + h * HD;
#pragma unroll
    for (int nt = 0; nt < 16; ++nt) {
        *(__half2*)(y0 + nt * 8 + 2 * qq) = __floats2half2_rn(O[nt][0] * inv0, O[nt][1] * inv0);
        *(__half2*)(y1 + nt * 8 + 2 * qq) = __floats2half2_rn(O[nt][2] * inv1, O[nt][3] * inv1);
    }
}

// ---------------------------------------------------------------------------
extern "C" void kernel_launch(void* const* d_in, const int* in_sizes, int n_in,
                              void* d_out, int out_size)
{
    const float* x    = (const float*)d_in[0];
    const float* fr   = (const float*)d_in[1];
    const float* wqkv = (const float*)d_in[3];
    const float* wo   = (const float*)d_in[4];
    const float* qw   = (const float*)d_in[5];
    const float* kw   = (const float*)d_in[6];
    float* out = (float*)d_out;

    __half *qkvh_p, *xh_p, *wqkvh_p, *woh_p, *yh_p;
    cudaGetSymbolAddress((void**)&qkvh_p,  g_qkvh);
    cudaGetSymbolAddress((void**)&xh_p,    g_xh);
    cudaGetSymbolAddress((void**)&wqkvh_p, g_wqkvh);
    cudaGetSymbolAddress((void**)&woh_p,   g_woh);
    cudaGetSymbolAddress((void**)&yh_p,    g_yh);

    // 0) Convert inputs/weights to fp16
    to_half<<<(TOK * DMODEL) / 1024, 256>>>(x, xh_p);
    to_half<<<(EQKV * DMODEL) / 1024, 256>>>(wqkv, wqkvh_p);
    to_half<<<(DMODEL * NH * HD) / 1024, 256>>>(wo, woh_p);

    cudaFuncSetAttribute(gemm_hp, cudaFuncAttributeMaxDynamicSharedMemorySize, GSMEM);

    // 1) QKV projection (fp16 out)
    gemm_hp<<<dim3(EQKV / 128, TOK / 128), 128, GSMEM>>>(
        xh_p, wqkvh_p, nullptr, qkvh_p, TOK, EQKV, DMODEL);

    // 2) RMSNorm + RoPE
    norm_rope<<<dim3(TOK, NH + NKV), 128>>>(fr, qw, kw);

    // 3) Causal GQA flash attention
    attn_hp<<<dim3(SEQ / 64, NH, BATCH), 128, ASMEM>>>();

    // 4) Output projection (fp32 out)
    gemm_hp<<<dim3(DMODEL / 128, TOK / 128), 128, GSMEM>>>(
        yh_p, woh_p, out, nullptr, TOK, DMODEL, DMODEL);
}

// round 10
// speedup vs baseline: 8.6008x; 1.0362x over previous
#include <cuda_runtime.h>
#include <cuda_fp16.h>
#include <math.h>
#include <stdint.h>

#define BATCH  2
#define SEQ    2048
#define DMODEL 2048
#define NH     16
#define NKV    4
#define HD     128
#define EQKV   3072
#define TOK    (BATCH*SEQ)

// Scratch (device globals; no allocation allowed) — fp16
__device__ __half g_qkvh [(size_t)TOK * EQKV];
__device__ __half g_qh   [(size_t)TOK * NH  * HD];
__device__ __half g_kh   [(size_t)TOK * NKV * HD];
__device__ __half g_yh   [(size_t)TOK * NH  * HD];
__device__ __half g_xh   [(size_t)TOK * DMODEL];
__device__ __half g_wqkvh[(size_t)EQKV * DMODEL];
__device__ __half g_woh  [(size_t)DMODEL * NH * HD];

__device__ __forceinline__ uint32_t s2u(const void* p) {
    uint32_t a;
    asm("{ .reg .u64 t; cvta.to.shared.u64 t, %1; cvt.u32.u64 %0, t; }"
        : "=r"(a) : "l"(p));
    return a;
}
__device__ __forceinline__ void mma_f16(float* c, const uint32_t* a, const uint32_t* b) {
    asm volatile(
        "mma.sync.aligned.m16n8k16.row.col.f32.f16.f16.f32 "
        "{%0,%1,%2,%3}, {%4,%5,%6,%7}, {%8,%9}, {%0,%1,%2,%3};"
        : "+f"(c[0]), "+f"(c[1]), "+f"(c[2]), "+f"(c[3])
        : "r"(a[0]), "r"(a[1]), "r"(a[2]), "r"(a[3]),
          "r"(b[0]), "r"(b[1]));
}
__device__ __forceinline__ void ldsm4(uint32_t* r, uint32_t a) {
    asm volatile("ldmatrix.sync.aligned.m8n8.x4.shared.b16 {%0,%1,%2,%3}, [%4];"
        : "=r"(r[0]), "=r"(r[1]), "=r"(r[2]), "=r"(r[3]) : "r"(a));
}
__device__ __forceinline__ void ldsm4t(uint32_t* r, uint32_t a) {
    asm volatile("ldmatrix.sync.aligned.m8n8.x4.trans.shared.b16 {%0,%1,%2,%3}, [%4];"
        : "=r"(r[0]), "=r"(r[1]), "=r"(r[2]), "=r"(r[3]) : "r"(a));
}
__device__ __forceinline__ void cp16(uint32_t smem_dst, const void* gptr) {
    asm volatile("cp.async.cg.shared.global [%0], [%1], 16;"
                 :: "r"(smem_dst), "l"(gptr) : "memory");
}
#define CP_COMMIT() asm volatile("cp.async.commit_group;" ::: "memory")
#define CP_WAIT0()  asm volatile("cp.async.wait_group 0;" ::: "memory")
#define CP_WAIT1()  asm volatile("cp.async.wait_group 1;" ::: "memory")

// ---------------------------------------------------------------------------
// Merged fp32 -> fp16 conversion of x, wqkv, wo in one launch.
// ---------------------------------------------------------------------------
#define N_X  ((size_t)TOK * DMODEL)
#define N_W1 ((size_t)EQKV * DMODEL)
#define N_W2 ((size_t)DMODEL * NH * HD)

__global__ __launch_bounds__(256)
void to_half_all(const float* __restrict__ x, const float* __restrict__ wqkv,
                 const float* __restrict__ wo)
{
    size_t i = ((size_t)blockIdx.x * 256 + threadIdx.x) * 4;
    const float* s; __half* d; size_t off;
    if (i < N_X)            { s = x;    d = g_xh;    off = i; }
    else if (i < N_X + N_W1){ s = wqkv; d = g_wqkvh; off = i - N_X; }
    else                    { s = wo;   d = g_woh;   off = i - N_X - N_W1; }
    float4 v = *(const float4*)(s + off);
    __half2* dp = (__half2*)(d + off);
    dp[0] = __floats2half2_rn(v.x, v.y);
    dp[1] = __floats2half2_rn(v.z, v.w);
}

// ---------------------------------------------------------------------------
// fp16 mma.sync GEMM (NT): BK=32, 3-stage cp.async, XOR-swizzled smem.
// 128x128 CTA tile, 128 threads (4 warps), warp tile 64x64.
// Swizzle: half-col chunk c (0..3) stored at c ^ ((row>>1)&3).
// ---------------------------------------------------------------------------
#define GTILEH (128 * 32)                 // halves per stage per matrix (8 KB)
#define NST 3
#define GSMEM (NST * 2 * GTILEH * 2)      // 49152 B

__global__ __launch_bounds__(128)
void gemm_hp(const __half* __restrict__ A, const __half* __restrict__ Bm,
             float* __restrict__ Cf, __half* __restrict__ Ch,
             int M, int N, int K)
{
    extern __shared__ __half smh[];
    __half* As = smh;
    __half* Bs = smh + NST * GTILEH;

    const int tid  = threadIdx.x;
    const int lane = tid & 31;
    const int wid  = tid >> 5;
    const int wm   = wid & 1;
    const int wn   = wid >> 1;
    const int gr   = lane >> 2;
    const int qq   = lane & 3;
    const int row0 = blockIdx.y * 128;
    const int col0 = blockIdx.x * 128;

    // staging: kq = 16B chunk (0..3), rb = base row (0..31), rows rb+32j
    const int kq = tid & 3, rb = tid >> 2;
    const __half* Ag = A  + (size_t)(row0 + rb) * K + kq * 8;
    const __half* Bg = Bm + (size_t)(col0 + rb) * K + kq * 8;
    const uint32_t sA = s2u(As), sB = s2u(Bs);
    const uint32_t d0 = (uint32_t)(rb * 32 + ((kq ^ ((rb >> 1) & 3)) << 3)) * 2;

    // ldmatrix precompute
    const int rowA = lane & 15, hiA = lane >> 4;
    const int rowB = (lane & 7) + 8 * (lane >> 4), hiB = (lane >> 3) & 1;
    uint32_t aOff[4], bOff[4];
    int aSw[4], bSw[4];
#pragma unroll
    for (int i = 0; i < 4; ++i) {
        int r = wm * 64 + i * 16 + rowA;
        aOff[i] = (uint32_t)r * 64; aSw[i] = (r >> 1) & 3;
    }
#pragma unroll
    for (int p = 0; p < 4; ++p) {
        int r = wn * 64 + p * 16 + rowB;
        bOff[p] = (uint32_t)r * 64; bSw[p] = (r >> 1) & 3;
    }

    float acc[4][8][4];
#pragma unroll
    for (int i = 0; i < 4; ++i)
#pragma unroll
        for (int j = 0; j < 8; ++j)
#pragma unroll
            for (int v = 0; v < 4; ++v) acc[i][j][v] = 0.f;

    const int nk = K >> 5;

    auto issue = [&](int st) {
        const uint32_t ab = sA + (uint32_t)((st % NST) * GTILEH) * 2 + d0;
        const uint32_t bb = sB + (uint32_t)((st % NST) * GTILEH) * 2 + d0;
        const int kc = st << 5;
#pragma unroll
        for (int j = 0; j < 4; ++j) {
            cp16(ab + j * 2048, Ag + (size_t)(32 * j) * K + kc);
            cp16(bb + j * 2048, Bg + (size_t)(32 * j) * K + kc);
        }
    };

    issue(0); CP_COMMIT();
    issue(1); CP_COMMIT();

    for (int it = 0; it < nk; ++it) {
        CP_WAIT1();
        __syncthreads();
        if (it + 2 < nk) issue(it + 2);
        CP_COMMIT();   // always commit (keeps group accounting exact at tail)

        const uint32_t aS = sA + (uint32_t)((it % NST) * GTILEH) * 2;
        const uint32_t bS = sB + (uint32_t)((it % NST) * GTILEH) * 2;
#pragma unroll
        for (int kk = 0; kk < 2; ++kk) {
            uint32_t af[4][4], bf[4][4];
#pragma unroll
            for (int i = 0; i < 4; ++i)
                ldsm4(af[i], aS + aOff[i] + (uint32_t)(((kk * 2 + hiA) ^ aSw[i]) << 4));
#pragma unroll
            for (int p = 0; p < 4; ++p)
                ldsm4(bf[p], bS + bOff[p] + (uint32_t)(((kk * 2 + hiB) ^ bSw[p]) << 4));
#pragma unroll
            for (int i = 0; i < 4; ++i)
#pragma unroll
                for (int j = 0; j < 8; ++j)
                    mma_f16(acc[i][j], af[i], &bf[j >> 1][(j & 1) * 2]);
        }
    }

    const int egc = qq * 2;
#pragma unroll
    for (int i = 0; i < 4; ++i) {
#pragma unroll
        for (int j = 0; j < 8; ++j) {
            const size_t base = (size_t)(row0 + wm * 64 + i * 16 + gr) * N +
                                col0 + wn * 64 + j * 8 + egc;
            if (Ch) {
                *(__half2*)(Ch + base) = __floats2half2_rn(acc[i][j][0], acc[i][j][1]);
                *(__half2*)(Ch + base + 8 * (size_t)N) = __floats2half2_rn(acc[i][j][2], acc[i][j][3]);
            } else {
                *(float2*)(Cf + base) = make_float2(acc[i][j][0], acc[i][j][1]);
                *(float2*)(Cf + base + 8 * (size_t)N) = make_float2(acc[i][j][2], acc[i][j][3]);
            }
        }
    }
}

// ---------------------------------------------------------------------------
// RMSNorm + RoPE (fp16 in/out, fp32 math). Folds D^-0.5 * log2e into Q.
// ---------------------------------------------------------------------------
__global__ __launch_bounds__(128)
void norm_rope(const float* __restrict__ freqs,
               const float* __restrict__ qw, const float* __restrict__ kw)
{
    const int tok  = blockIdx.x;
    const int head = blockIdx.y;
    const int d    = threadIdx.x;
    const int s    = tok & (SEQ - 1);
    const bool isq = head < NH;
    const __half* src = g_qkvh + (size_t)tok * EQKV +
                        (isq ? head * HD : DMODEL + (head - NH) * HD);
    float x = __half2float(src[d]);
    float v = x * x;
#pragma unroll
    for (int o = 16; o; o >>= 1) v += __shfl_xor_sync(0xffffffffu, v, o);
    __shared__ float red[4];
    if ((d & 31) == 0) red[d >> 5] = v;
    __syncthreads();
    v = red[0] + red[1] + red[2] + red[3];
    float rs = rsqrtf(v * (1.f / HD) + 1e-5f);
    float w  = isq ? qw[d] : kw[d];
    float xn = x * rs * w;
    float cr = freqs[s * HD + (d & ~1)];
    float ci = freqs[s * HD + (d & ~1) + 1];
    float other = __shfl_xor_sync(0xffffffffu, xn, 1);
    float out = (d & 1) ? fmaf(xn, cr, other * ci)
                        : fmaf(xn, cr, -other * ci);
    if (isq) {
        const float qscale = 0.08838834764831845f * 1.44269504088896341f;
        g_qh[(size_t)tok * (NH * HD) + head * HD + d] = __float2half_rn(out * qscale);
    } else {
        g_kh[(size_t)tok * (NKV * HD) + (head - NH) * HD + d] = __float2half_rn(out);
    }
}

// ---------------------------------------------------------------------------
// Flash attention, fp16 mma.sync + ldmatrix. Double-buffered K and V,
// K/V(kt+1) prefetched during PV(kt). 1 __syncthreads + 1 wait per iter.
// ---------------------------------------------------------------------------
#define QS 136
#define KS 136
#define PS 72
#define KVT (64 * KS)
#define ASMEM ((64 * QS + 4 * KVT + 64 * PS) * 2)   // 96256 B

__global__ __launch_bounds__(128, 2)
void attn_hp()
{
    extern __shared__ __half smh[];
    __half* Qsm = smh;
    __half* Ksm = Qsm + 64 * QS;      // 2 buffers
    __half* Vsm = Ksm + 2 * KVT;      // 2 buffers
    __half* Psm = Vsm + 2 * KVT;
    const uint32_t qB = s2u(Qsm), kB0 = s2u(Ksm), vB0 = s2u(Vsm), pB = s2u(Psm);

    const int qt  = (int)gridDim.x - 1 - (int)blockIdx.x;
    const int h   = blockIdx.y;
    const int b   = blockIdx.z;
    const int kvh = h >> 2;
    const int q0  = qt * 64;
    const int tid = threadIdx.x;
    const int w   = tid >> 5;
    const int lane = tid & 31;
    const int gr  = lane >> 2;
    const int qq  = lane & 3;
    const int r0l = w * 16 + gr;
    const int r1l = r0l + 8;

    const int rowA = lane & 15, rowB = (lane & 7) + 8 * (lane >> 4);
    const int colA = 8 * (lane >> 4), colB = 8 * ((lane >> 3) & 1);
    const uint32_t qAddr = qB + (uint32_t)((w * 16 + rowA) * QS + colA) * 2;
    const uint32_t pAddr = pB + (uint32_t)((w * 16 + rowA) * PS + colA) * 2;
    const uint32_t kOff  = (uint32_t)(rowB * KS + colB) * 2;
    const uint32_t vOff  = (uint32_t)((lane & 15) * KS + 8 * (lane >> 4)) * 2;

    // staging helpers: 8 cp16 per thread per 64x128 tile
    const int sr = tid >> 4, sc = (tid & 15) * 8;
    auto stageK = [&](int kt, int buf) {
        const __half* src = g_kh + (size_t)(b * SEQ + kt * 64 + sr) * (NKV * HD) + kvh * HD + sc;
        uint32_t dst = kB0 + (uint32_t)(buf * KVT) * 2 + (uint32_t)(sr * KS + sc) * 2;
#pragma unroll
        for (int it = 0; it < 8; ++it)
            cp16(dst + (uint32_t)(8 * it * KS) * 2, src + (size_t)(8 * it) * (NKV * HD));
    };
    auto stageV = [&](int kt, int buf) {
        const __half* src = g_qkvh + (size_t)(b * SEQ + kt * 64 + sr) * EQKV +
                            (DMODEL + NKV * HD) + kvh * HD + sc;
        uint32_t dst = vB0 + (uint32_t)(buf * KVT) * 2 + (uint32_t)(sr * KS + sc) * 2;
#pragma unroll
        for (int it = 0; it < 8; ++it)
            cp16(dst + (uint32_t)(8 * it * KS) * 2, src + (size_t)(8 * it) * EQKV);
    };

    // prologue: Q + K0 + V0 in one group
    {
        const __half* src = g_qh + (size_t)(b * SEQ + q0 + sr) * (NH * HD) + h * HD + sc;
        uint32_t dst = qB + (uint32_t)(sr * QS + sc) * 2;
#pragma unroll
        for (int it = 0; it < 8; ++it)
            cp16(dst + (uint32_t)(8 * it * QS) * 2, src + (size_t)(8 * it) * (NH * HD));
        stageK(0, 0); stageV(0, 0);
        CP_COMMIT(); CP_WAIT0();
        __syncthreads();
    }

    float m0 = -1e30f, m1 = -1e30f, l0 = 0.f, l1 = 0.f;
    float O[16][4];
#pragma unroll
    for (int nt = 0; nt < 16; ++nt)
#pragma unroll
        for (int v = 0; v < 4; ++v) O[nt][v] = 0.f;

    for (int kt = 0; kt <= qt; ++kt) {
        const uint32_t kAddr = kB0 + (uint32_t)((kt & 1) * KVT) * 2 + kOff;
        const uint32_t vAddr = vB0 + (uint32_t)((kt & 1) * KVT) * 2 + vOff;

        // S = Q K^T
        float s[8][4];
#pragma unroll
        for (int nt = 0; nt < 8; ++nt)
#pragma unroll
            for (int v = 0; v < 4; ++v) s[nt][v] = 0.f;
#pragma unroll
        for (int kk = 0; kk < 8; ++kk) {
            uint32_t af[4], bf[4][4];
            ldsm4(af, qAddr + (uint32_t)(kk * 16) * 2);
#pragma unroll
            for (int p = 0; p < 4; ++p)
                ldsm4(bf[p], kAddr + (uint32_t)(p * 16 * KS + kk * 16) * 2);
#pragma unroll
            for (int nt = 0; nt < 8; ++nt)
                mma_f16(s[nt], af, &bf[nt >> 1][(nt & 1) * 2]);
        }

        // softmax (all warp-local)
        if (kt == qt) {
#pragma unroll
            for (int nt = 0; nt < 8; ++nt) {
                int cb = nt * 8 + 2 * qq;
                if (cb     > r0l) s[nt][0] = -1e30f;
                if (cb + 1 > r0l) s[nt][1] = -1e30f;
                if (cb     > r1l) s[nt][2] = -1e30f;
                if (cb + 1 > r1l) s[nt][3] = -1e30f;
            }
        }
        float ml0 = -1e30f, ml1 = -1e30f;
#pragma unroll
        for (int nt = 0; nt < 8; ++nt) {
            ml0 = fmaxf(ml0, fmaxf(s[nt][0], s[nt][1]));
            ml1 = fmaxf(ml1, fmaxf(s[nt][2], s[nt][3]));
        }
        ml0 = fmaxf(ml0, __shfl_xor_sync(0xffffffffu, ml0, 1));
        ml0 = fmaxf(ml0, __shfl_xor_sync(0xffffffffu, ml0, 2));
        ml1 = fmaxf(ml1, __shfl_xor_sync(0xffffffffu, ml1, 1));
        ml1 = fmaxf(ml1, __shfl_xor_sync(0xffffffffu, ml1, 2));
        float mn0 = fmaxf(m0, ml0), mn1 = fmaxf(m1, ml1);
        float c0f = exp2f(m0 - mn0), c1f = exp2f(m1 - mn1);
        m0 = mn0; m1 = mn1;
        __half2 ph0[8], ph1[8];
        float rs0 = 0.f, rs1 = 0.f;
#pragma unroll
        for (int nt = 0; nt < 8; ++nt) {
            ph0[nt] = __floats2half2_rn(exp2f(s[nt][0] - mn0), exp2f(s[nt][1] - mn0));
            ph1[nt] = __floats2half2_rn(exp2f(s[nt][2] - mn1), exp2f(s[nt][3] - mn1));
            rs0 += __low2float(ph0[nt]) + __high2float(ph0[nt]);
            rs1 += __low2float(ph1[nt]) + __high2float(ph1[nt]);
        }
        rs0 += __shfl_xor_sync(0xffffffffu, rs0, 1);
        rs0 += __shfl_xor_sync(0xffffffffu, rs0, 2);
        rs1 += __shfl_xor_sync(0xffffffffu, rs1, 1);
        rs1 += __shfl_xor_sync(0xffffffffu, rs1, 2);
        l0 = l0 * c0f + rs0;
        l1 = l1 * c1f + rs1;
#pragma unroll
        for (int nt = 0; nt < 16; ++nt) {
            O[nt][0] *= c0f; O[nt][1] *= c0f;
            O[nt][2] *= c1f; O[nt][3] *= c1f;
        }
        // P store (warp-local rows) + prefetch next K/V
#pragma unroll
        for (int nt = 0; nt < 8; ++nt) {
            *(__half2*)(Psm + r0l * PS + nt * 8 + 2 * qq) = ph0[nt];
            *(__half2*)(Psm + r1l * PS + nt * 8 + 2 * qq) = ph1[nt];
        }
        __syncwarp();

        if (kt < qt) {
            stageK(kt + 1, (kt + 1) & 1);
            stageV(kt + 1, (kt + 1) & 1);
            CP_COMMIT();
        }

        // O += P V (ldmatrix.trans on V)
#pragma unroll
        for (int kk = 0; kk < 4; ++kk) {
            uint32_t af[4], bf[8][4];
            ldsm4(af, pAddr + (uint32_t)(kk * 16) * 2);
#pragma unroll
            for (int p = 0; p < 8; ++p)
                ldsm4t(bf[p], vAddr + (uint32_t)(kk * 16 * KS + p * 16) * 2);
#pragma unroll
            for (int nt = 0; nt < 16; ++nt)
                mma_f16(O[nt], af, &bf[nt >> 1][(nt & 1) * 2]);
        }

        if (kt < qt) {
            CP_WAIT0();
            __syncthreads();
        }
    }

    float inv0 = 1.f / l0, inv1 = 1.f / l1;
    __half* y0 = g_yh + (size_t)(b * SEQ + q0 + r0l) * (NH * HD) + h * HD;
    __half* y1 = g_yh + (size_t)(b * SEQ + q0 + r1l) * (NH * HD) + h * HD;
#pragma unroll
    for (int nt = 0; nt < 16; ++nt) {
        *(__half2*)(y0 + nt * 8 + 2 * qq) = __floats2half2_rn(O[nt][0] * inv0, O[nt][1] * inv0);
        *(__half2*)(y1 + nt * 8 + 2 * qq) = __floats2half2_rn(O[nt][2] * inv1, O[nt][3] * inv1);
    }
}

// ---------------------------------------------------------------------------
extern "C" void kernel_launch(void* const* d_in, const int* in_sizes, int n_in,
                              void* d_out, int out_size)
{
    const float* x    = (const float*)d_in[0];
    const float* fr   = (const float*)d_in[1];
    const float* wqkv = (const float*)d_in[3];
    const float* wo   = (const float*)d_in[4];
    const float* qw   = (const float*)d_in[5];
    const float* kw   = (const float*)d_in[6];
    float* out = (float*)d_out;

    __half *qkvh_p, *yh_p, *xh_p, *wqkvh_p, *woh_p;
    cudaGetSymbolAddress((void**)&qkvh_p,  g_qkvh);
    cudaGetSymbolAddress((void**)&yh_p,    g_yh);
    cudaGetSymbolAddress((void**)&xh_p,    g_xh);
    cudaGetSymbolAddress((void**)&wqkvh_p, g_wqkvh);
    cudaGetSymbolAddress((void**)&woh_p,   g_woh);

    // 0) Convert inputs/weights to fp16 (single launch)
    const size_t ntot = N_X + N_W1 + N_W2;
    to_half_all<<<(unsigned)(ntot / 1024), 256>>>(x, wqkv, wo);

    cudaFuncSetAttribute(gemm_hp, cudaFuncAttributeMaxDynamicSharedMemorySize, GSMEM);
    cudaFuncSetAttribute(attn_hp, cudaFuncAttributeMaxDynamicSharedMemorySize, ASMEM);

    // 1) QKV projection (fp16 out)
    gemm_hp<<<dim3(EQKV / 128, TOK / 128), 128, GSMEM>>>(
        xh_p, wqkvh_p, nullptr, qkvh_p, TOK, EQKV, DMODEL);

    // 2) RMSNorm + RoPE
    norm_rope<<<dim3(TOK, NH + NKV), 128>>>(fr, qw, kw);

    // 3) Causal GQA flash attention
    attn_hp<<<dim3(SEQ / 64, NH, BATCH), 128, ASMEM>>>();

    // 4) Output projection (fp32 out)
    gemm_hp<<<dim3(DMODEL / 128, TOK / 128), 128, GSMEM>>>(
        yh_p, woh_p, out, nullptr, TOK, DMODEL, DMODEL);
}

// round 11
// speedup vs baseline: 8.9237x; 1.0375x over previous
#include <cuda_runtime.h>
#include <cuda_fp16.h>
#include <math.h>
#include <stdint.h>

#define BATCH  2
#define SEQ    2048
#define DMODEL 2048
#define NH     16
#define NKV    4
#define HD     128
#define EQKV   3072
#define TOK    (BATCH*SEQ)

// Scratch (device globals; no allocation allowed) — fp16
__device__ __half g_qh   [(size_t)TOK * NH  * HD];   // 16 MB (normed, roped, scaled)
__device__ __half g_kh   [(size_t)TOK * NKV * HD];   //  4 MB (normed, roped)
__device__ __half g_vh   [(size_t)TOK * NKV * HD];   //  4 MB
__device__ __half g_yh   [(size_t)TOK * NH  * HD];   // 16 MB
__device__ __half g_xh   [(size_t)TOK * DMODEL];     // 16 MB
__device__ __half g_wqkvh[(size_t)EQKV * DMODEL];    // 12 MB
__device__ __half g_woh  [(size_t)DMODEL * NH * HD]; //  8 MB

__device__ __forceinline__ uint32_t s2u(const void* p) {
    uint32_t a;
    asm("{ .reg .u64 t; cvta.to.shared.u64 t, %1; cvt.u32.u64 %0, t; }"
        : "=r"(a) : "l"(p));
    return a;
}
__device__ __forceinline__ void mma_f16(float* c, const uint32_t* a, const uint32_t* b) {
    asm volatile(
        "mma.sync.aligned.m16n8k16.row.col.f32.f16.f16.f32 "
        "{%0,%1,%2,%3}, {%4,%5,%6,%7}, {%8,%9}, {%0,%1,%2,%3};"
        : "+f"(c[0]), "+f"(c[1]), "+f"(c[2]), "+f"(c[3])
        : "r"(a[0]), "r"(a[1]), "r"(a[2]), "r"(a[3]),
          "r"(b[0]), "r"(b[1]));
}
__device__ __forceinline__ void ldsm4(uint32_t* r, uint32_t a) {
    asm volatile("ldmatrix.sync.aligned.m8n8.x4.shared.b16 {%0,%1,%2,%3}, [%4];"
        : "=r"(r[0]), "=r"(r[1]), "=r"(r[2]), "=r"(r[3]) : "r"(a));
}
__device__ __forceinline__ void ldsm4t(uint32_t* r, uint32_t a) {
    asm volatile("ldmatrix.sync.aligned.m8n8.x4.trans.shared.b16 {%0,%1,%2,%3}, [%4];"
        : "=r"(r[0]), "=r"(r[1]), "=r"(r[2]), "=r"(r[3]) : "r"(a));
}
__device__ __forceinline__ void cp16(uint32_t smem_dst, const void* gptr) {
    asm volatile("cp.async.cg.shared.global [%0], [%1], 16;"
                 :: "r"(smem_dst), "l"(gptr) : "memory");
}
#define CP_COMMIT() asm volatile("cp.async.commit_group;" ::: "memory")
#define CP_WAIT0()  asm volatile("cp.async.wait_group 0;" ::: "memory")
#define CP_WAIT1()  asm volatile("cp.async.wait_group 1;" ::: "memory")

// ---------------------------------------------------------------------------
// Merged fp32 -> fp16 conversion of x, wqkv, wo in one launch.
// ---------------------------------------------------------------------------
#define N_X  ((size_t)TOK * DMODEL)
#define N_W1 ((size_t)EQKV * DMODEL)
#define N_W2 ((size_t)DMODEL * NH * HD)

__global__ __launch_bounds__(256)
void to_half_all(const float* __restrict__ x, const float* __restrict__ wqkv,
                 const float* __restrict__ wo)
{
    size_t i = ((size_t)blockIdx.x * 256 + threadIdx.x) * 4;
    const float* s; __half* d; size_t off;
    if (i < N_X)            { s = x;    d = g_xh;    off = i; }
    else if (i < N_X + N_W1){ s = wqkv; d = g_wqkvh; off = i - N_X; }
    else                    { s = wo;   d = g_woh;   off = i - N_X - N_W1; }
    float4 v = *(const float4*)(s + off);
    __half2* dp = (__half2*)(d + off);
    dp[0] = __floats2half2_rn(v.x, v.y);
    dp[1] = __floats2half2_rn(v.z, v.w);
}

// ---------------------------------------------------------------------------
// fp16 mma.sync GEMM (NT): BK=32, 3-stage cp.async, XOR-swizzled smem.
// 128x128 CTA tile, 128 threads (4 warps), warp tile 64x64.
// mode 0: plain fp32 store to Cf.
// mode 1: fused qkv epilogue — per-head RMSNorm + RoPE + scale, fp16 stores
//         to g_qh/g_kh (normed/roped) or g_vh (plain). Tile == one head.
// ---------------------------------------------------------------------------
#define GTILEH (128 * 32)
#define NST 3
#define GSMEM (NST * 2 * GTILEH * 2)      // 49152 B

__global__ __launch_bounds__(128)
void gemm_hp(const __half* __restrict__ A, const __half* __restrict__ Bm,
             float* __restrict__ Cf, int M, int N, int K, int mode,
             const float* __restrict__ freqs,
             const float* __restrict__ qw, const float* __restrict__ kw)
{
    extern __shared__ __half smh[];
    __half* As = smh;
    __half* Bs = smh + NST * GTILEH;

    const int tid  = threadIdx.x;
    const int lane = tid & 31;
    const int wid  = tid >> 5;
    const int wm   = wid & 1;
    const int wn   = wid >> 1;
    const int gr   = lane >> 2;
    const int qq   = lane & 3;
    const int row0 = blockIdx.y * 128;
    const int col0 = blockIdx.x * 128;

    const int kq = tid & 3, rb = tid >> 2;
    const __half* Ag = A  + (size_t)(row0 + rb) * K + kq * 8;
    const __half* Bg = Bm + (size_t)(col0 + rb) * K + kq * 8;
    const uint32_t sA = s2u(As), sB = s2u(Bs);
    const uint32_t d0 = (uint32_t)(rb * 32 + ((kq ^ ((rb >> 1) & 3)) << 3)) * 2;

    const int rowA = lane & 15, hiA = lane >> 4;
    const int rowB = (lane & 7) + 8 * (lane >> 4), hiB = (lane >> 3) & 1;
    uint32_t aOff[4], bOff[4];
    int aSw[4], bSw[4];
#pragma unroll
    for (int i = 0; i < 4; ++i) {
        int r = wm * 64 + i * 16 + rowA;
        aOff[i] = (uint32_t)r * 64; aSw[i] = (r >> 1) & 3;
    }
#pragma unroll
    for (int p = 0; p < 4; ++p) {
        int r = wn * 64 + p * 16 + rowB;
        bOff[p] = (uint32_t)r * 64; bSw[p] = (r >> 1) & 3;
    }

    float acc[4][8][4];
#pragma unroll
    for (int i = 0; i < 4; ++i)
#pragma unroll
        for (int j = 0; j < 8; ++j)
#pragma unroll
            for (int v = 0; v < 4; ++v) acc[i][j][v] = 0.f;

    const int nk = K >> 5;

    auto issue = [&](int st) {
        const uint32_t ab = sA + (uint32_t)((st % NST) * GTILEH) * 2 + d0;
        const uint32_t bb = sB + (uint32_t)((st % NST) * GTILEH) * 2 + d0;
        const int kc = st << 5;
#pragma unroll
        for (int j = 0; j < 4; ++j) {
            cp16(ab + j * 2048, Ag + (size_t)(32 * j) * K + kc);
            cp16(bb + j * 2048, Bg + (size_t)(32 * j) * K + kc);
        }
    };

    issue(0); CP_COMMIT();
    issue(1); CP_COMMIT();

    for (int it = 0; it < nk; ++it) {
        CP_WAIT1();
        __syncthreads();
        if (it + 2 < nk) issue(it + 2);
        CP_COMMIT();

        const uint32_t aS = sA + (uint32_t)((it % NST) * GTILEH) * 2;
        const uint32_t bS = sB + (uint32_t)((it % NST) * GTILEH) * 2;
#pragma unroll
        for (int kk = 0; kk < 2; ++kk) {
            uint32_t af[4][4], bf[4][4];
#pragma unroll
            for (int i = 0; i < 4; ++i)
                ldsm4(af[i], aS + aOff[i] + (uint32_t)(((kk * 2 + hiA) ^ aSw[i]) << 4));
#pragma unroll
            for (int p = 0; p < 4; ++p)
                ldsm4(bf[p], bS + bOff[p] + (uint32_t)(((kk * 2 + hiB) ^ bSw[p]) << 4));
#pragma unroll
            for (int i = 0; i < 4; ++i)
#pragma unroll
                for (int j = 0; j < 8; ++j)
                    mma_f16(acc[i][j], af[i], &bf[j >> 1][(j & 1) * 2]);
        }
    }

    if (mode == 0) {
        const int egc = qq * 2;
#pragma unroll
        for (int i = 0; i < 4; ++i) {
#pragma unroll
            for (int j = 0; j < 8; ++j) {
                const size_t base = (size_t)(row0 + wm * 64 + i * 16 + gr) * N +
                                    col0 + wn * 64 + j * 8 + egc;
                *(float2*)(Cf + base) = make_float2(acc[i][j][0], acc[i][j][1]);
                *(float2*)(Cf + base + 8 * (size_t)N) = make_float2(acc[i][j][2], acc[i][j][3]);
            }
        }
        return;
    }

    // ---- fused qkv epilogue: one CTA tile == one head (128 cols) ----
    CP_WAIT0();
    __syncthreads();
    float* red = (float*)smh;             // [128 local rows][2 warp-halves]
    const bool isV = (col0 >= DMODEL + NKV * HD);
    const bool isQ = (col0 < DMODEL);

    if (!isV) {
#pragma unroll
        for (int i = 0; i < 4; ++i) {
            float p0 = 0.f, p1 = 0.f;
#pragma unroll
            for (int j = 0; j < 8; ++j) {
                p0 += acc[i][j][0] * acc[i][j][0] + acc[i][j][1] * acc[i][j][1];
                p1 += acc[i][j][2] * acc[i][j][2] + acc[i][j][3] * acc[i][j][3];
            }
            p0 += __shfl_xor_sync(0xffffffffu, p0, 1);
            p0 += __shfl_xor_sync(0xffffffffu, p0, 2);
            p1 += __shfl_xor_sync(0xffffffffu, p1, 1);
            p1 += __shfl_xor_sync(0xffffffffu, p1, 2);
            if (qq == 0) {
                red[(wm * 64 + i * 16 + gr) * 2 + wn]     = p0;
                red[(wm * 64 + i * 16 + gr + 8) * 2 + wn] = p1;
            }
        }
        __syncthreads();
    }

    const float* nw = isQ ? qw : kw;
    const float qs = isQ ? (0.08838834764831845f * 1.44269504088896341f) : 1.0f;

#pragma unroll
    for (int i = 0; i < 4; ++i) {
        const int lra = wm * 64 + i * 16 + gr;       // local rows
        const int lrb = lra + 8;
        const int ra = row0 + lra, rbg = row0 + lrb; // global tokens
        float rsA = 1.f, rsB = 1.f;
        if (!isV) {
            rsA = rsqrtf((red[lra * 2] + red[lra * 2 + 1]) * (1.f / HD) + 1e-5f);
            rsB = rsqrtf((red[lrb * 2] + red[lrb * 2 + 1]) * (1.f / HD) + 1e-5f);
        }
        const int sa = ra & (SEQ - 1), sb = rbg & (SEQ - 1);
#pragma unroll
        for (int j = 0; j < 8; ++j) {
            const int cb = wn * 64 + j * 8 + 2 * qq;   // head-local col (even)
            if (isV) {
                const int vc = (col0 - DMODEL - NKV * HD) + cb;
                *(__half2*)(g_vh + (size_t)ra  * (NKV * HD) + vc) =
                    __floats2half2_rn(acc[i][j][0], acc[i][j][1]);
                *(__half2*)(g_vh + (size_t)rbg * (NKV * HD) + vc) =
                    __floats2half2_rn(acc[i][j][2], acc[i][j][3]);
            } else {
                const float we = nw[cb], wo_ = nw[cb + 1];
                float2 fa = *(const float2*)(freqs + (size_t)sa * HD + cb);
                float xe = acc[i][j][0] * rsA * we;
                float xo = acc[i][j][1] * rsA * wo_;
                float oe = xe * fa.x - xo * fa.y;
                float oo = xo * fa.x + xe * fa.y;
                __half2 ha = __floats2half2_rn(oe * qs, oo * qs);
                float2 fb = *(const float2*)(freqs + (size_t)sb * HD + cb);
                xe = acc[i][j][2] * rsB * we;
                xo = acc[i][j][3] * rsB * wo_;
                oe = xe * fb.x - xo * fb.y;
                oo = xo * fb.x + xe * fb.y;
                __half2 hb = __floats2half2_rn(oe * qs, oo * qs);
                if (isQ) {
                    *(__half2*)(g_qh + (size_t)ra  * (NH * HD) + col0 + cb) = ha;
                    *(__half2*)(g_qh + (size_t)rbg * (NH * HD) + col0 + cb) = hb;
                } else {
                    const int kc = (col0 - DMODEL) + cb;
                    *(__half2*)(g_kh + (size_t)ra  * (NKV * HD) + kc) = ha;
                    *(__half2*)(g_kh + (size_t)rbg * (NKV * HD) + kc) = hb;
                }
            }
        }
    }
}

// ---------------------------------------------------------------------------
// Flash attention, fp16 mma.sync + ldmatrix. Double-buffered K and V.
// l accumulated via ones-column MMA (extra n-tile); vote-skipped rescale.
// ---------------------------------------------------------------------------
#define QS 136
#define KS 136
#define VS 152
#define PS 72
#define KT (64 * KS)
#define VT (64 * VS)
#define ASMEM ((64 * QS + 2 * KT + 2 * VT + 64 * PS) * 2)   // 100352 B

__global__ __launch_bounds__(128, 2)
void attn_hp()
{
    extern __shared__ __half smh[];
    __half* Qsm = smh;
    __half* Ksm = Qsm + 64 * QS;
    __half* Vsm = Ksm + 2 * KT;
    __half* Psm = Vsm + 2 * VT;
    const uint32_t qB = s2u(Qsm), kB0 = s2u(Ksm), vB0 = s2u(Vsm), pB = s2u(Psm);

    const int qt  = (int)gridDim.x - 1 - (int)blockIdx.x;
    const int h   = blockIdx.y;
    const int b   = blockIdx.z;
    const int kvh = h >> 2;
    const int q0  = qt * 64;
    const int tid = threadIdx.x;
    const int w   = tid >> 5;
    const int lane = tid & 31;
    const int gr  = lane >> 2;
    const int qq  = lane & 3;
    const int r0l = w * 16 + gr;
    const int r1l = r0l + 8;

    const int rowA = lane & 15, rowB = (lane & 7) + 8 * (lane >> 4);
    const int colA = 8 * (lane >> 4), colB = 8 * ((lane >> 3) & 1);
    const uint32_t qAddr = qB + (uint32_t)((w * 16 + rowA) * QS + colA) * 2;
    const uint32_t pAddr = pB + (uint32_t)((w * 16 + rowA) * PS + colA) * 2;
    const uint32_t kOff  = (uint32_t)(rowB * KS + colB) * 2;
    const uint32_t vOff  = (uint32_t)((lane & 15) * VS + 8 * (lane >> 4)) * 2;

    const int sr = tid >> 4, sc = (tid & 15) * 8;
    auto stageK = [&](int kt, int buf) {
        const __half* src = g_kh + (size_t)(b * SEQ + kt * 64 + sr) * (NKV * HD) + kvh * HD + sc;
        uint32_t dst = kB0 + (uint32_t)(buf * KT) * 2 + (uint32_t)(sr * KS + sc) * 2;
#pragma unroll
        for (int it = 0; it < 8; ++it)
            cp16(dst + (uint32_t)(8 * it * KS) * 2, src + (size_t)(8 * it) * (NKV * HD));
    };
    auto stageV = [&](int kt, int buf) {
        const __half* src = g_vh + (size_t)(b * SEQ + kt * 64 + sr) * (NKV * HD) + kvh * HD + sc;
        uint32_t dst = vB0 + (uint32_t)(buf * VT) * 2 + (uint32_t)(sr * VS + sc) * 2;
#pragma unroll
        for (int it = 0; it < 8; ++it)
            cp16(dst + (uint32_t)(8 * it * VS) * 2, src + (size_t)(8 * it) * (NKV * HD));
    };

    // prologue: Q + K0 + V0; init ones-column (col 128) in both V buffers
    {
        const __half* src = g_qh + (size_t)(b * SEQ + q0 + sr) * (NH * HD) + h * HD + sc;
        uint32_t dst = qB + (uint32_t)(sr * QS + sc) * 2;
#pragma unroll
        for (int it = 0; it < 8; ++it)
            cp16(dst + (uint32_t)(8 * it * QS) * 2, src + (size_t)(8 * it) * (NH * HD));
        stageK(0, 0); stageV(0, 0);
        CP_COMMIT();
        for (int idx = tid; idx < 2 * 64 * 16; idx += 128) {
            int bu = idx >> 10, r = (idx >> 4) & 63, c = idx & 15;
            Vsm[bu * VT + r * VS + 128 + c] = (c == 0) ? __float2half(1.f) : __float2half(0.f);
        }
        CP_WAIT0();
        __syncthreads();
    }

    float m0 = -1e30f, m1 = -1e30f;
    float O[17][4];   // 16 hd tiles + 1 l tile
#pragma unroll
    for (int nt = 0; nt < 17; ++nt)
#pragma unroll
        for (int v = 0; v < 4; ++v) O[nt][v] = 0.f;

    for (int kt = 0; kt <= qt; ++kt) {
        const uint32_t kAddr = kB0 + (uint32_t)((kt & 1) * KT) * 2 + kOff;
        const uint32_t vAddr = vB0 + (uint32_t)((kt & 1) * VT) * 2 + vOff;

        // S = Q K^T
        float s[8][4];
#pragma unroll
        for (int nt = 0; nt < 8; ++nt)
#pragma unroll
            for (int v = 0; v < 4; ++v) s[nt][v] = 0.f;
#pragma unroll
        for (int kk = 0; kk < 8; ++kk) {
            uint32_t af[4], bf[4][4];
            ldsm4(af, qAddr + (uint32_t)(kk * 16) * 2);
#pragma unroll
            for (int p = 0; p < 4; ++p)
                ldsm4(bf[p], kAddr + (uint32_t)(p * 16 * KS + kk * 16) * 2);
#pragma unroll
            for (int nt = 0; nt < 8; ++nt)
                mma_f16(s[nt], af, &bf[nt >> 1][(nt & 1) * 2]);
        }

        // softmax
        if (kt == qt) {
#pragma unroll
            for (int nt = 0; nt < 8; ++nt) {
                int cb = nt * 8 + 2 * qq;
                if (cb     > r0l) s[nt][0] = -1e30f;
                if (cb + 1 > r0l) s[nt][1] = -1e30f;
                if (cb     > r1l) s[nt][2] = -1e30f;
                if (cb + 1 > r1l) s[nt][3] = -1e30f;
            }
        }
        float ml0 = -1e30f, ml1 = -1e30f;
#pragma unroll
        for (int nt = 0; nt < 8; ++nt) {
            ml0 = fmaxf(ml0, fmaxf(s[nt][0], s[nt][1]));
            ml1 = fmaxf(ml1, fmaxf(s[nt][2], s[nt][3]));
        }
        ml0 = fmaxf(ml0, __shfl_xor_sync(0xffffffffu, ml0, 1));
        ml0 = fmaxf(ml0, __shfl_xor_sync(0xffffffffu, ml0, 2));
        ml1 = fmaxf(ml1, __shfl_xor_sync(0xffffffffu, ml1, 1));
        ml1 = fmaxf(ml1, __shfl_xor_sync(0xffffffffu, ml1, 2));
        float mn0 = fmaxf(m0, ml0), mn1 = fmaxf(m1, ml1);
        float c0f = exp2f(m0 - mn0), c1f = exp2f(m1 - mn1);
        m0 = mn0; m1 = mn1;
        // P to fp16 + store (warp-private rows; no barrier needed)
#pragma unroll
        for (int nt = 0; nt < 8; ++nt) {
            *(__half2*)(Psm + r0l * PS + nt * 8 + 2 * qq) =
                __floats2half2_rn(exp2f(s[nt][0] - mn0), exp2f(s[nt][1] - mn0));
            *(__half2*)(Psm + r1l * PS + nt * 8 + 2 * qq) =
                __floats2half2_rn(exp2f(s[nt][2] - mn1), exp2f(s[nt][3] - mn1));
        }
        // vote-skipped O rescale (exact skip when corr == 1)
        if (!__all_sync(0xffffffffu, (c0f == 1.f) && (c1f == 1.f))) {
#pragma unroll
            for (int nt = 0; nt < 17; ++nt) {
                O[nt][0] *= c0f; O[nt][1] *= c0f;
                O[nt][2] *= c1f; O[nt][3] *= c1f;
            }
        }
        __syncwarp();

        if (kt < qt) {
            stageK(kt + 1, (kt + 1) & 1);
            stageV(kt + 1, (kt + 1) & 1);
            CP_COMMIT();
        }

        // O += P V  (+ l via ones column)
#pragma unroll
        for (int kk = 0; kk < 4; ++kk) {
            uint32_t af[4], bf[8][4], b8[4];
            ldsm4(af, pAddr + (uint32_t)(kk * 16) * 2);
#pragma unroll
            for (int p = 0; p < 8; ++p)
                ldsm4t(bf[p], vAddr + (uint32_t)(kk * 16 * VS + p * 16) * 2);
            ldsm4t(b8, vAddr + (uint32_t)(kk * 16 * VS + 128) * 2);
#pragma unroll
            for (int nt = 0; nt < 16; ++nt)
                mma_f16(O[nt], af, &bf[nt >> 1][(nt & 1) * 2]);
            mma_f16(O[16], af, &b8[0]);
        }

        if (kt < qt) {
            CP_WAIT0();
            __syncthreads();
        }
    }

    // l lives in O[16][0]/[2] of qq==0 lanes; broadcast within quad
    float l0 = __shfl_sync(0xffffffffu, O[16][0], lane & ~3);
    float l1 = __shfl_sync(0xffffffffu, O[16][2], lane & ~3);
    float inv0 = 1.f / l0, inv1 = 1.f / l1;
    __half* y0 = g_yh + (size_t)(b * SEQ + q0 + r0l) * (NH * HD) + h * HD;
    __half* y1 = g_yh + (size_t)(b * SEQ + q0 + r1l) * (NH * HD) + h * HD;
#pragma unroll
    for (int nt = 0; nt < 16; ++nt) {
        *(__half2*)(y0 + nt * 8 + 2 * qq) = __floats2half2_rn(O[nt][0] * inv0, O[nt][1] * inv0);
        *(__half2*)(y1 + nt * 8 + 2 * qq) = __floats2half2_rn(O[nt][2] * inv1, O[nt][3] * inv1);
    }
}

// ---------------------------------------------------------------------------
extern "C" void kernel_launch(void* const* d_in, const int* in_sizes, int n_in,
                              void* d_out, int out_size)
{
    const float* x    = (const float*)d_in[0];
    const float* fr   = (const float*)d_in[1];
    const float* wqkv = (const float*)d_in[3];
    const float* wo   = (const float*)d_in[4];
    const float* qw   = (const float*)d_in[5];
    const float* kw   = (const float*)d_in[6];
    float* out = (float*)d_out;

    __half *yh_p, *xh_p, *wqkvh_p, *woh_p;
    cudaGetSymbolAddress((void**)&yh_p,    g_yh);
    cudaGetSymbolAddress((void**)&xh_p,    g_xh);
    cudaGetSymbolAddress((void**)&wqkvh_p, g_wqkvh);
    cudaGetSymbolAddress((void**)&woh_p,   g_woh);

    // 0) Convert inputs/weights to fp16 (single launch)
    const size_t ntot = N_X + N_W1 + N_W2;
    to_half_all<<<(unsigned)(ntot / 1024), 256>>>(x, wqkv, wo);

    cudaFuncSetAttribute(gemm_hp, cudaFuncAttributeMaxDynamicSharedMemorySize, GSMEM);
    cudaFuncSetAttribute(attn_hp, cudaFuncAttributeMaxDynamicSharedMemorySize, ASMEM);

    // 1) QKV projection + fused RMSNorm/RoPE/scale epilogue
    gemm_hp<<<dim3(EQKV / 128, TOK / 128), 128, GSMEM>>>(
        xh_p, wqkvh_p, nullptr, TOK, EQKV, DMODEL, 1, fr, qw, kw);

    // 2) Causal GQA flash attention
    attn_hp<<<dim3(SEQ / 64, NH, BATCH), 128, ASMEM>>>();

    // 3) Output projection (fp32 out)
    gemm_hp<<<dim3(DMODEL / 128, TOK / 128), 128, GSMEM>>>(
        yh_p, woh_p, out, TOK, DMODEL, DMODEL, 0, nullptr, nullptr, nullptr);
}

// round 12
// speedup vs baseline: 9.1644x; 1.0270x over previous
#include <cuda_runtime.h>
#include <cuda_fp16.h>
#include <math.h>
#include <stdint.h>

#define BATCH  2
#define SEQ    2048
#define DMODEL 2048
#define NH     16
#define NKV    4
#define HD     128
#define EQKV   3072
#define TOK    (BATCH*SEQ)

// Scratch (device globals; no allocation allowed) — fp16
__device__ __half g_qh   [(size_t)TOK * NH  * HD];   // normed, roped, scaled
__device__ __half g_kh   [(size_t)TOK * NKV * HD];   // normed, roped
__device__ __half g_vh   [(size_t)TOK * NKV * HD];
__device__ __half g_yh   [(size_t)TOK * NH  * HD];
__device__ __half g_xh   [(size_t)TOK * DMODEL];
__device__ __half g_wqkvh[(size_t)EQKV * DMODEL];
__device__ __half g_woh  [(size_t)DMODEL * NH * HD];

__device__ __forceinline__ uint32_t s2u(const void* p) {
    uint32_t a;
    asm("{ .reg .u64 t; cvta.to.shared.u64 t, %1; cvt.u32.u64 %0, t; }"
        : "=r"(a) : "l"(p));
    return a;
}
__device__ __forceinline__ void mma_f16(float* c, const uint32_t* a, const uint32_t* b) {
    asm volatile(
        "mma.sync.aligned.m16n8k16.row.col.f32.f16.f16.f32 "
        "{%0,%1,%2,%3}, {%4,%5,%6,%7}, {%8,%9}, {%0,%1,%2,%3};"
        : "+f"(c[0]), "+f"(c[1]), "+f"(c[2]), "+f"(c[3])
        : "r"(a[0]), "r"(a[1]), "r"(a[2]), "r"(a[3]),
          "r"(b[0]), "r"(b[1]));
}
__device__ __forceinline__ void ldsm4(uint32_t* r, uint32_t a) {
    asm volatile("ldmatrix.sync.aligned.m8n8.x4.shared.b16 {%0,%1,%2,%3}, [%4];"
        : "=r"(r[0]), "=r"(r[1]), "=r"(r[2]), "=r"(r[3]) : "r"(a));
}
__device__ __forceinline__ void ldsm4t(uint32_t* r, uint32_t a) {
    asm volatile("ldmatrix.sync.aligned.m8n8.x4.trans.shared.b16 {%0,%1,%2,%3}, [%4];"
        : "=r"(r[0]), "=r"(r[1]), "=r"(r[2]), "=r"(r[3]) : "r"(a));
}
__device__ __forceinline__ void cp16(uint32_t smem_dst, const void* gptr) {
    asm volatile("cp.async.cg.shared.global [%0], [%1], 16;"
                 :: "r"(smem_dst), "l"(gptr) : "memory");
}
#define CP_COMMIT() asm volatile("cp.async.commit_group;" ::: "memory")
#define CP_WAIT0()  asm volatile("cp.async.wait_group 0;" ::: "memory")
#define CP_WAIT1()  asm volatile("cp.async.wait_group 1;" ::: "memory")

// ---------------------------------------------------------------------------
// Merged fp32 -> fp16 conversion of x, wqkv, wo in one launch.
// ---------------------------------------------------------------------------
#define N_X  ((size_t)TOK * DMODEL)
#define N_W1 ((size_t)EQKV * DMODEL)
#define N_W2 ((size_t)DMODEL * NH * HD)

__global__ __launch_bounds__(256)
void to_half_all(const float* __restrict__ x, const float* __restrict__ wqkv,
                 const float* __restrict__ wo)
{
    size_t i = ((size_t)blockIdx.x * 256 + threadIdx.x) * 4;
    const float* s; __half* d; size_t off;
    if (i < N_X)            { s = x;    d = g_xh;    off = i; }
    else if (i < N_X + N_W1){ s = wqkv; d = g_wqkvh; off = i - N_X; }
    else                    { s = wo;   d = g_woh;   off = i - N_X - N_W1; }
    float4 v = *(const float4*)(s + off);
    __half2* dp = (__half2*)(d + off);
    dp[0] = __floats2half2_rn(v.x, v.y);
    dp[1] = __floats2half2_rn(v.z, v.w);
}

// ---------------------------------------------------------------------------
// fp16 mma.sync GEMM (NT): BK=32, 3-stage cp.async, XOR-swizzled smem.
// mode 1: fused qkv epilogue (RMSNorm + RoPE + scale per head-tile).
// ---------------------------------------------------------------------------
#define GTILEH (128 * 32)
#define NST 3
#define GSMEM (NST * 2 * GTILEH * 2)      // 49152 B

__global__ __launch_bounds__(128)
void gemm_hp(const __half* __restrict__ A, const __half* __restrict__ Bm,
             float* __restrict__ Cf, int M, int N, int K, int mode,
             const float* __restrict__ freqs,
             const float* __restrict__ qw, const float* __restrict__ kw)
{
    extern __shared__ __half smh[];
    __half* As = smh;
    __half* Bs = smh + NST * GTILEH;

    const int tid  = threadIdx.x;
    const int lane = tid & 31;
    const int wid  = tid >> 5;
    const int wm   = wid & 1;
    const int wn   = wid >> 1;
    const int gr   = lane >> 2;
    const int qq   = lane & 3;
    const int row0 = blockIdx.y * 128;
    const int col0 = blockIdx.x * 128;

    const int kq = tid & 3, rb = tid >> 2;
    const __half* Ag = A  + (size_t)(row0 + rb) * K + kq * 8;
    const __half* Bg = Bm + (size_t)(col0 + rb) * K + kq * 8;
    const uint32_t sA = s2u(As), sB = s2u(Bs);
    const uint32_t d0 = (uint32_t)(rb * 32 + ((kq ^ ((rb >> 1) & 3)) << 3)) * 2;

    const int rowA = lane & 15, hiA = lane >> 4;
    const int rowB = (lane & 7) + 8 * (lane >> 4), hiB = (lane >> 3) & 1;
    uint32_t aOff[4], bOff[4];
    int aSw[4], bSw[4];
#pragma unroll
    for (int i = 0; i < 4; ++i) {
        int r = wm * 64 + i * 16 + rowA;
        aOff[i] = (uint32_t)r * 64; aSw[i] = (r >> 1) & 3;
    }
#pragma unroll
    for (int p = 0; p < 4; ++p) {
        int r = wn * 64 + p * 16 + rowB;
        bOff[p] = (uint32_t)r * 64; bSw[p] = (r >> 1) & 3;
    }

    float acc[4][8][4];
#pragma unroll
    for (int i = 0; i < 4; ++i)
#pragma unroll
        for (int j = 0; j < 8; ++j)
#pragma unroll
            for (int v = 0; v < 4; ++v) acc[i][j][v] = 0.f;

    const int nk = K >> 5;

    auto issue = [&](int st) {
        const uint32_t ab = sA + (uint32_t)((st % NST) * GTILEH) * 2 + d0;
        const uint32_t bb = sB + (uint32_t)((st % NST) * GTILEH) * 2 + d0;
        const int kc = st << 5;
#pragma unroll
        for (int j = 0; j < 4; ++j) {
            cp16(ab + j * 2048, Ag + (size_t)(32 * j) * K + kc);
            cp16(bb + j * 2048, Bg + (size_t)(32 * j) * K + kc);
        }
    };

    issue(0); CP_COMMIT();
    issue(1); CP_COMMIT();

    for (int it = 0; it < nk; ++it) {
        CP_WAIT1();
        __syncthreads();
        if (it + 2 < nk) issue(it + 2);
        CP_COMMIT();

        const uint32_t aS = sA + (uint32_t)((it % NST) * GTILEH) * 2;
        const uint32_t bS = sB + (uint32_t)((it % NST) * GTILEH) * 2;
#pragma unroll
        for (int kk = 0; kk < 2; ++kk) {
            uint32_t af[4][4], bf[4][4];
#pragma unroll
            for (int i = 0; i < 4; ++i)
                ldsm4(af[i], aS + aOff[i] + (uint32_t)(((kk * 2 + hiA) ^ aSw[i]) << 4));
#pragma unroll
            for (int p = 0; p < 4; ++p)
                ldsm4(bf[p], bS + bOff[p] + (uint32_t)(((kk * 2 + hiB) ^ bSw[p]) << 4));
#pragma unroll
            for (int i = 0; i < 4; ++i)
#pragma unroll
                for (int j = 0; j < 8; ++j)
                    mma_f16(acc[i][j], af[i], &bf[j >> 1][(j & 1) * 2]);
        }
    }

    if (mode == 0) {
        const int egc = qq * 2;
#pragma unroll
        for (int i = 0; i < 4; ++i) {
#pragma unroll
            for (int j = 0; j < 8; ++j) {
                const size_t base = (size_t)(row0 + wm * 64 + i * 16 + gr) * N +
                                    col0 + wn * 64 + j * 8 + egc;
                *(float2*)(Cf + base) = make_float2(acc[i][j][0], acc[i][j][1]);
                *(float2*)(Cf + base + 8 * (size_t)N) = make_float2(acc[i][j][2], acc[i][j][3]);
            }
        }
        return;
    }

    // ---- fused qkv epilogue ----
    CP_WAIT0();
    __syncthreads();
    float* red = (float*)smh;
    const bool isV = (col0 >= DMODEL + NKV * HD);
    const bool isQ = (col0 < DMODEL);

    if (!isV) {
#pragma unroll
        for (int i = 0; i < 4; ++i) {
            float p0 = 0.f, p1 = 0.f;
#pragma unroll
            for (int j = 0; j < 8; ++j) {
                p0 += acc[i][j][0] * acc[i][j][0] + acc[i][j][1] * acc[i][j][1];
                p1 += acc[i][j][2] * acc[i][j][2] + acc[i][j][3] * acc[i][j][3];
            }
            p0 += __shfl_xor_sync(0xffffffffu, p0, 1);
            p0 += __shfl_xor_sync(0xffffffffu, p0, 2);
            p1 += __shfl_xor_sync(0xffffffffu, p1, 1);
            p1 += __shfl_xor_sync(0xffffffffu, p1, 2);
            if (qq == 0) {
                red[(wm * 64 + i * 16 + gr) * 2 + wn]     = p0;
                red[(wm * 64 + i * 16 + gr + 8) * 2 + wn] = p1;
            }
        }
        __syncthreads();
    }

    const float* nw = isQ ? qw : kw;
    const float qs = isQ ? (0.08838834764831845f * 1.44269504088896341f) : 1.0f;

#pragma unroll
    for (int i = 0; i < 4; ++i) {
        const int lra = wm * 64 + i * 16 + gr;
        const int lrb = lra + 8;
        const int ra = row0 + lra, rbg = row0 + lrb;
        float rsA = 1.f, rsB = 1.f;
        if (!isV) {
            rsA = rsqrtf((red[lra * 2] + red[lra * 2 + 1]) * (1.f / HD) + 1e-5f);
            rsB = rsqrtf((red[lrb * 2] + red[lrb * 2 + 1]) * (1.f / HD) + 1e-5f);
        }
        const int sa = ra & (SEQ - 1), sb = rbg & (SEQ - 1);
#pragma unroll
        for (int j = 0; j < 8; ++j) {
            const int cb = wn * 64 + j * 8 + 2 * qq;
            if (isV) {
                const int vc = (col0 - DMODEL - NKV * HD) + cb;
                *(__half2*)(g_vh + (size_t)ra  * (NKV * HD) + vc) =
                    __floats2half2_rn(acc[i][j][0], acc[i][j][1]);
                *(__half2*)(g_vh + (size_t)rbg * (NKV * HD) + vc) =
                    __floats2half2_rn(acc[i][j][2], acc[i][j][3]);
            } else {
                const float we = nw[cb], wo_ = nw[cb + 1];
                float2 fa = *(const float2*)(freqs + (size_t)sa * HD + cb);
                float xe = acc[i][j][0] * rsA * we;
                float xo = acc[i][j][1] * rsA * wo_;
                float oe = xe * fa.x - xo * fa.y;
                float oo = xo * fa.x + xe * fa.y;
                __half2 ha = __floats2half2_rn(oe * qs, oo * qs);
                float2 fb = *(const float2*)(freqs + (size_t)sb * HD + cb);
                xe = acc[i][j][2] * rsB * we;
                xo = acc[i][j][3] * rsB * wo_;
                oe = xe * fb.x - xo * fb.y;
                oo = xo * fb.x + xe * fb.y;
                __half2 hb = __floats2half2_rn(oe * qs, oo * qs);
                if (isQ) {
                    *(__half2*)(g_qh + (size_t)ra  * (NH * HD) + col0 + cb) = ha;
                    *(__half2*)(g_qh + (size_t)rbg * (NH * HD) + col0 + cb) = hb;
                } else {
                    const int kc = (col0 - DMODEL) + cb;
                    *(__half2*)(g_kh + (size_t)ra  * (NKV * HD) + kc) = ha;
                    *(__half2*)(g_kh + (size_t)rbg * (NKV * HD) + kc) = hb;
                }
            }
        }
    }
}

// ---------------------------------------------------------------------------
// Flash attention, fp16 mma.sync + ldmatrix. Double-buffered K and V.
// FIXED-BASE softmax: p = exp2(s - 6); no running max, no rescale.
// (|s| <= sqrt(HD)*log2e = 16.3 with RMS-normed q,k -> exp2(s-6) <= 1260,
//  never overflows fp16; base cancels exactly in O/l.)
// l accumulated via ones-column MMA.
// ---------------------------------------------------------------------------
#define SM_BIAS 6.0f
#define QS 136
#define KS 136
#define VS 152
#define PS 72
#define KT (64 * KS)
#define VT (64 * VS)
#define ASMEM ((64 * QS + 2 * KT + 2 * VT + 64 * PS) * 2)   // 100352 B

__global__ __launch_bounds__(128, 2)
void attn_hp()
{
    extern __shared__ __half smh[];
    __half* Qsm = smh;
    __half* Ksm = Qsm + 64 * QS;
    __half* Vsm = Ksm + 2 * KT;
    __half* Psm = Vsm + 2 * VT;
    const uint32_t qB = s2u(Qsm), kB0 = s2u(Ksm), vB0 = s2u(Vsm), pB = s2u(Psm);

    const int qt  = (int)gridDim.x - 1 - (int)blockIdx.x;
    const int h   = blockIdx.y;
    const int b   = blockIdx.z;
    const int kvh = h >> 2;
    const int q0  = qt * 64;
    const int tid = threadIdx.x;
    const int w   = tid >> 5;
    const int lane = tid & 31;
    const int gr  = lane >> 2;
    const int qq  = lane & 3;
    const int r0l = w * 16 + gr;
    const int r1l = r0l + 8;

    const int rowA = lane & 15;
    const int rowB = (lane & 7) + 8 * (lane >> 4);
    const int colA = 8 * (lane >> 4), colB = 8 * ((lane >> 3) & 1);
    const uint32_t qAddr = qB + (uint32_t)((w * 16 + rowA) * QS + colA) * 2;
    const uint32_t pAddr = pB + (uint32_t)((w * 16 + rowA) * PS + colA) * 2;
    const uint32_t kOff  = (uint32_t)(rowB * KS + colB) * 2;
    const uint32_t vOff  = (uint32_t)((lane & 15) * VS + 8 * (lane >> 4)) * 2;

    const int sr = tid >> 4, sc = (tid & 15) * 8;
    auto stageK = [&](int kt, int buf) {
        const __half* src = g_kh + (size_t)(b * SEQ + kt * 64 + sr) * (NKV * HD) + kvh * HD + sc;
        uint32_t dst = kB0 + (uint32_t)(buf * KT) * 2 + (uint32_t)(sr * KS + sc) * 2;
#pragma unroll
        for (int it = 0; it < 8; ++it)
            cp16(dst + (uint32_t)(8 * it * KS) * 2, src + (size_t)(8 * it) * (NKV * HD));
    };
    auto stageV = [&](int kt, int buf) {
        const __half* src = g_vh + (size_t)(b * SEQ + kt * 64 + sr) * (NKV * HD) + kvh * HD + sc;
        uint32_t dst = vB0 + (uint32_t)(buf * VT) * 2 + (uint32_t)(sr * VS + sc) * 2;
#pragma unroll
        for (int it = 0; it < 8; ++it)
            cp16(dst + (uint32_t)(8 * it * VS) * 2, src + (size_t)(8 * it) * (NKV * HD));
    };

    // prologue: Q + K0 + V0; ones-column init in both V buffers
    {
        const __half* src = g_qh + (size_t)(b * SEQ + q0 + sr) * (NH * HD) + h * HD + sc;
        uint32_t dst = qB + (uint32_t)(sr * QS + sc) * 2;
#pragma unroll
        for (int it = 0; it < 8; ++it)
            cp16(dst + (uint32_t)(8 * it * QS) * 2, src + (size_t)(8 * it) * (NH * HD));
        stageK(0, 0); stageV(0, 0);
        CP_COMMIT();
        for (int idx = tid; idx < 2 * 64 * 16; idx += 128) {
            int bu = idx >> 10, r = (idx >> 4) & 63, c = idx & 15;
            Vsm[bu * VT + r * VS + 128 + c] = (c == 0) ? __float2half(1.f) : __float2half(0.f);
        }
        CP_WAIT0();
        __syncthreads();
    }

    float O[17][4];   // 16 hd tiles + 1 l tile
#pragma unroll
    for (int nt = 0; nt < 17; ++nt)
#pragma unroll
        for (int v = 0; v < 4; ++v) O[nt][v] = 0.f;

    for (int kt = 0; kt <= qt; ++kt) {
        const uint32_t kAddr = kB0 + (uint32_t)((kt & 1) * KT) * 2 + kOff;
        const uint32_t vAddr = vB0 + (uint32_t)((kt & 1) * VT) * 2 + vOff;

        // S = Q K^T
        float s[8][4];
#pragma unroll
        for (int nt = 0; nt < 8; ++nt)
#pragma unroll
            for (int v = 0; v < 4; ++v) s[nt][v] = 0.f;
#pragma unroll
        for (int kk = 0; kk < 8; ++kk) {
            uint32_t af[4], bf[4][4];
            ldsm4(af, qAddr + (uint32_t)(kk * 16) * 2);
#pragma unroll
            for (int p = 0; p < 4; ++p)
                ldsm4(bf[p], kAddr + (uint32_t)(p * 16 * KS + kk * 16) * 2);
#pragma unroll
            for (int nt = 0; nt < 8; ++nt)
                mma_f16(s[nt], af, &bf[nt >> 1][(nt & 1) * 2]);
        }

        // fixed-base softmax: p = exp2(s - BIAS); mask via -inf -> 0
        if (kt == qt) {
#pragma unroll
            for (int nt = 0; nt < 8; ++nt) {
                int cb = nt * 8 + 2 * qq;
                if (cb     > r0l) s[nt][0] = -1e30f;
                if (cb + 1 > r0l) s[nt][1] = -1e30f;
                if (cb     > r1l) s[nt][2] = -1e30f;
                if (cb + 1 > r1l) s[nt][3] = -1e30f;
            }
        }
#pragma unroll
        for (int nt = 0; nt < 8; ++nt) {
            *(__half2*)(Psm + r0l * PS + nt * 8 + 2 * qq) =
                __floats2half2_rn(exp2f(s[nt][0] - SM_BIAS), exp2f(s[nt][1] - SM_BIAS));
            *(__half2*)(Psm + r1l * PS + nt * 8 + 2 * qq) =
                __floats2half2_rn(exp2f(s[nt][2] - SM_BIAS), exp2f(s[nt][3] - SM_BIAS));
        }
        __syncwarp();

        if (kt < qt) {
            stageK(kt + 1, (kt + 1) & 1);
            stageV(kt + 1, (kt + 1) & 1);
            CP_COMMIT();
        }

        // O += P V  (+ l via ones column)
#pragma unroll
        for (int kk = 0; kk < 4; ++kk) {
            uint32_t af[4], bf[8][4], b8[4];
            ldsm4(af, pAddr + (uint32_t)(kk * 16) * 2);
#pragma unroll
            for (int p = 0; p < 8; ++p)
                ldsm4t(bf[p], vAddr + (uint32_t)(kk * 16 * VS + p * 16) * 2);
            ldsm4t(b8, vAddr + (uint32_t)(kk * 16 * VS + 128) * 2);
#pragma unroll
            for (int nt = 0; nt < 16; ++nt)
                mma_f16(O[nt], af, &bf[nt >> 1][(nt & 1) * 2]);
            mma_f16(O[16], af, &b8[0]);
        }

        if (kt < qt) {
            CP_WAIT0();
            __syncthreads();
        }
    }

    float l0 = __shfl_sync(0xffffffffu, O[16][0], lane & ~3);
    float l1 = __shfl_sync(0xffffffffu, O[16][2], lane & ~3);
    float inv0 = 1.f / l0, inv1 = 1.f / l1;
    __half* y0 = g_yh + (size_t)(b * SEQ + q0 + r0l) * (NH * HD) + h * HD;
    __half* y1 = g_yh + (size_t)(b * SEQ + q0 + r1l) * (NH * HD) + h * HD;
#pragma unroll
    for (int nt = 0; nt < 16; ++nt) {
        *(__half2*)(y0 + nt * 8 + 2 * qq) = __floats2half2_rn(O[nt][0] * inv0, O[nt][1] * inv0);
        *(__half2*)(y1 + nt * 8 + 2 * qq) = __floats2half2_rn(O[nt][2] * inv1, O[nt][3] * inv1);
    }
}

// ---------------------------------------------------------------------------
extern "C" void kernel_launch(void* const* d_in, const int* in_sizes, int n_in,
                              void* d_out, int out_size)
{
    const float* x    = (const float*)d_in[0];
    const float* fr   = (const float*)d_in[1];
    const float* wqkv = (const float*)d_in[3];
    const float* wo   = (const float*)d_in[4];
    const float* qw   = (const float*)d_in[5];
    const float* kw   = (const float*)d_in[6];
    float* out = (float*)d_out;

    __half *yh_p, *xh_p, *wqkvh_p, *woh_p;
    cudaGetSymbolAddress((void**)&yh_p,    g_yh);
    cudaGetSymbolAddress((void**)&xh_p,    g_xh);
    cudaGetSymbolAddress((void**)&wqkvh_p, g_wqkvh);
    cudaGetSymbolAddress((void**)&woh_p,   g_woh);

    // 0) Convert inputs/weights to fp16 (single launch)
    const size_t ntot = N_X + N_W1 + N_W2;
    to_half_all<<<(unsigned)(ntot / 1024), 256>>>(x, wqkv, wo);

    cudaFuncSetAttribute(gemm_hp, cudaFuncAttributeMaxDynamicSharedMemorySize, GSMEM);
    cudaFuncSetAttribute(attn_hp, cudaFuncAttributeMaxDynamicSharedMemorySize, ASMEM);

    // 1) QKV projection + fused RMSNorm/RoPE/scale epilogue
    gemm_hp<<<dim3(EQKV / 128, TOK / 128), 128, GSMEM>>>(
        xh_p, wqkvh_p, nullptr, TOK, EQKV, DMODEL, 1, fr, qw, kw);

    // 2) Causal GQA flash attention (fixed-base softmax)
    attn_hp<<<dim3(SEQ / 64, NH, BATCH), 128, ASMEM>>>();

    // 3) Output projection (fp32 out)
    gemm_hp<<<dim3(DMODEL / 128, TOK / 128), 128, GSMEM>>>(
        yh_p, woh_p, out, TOK, DMODEL, DMODEL, 0, nullptr, nullptr, nullptr);
}

// round 13
// speedup vs baseline: 9.8851x; 1.0786x over previous
#include <cuda_runtime.h>
#include <cuda_fp16.h>
#include <math.h>
#include <stdint.h>

#define BATCH  2
#define SEQ    2048
#define DMODEL 2048
#define NH     16
#define NKV    4
#define HD     128
#define EQKV   3072
#define TOK    (BATCH*SEQ)

// Scratch (device globals; no allocation allowed) — fp16
__device__ __half g_qh   [(size_t)TOK * NH  * HD];   // normed, roped, scaled
__device__ __half g_kh   [(size_t)TOK * NKV * HD];   // normed, roped
__device__ __half g_vh   [(size_t)TOK * NKV * HD];
__device__ __half g_yh   [(size_t)TOK * NH  * HD];
__device__ __half g_xh   [(size_t)TOK * DMODEL];
__device__ __half g_wqkvh[(size_t)EQKV * DMODEL];
__device__ __half g_woh  [(size_t)DMODEL * NH * HD];

__device__ __forceinline__ uint32_t s2u(const void* p) {
    uint32_t a;
    asm("{ .reg .u64 t; cvta.to.shared.u64 t, %1; cvt.u32.u64 %0, t; }"
        : "=r"(a) : "l"(p));
    return a;
}
__device__ __forceinline__ void mma_f16(float* c, const uint32_t* a, const uint32_t* b) {
    asm volatile(
        "mma.sync.aligned.m16n8k16.row.col.f32.f16.f16.f32 "
        "{%0,%1,%2,%3}, {%4,%5,%6,%7}, {%8,%9}, {%0,%1,%2,%3};"
        : "+f"(c[0]), "+f"(c[1]), "+f"(c[2]), "+f"(c[3])
        : "r"(a[0]), "r"(a[1]), "r"(a[2]), "r"(a[3]),
          "r"(b[0]), "r"(b[1]));
}
__device__ __forceinline__ void ldsm4(uint32_t* r, uint32_t a) {
    asm volatile("ldmatrix.sync.aligned.m8n8.x4.shared.b16 {%0,%1,%2,%3}, [%4];"
        : "=r"(r[0]), "=r"(r[1]), "=r"(r[2]), "=r"(r[3]) : "r"(a));
}
__device__ __forceinline__ void ldsm4t(uint32_t* r, uint32_t a) {
    asm volatile("ldmatrix.sync.aligned.m8n8.x4.trans.shared.b16 {%0,%1,%2,%3}, [%4];"
        : "=r"(r[0]), "=r"(r[1]), "=r"(r[2]), "=r"(r[3]) : "r"(a));
}
__device__ __forceinline__ void cp16(uint32_t smem_dst, const void* gptr) {
    asm volatile("cp.async.cg.shared.global [%0], [%1], 16;"
                 :: "r"(smem_dst), "l"(gptr) : "memory");
}
#define CP_COMMIT() asm volatile("cp.async.commit_group;" ::: "memory")
#define CP_WAIT0()  asm volatile("cp.async.wait_group 0;" ::: "memory")
#define CP_WAIT1()  asm volatile("cp.async.wait_group 1;" ::: "memory")
__device__ __forceinline__ uint32_t h2u(__half2 h) {
    return *reinterpret_cast<uint32_t*>(&h);
}

// ---------------------------------------------------------------------------
// Merged fp32 -> fp16 conversion of x, wqkv, wo in one launch.
// ---------------------------------------------------------------------------
#define N_X  ((size_t)TOK * DMODEL)
#define N_W1 ((size_t)EQKV * DMODEL)
#define N_W2 ((size_t)DMODEL * NH * HD)

__global__ __launch_bounds__(256)
void to_half_all(const float* __restrict__ x, const float* __restrict__ wqkv,
                 const float* __restrict__ wo)
{
    size_t i = ((size_t)blockIdx.x * 256 + threadIdx.x) * 4;
    const float* s; __half* d; size_t off;
    if (i < N_X)            { s = x;    d = g_xh;    off = i; }
    else if (i < N_X + N_W1){ s = wqkv; d = g_wqkvh; off = i - N_X; }
    else                    { s = wo;   d = g_woh;   off = i - N_X - N_W1; }
    float4 v = *(const float4*)(s + off);
    __half2* dp = (__half2*)(d + off);
    dp[0] = __floats2half2_rn(v.x, v.y);
    dp[1] = __floats2half2_rn(v.z, v.w);
}

// ---------------------------------------------------------------------------
// fp16 mma.sync GEMM (NT): BK=32, 4-stage cp.async, XOR-swizzled smem.
// mode 1: fused qkv epilogue (RMSNorm + RoPE + scale per head-tile).
// ---------------------------------------------------------------------------
#define GTILEH (128 * 32)
#define NST 4
#define GSMEM (NST * 2 * GTILEH * 2)      // 65536 B

__global__ __launch_bounds__(128)
void gemm_hp(const __half* __restrict__ A, const __half* __restrict__ Bm,
             float* __restrict__ Cf, int M, int N, int K, int mode,
             const float* __restrict__ freqs,
             const float* __restrict__ qw, const float* __restrict__ kw)
{
    extern __shared__ __half smh[];
    __half* As = smh;
    __half* Bs = smh + NST * GTILEH;

    const int tid  = threadIdx.x;
    const int lane = tid & 31;
    const int wid  = tid >> 5;
    const int wm   = wid & 1;
    const int wn   = wid >> 1;
    const int gr   = lane >> 2;
    const int qq   = lane & 3;
    const int row0 = blockIdx.y * 128;
    const int col0 = blockIdx.x * 128;

    const int kq = tid & 3, rb = tid >> 2;
    const __half* Ag = A  + (size_t)(row0 + rb) * K + kq * 8;
    const __half* Bg = Bm + (size_t)(col0 + rb) * K + kq * 8;
    const uint32_t sA = s2u(As), sB = s2u(Bs);
    const uint32_t d0 = (uint32_t)(rb * 32 + ((kq ^ ((rb >> 1) & 3)) << 3)) * 2;

    const int rowA = lane & 15, hiA = lane >> 4;
    const int rowB = (lane & 7) + 8 * (lane >> 4), hiB = (lane >> 3) & 1;
    uint32_t aOff[4], bOff[4];
    int aSw[4], bSw[4];
#pragma unroll
    for (int i = 0; i < 4; ++i) {
        int r = wm * 64 + i * 16 + rowA;
        aOff[i] = (uint32_t)r * 64; aSw[i] = (r >> 1) & 3;
    }
#pragma unroll
    for (int p = 0; p < 4; ++p) {
        int r = wn * 64 + p * 16 + rowB;
        bOff[p] = (uint32_t)r * 64; bSw[p] = (r >> 1) & 3;
    }

    float acc[4][8][4];
#pragma unroll
    for (int i = 0; i < 4; ++i)
#pragma unroll
        for (int j = 0; j < 8; ++j)
#pragma unroll
            for (int v = 0; v < 4; ++v) acc[i][j][v] = 0.f;

    const int nk = K >> 5;

    auto issue = [&](int st) {
        const uint32_t ab = sA + (uint32_t)((st % NST) * GTILEH) * 2 + d0;
        const uint32_t bb = sB + (uint32_t)((st % NST) * GTILEH) * 2 + d0;
        const int kc = st << 5;
#pragma unroll
        for (int j = 0; j < 4; ++j) {
            cp16(ab + j * 2048, Ag + (size_t)(32 * j) * K + kc);
            cp16(bb + j * 2048, Bg + (size_t)(32 * j) * K + kc);
        }
    };

    issue(0); CP_COMMIT();
    issue(1); CP_COMMIT();
    issue(2); CP_COMMIT();

    for (int it = 0; it < nk; ++it) {
        CP_WAIT1();
        __syncthreads();
        if (it + 3 < nk) issue(it + 3);
        CP_COMMIT();

        const uint32_t aS = sA + (uint32_t)((it % NST) * GTILEH) * 2;
        const uint32_t bS = sB + (uint32_t)((it % NST) * GTILEH) * 2;
#pragma unroll
        for (int kk = 0; kk < 2; ++kk) {
            uint32_t af[4][4], bf[4][4];
#pragma unroll
            for (int i = 0; i < 4; ++i)
                ldsm4(af[i], aS + aOff[i] + (uint32_t)(((kk * 2 + hiA) ^ aSw[i]) << 4));
#pragma unroll
            for (int p = 0; p < 4; ++p)
                ldsm4(bf[p], bS + bOff[p] + (uint32_t)(((kk * 2 + hiB) ^ bSw[p]) << 4));
#pragma unroll
            for (int i = 0; i < 4; ++i)
#pragma unroll
                for (int j = 0; j < 8; ++j)
                    mma_f16(acc[i][j], af[i], &bf[j >> 1][(j & 1) * 2]);
        }
    }

    if (mode == 0) {
        const int egc = qq * 2;
#pragma unroll
        for (int i = 0; i < 4; ++i) {
#pragma unroll
            for (int j = 0; j < 8; ++j) {
                const size_t base = (size_t)(row0 + wm * 64 + i * 16 + gr) * N +
                                    col0 + wn * 64 + j * 8 + egc;
                *(float2*)(Cf + base) = make_float2(acc[i][j][0], acc[i][j][1]);
                *(float2*)(Cf + base + 8 * (size_t)N) = make_float2(acc[i][j][2], acc[i][j][3]);
            }
        }
        return;
    }

    // ---- fused qkv epilogue ----
    CP_WAIT0();
    __syncthreads();
    float* red = (float*)smh;
    const bool isV = (col0 >= DMODEL + NKV * HD);
    const bool isQ = (col0 < DMODEL);

    if (!isV) {
#pragma unroll
        for (int i = 0; i < 4; ++i) {
            float p0 = 0.f, p1 = 0.f;
#pragma unroll
            for (int j = 0; j < 8; ++j) {
                p0 += acc[i][j][0] * acc[i][j][0] + acc[i][j][1] * acc[i][j][1];
                p1 += acc[i][j][2] * acc[i][j][2] + acc[i][j][3] * acc[i][j][3];
            }
            p0 += __shfl_xor_sync(0xffffffffu, p0, 1);
            p0 += __shfl_xor_sync(0xffffffffu, p0, 2);
            p1 += __shfl_xor_sync(0xffffffffu, p1, 1);
            p1 += __shfl_xor_sync(0xffffffffu, p1, 2);
            if (qq == 0) {
                red[(wm * 64 + i * 16 + gr) * 2 + wn]     = p0;
                red[(wm * 64 + i * 16 + gr + 8) * 2 + wn] = p1;
            }
        }
        __syncthreads();
    }

    const float* nw = isQ ? qw : kw;
    const float qs = isQ ? (0.08838834764831845f * 1.44269504088896341f) : 1.0f;

#pragma unroll
    for (int i = 0; i < 4; ++i) {
        const int lra = wm * 64 + i * 16 + gr;
        const int lrb = lra + 8;
        const int ra = row0 + lra, rbg = row0 + lrb;
        float rsA = 1.f, rsB = 1.f;
        if (!isV) {
            rsA = rsqrtf((red[lra * 2] + red[lra * 2 + 1]) * (1.f / HD) + 1e-5f);
            rsB = rsqrtf((red[lrb * 2] + red[lrb * 2 + 1]) * (1.f / HD) + 1e-5f);
        }
        const int sa = ra & (SEQ - 1), sb = rbg & (SEQ - 1);
#pragma unroll
        for (int j = 0; j < 8; ++j) {
            const int cb = wn * 64 + j * 8 + 2 * qq;
            if (isV) {
                const int vc = (col0 - DMODEL - NKV * HD) + cb;
                *(__half2*)(g_vh + (size_t)ra  * (NKV * HD) + vc) =
                    __floats2half2_rn(acc[i][j][0], acc[i][j][1]);
                *(__half2*)(g_vh + (size_t)rbg * (NKV * HD) + vc) =
                    __floats2half2_rn(acc[i][j][2], acc[i][j][3]);
            } else {
                const float we = nw[cb], wo_ = nw[cb + 1];
                float2 fa = *(const float2*)(freqs + (size_t)sa * HD + cb);
                float xe = acc[i][j][0] * rsA * we;
                float xo = acc[i][j][1] * rsA * wo_;
                float oe = xe * fa.x - xo * fa.y;
                float oo = xo * fa.x + xe * fa.y;
                __half2 ha = __floats2half2_rn(oe * qs, oo * qs);
                float2 fb = *(const float2*)(freqs + (size_t)sb * HD + cb);
                xe = acc[i][j][2] * rsB * we;
                xo = acc[i][j][3] * rsB * wo_;
                oe = xe * fb.x - xo * fb.y;
                oo = xo * fb.x + xe * fb.y;
                __half2 hb = __floats2half2_rn(oe * qs, oo * qs);
                if (isQ) {
                    *(__half2*)(g_qh + (size_t)ra  * (NH * HD) + col0 + cb) = ha;
                    *(__half2*)(g_qh + (size_t)rbg * (NH * HD) + col0 + cb) = hb;
                } else {
                    const int kc = (col0 - DMODEL) + cb;
                    *(__half2*)(g_kh + (size_t)ra  * (NKV * HD) + kc) = ha;
                    *(__half2*)(g_kh + (size_t)rbg * (NKV * HD) + kc) = hb;
                }
            }
        }
    }
}

// ---------------------------------------------------------------------------
// Flash attention, fp16 mma.sync + ldmatrix. Double-buffered K/V.
// Fixed-base softmax (p = exp2(s-6)); P stays in registers (S-accumulator
// layout == PV A-operand layout for m16n8k16); Q fragments hoisted out of
// the kt loop; l via ones-column MMA.
// ---------------------------------------------------------------------------
#define SM_BIAS 6.0f
#define QS 136
#define KS 136
#define VS 152
#define KT (64 * KS)
#define VT (64 * VS)
#define ASMEM ((64 * QS + 2 * KT + 2 * VT) * 2)   // 91136 B

__global__ __launch_bounds__(128, 2)
void attn_hp()
{
    extern __shared__ __half smh[];
    __half* Qsm = smh;
    __half* Ksm = Qsm + 64 * QS;
    __half* Vsm = Ksm + 2 * KT;
    const uint32_t qB = s2u(Qsm), kB0 = s2u(Ksm), vB0 = s2u(Vsm);

    const int qt  = (int)gridDim.x - 1 - (int)blockIdx.x;
    const int h   = blockIdx.y;
    const int b   = blockIdx.z;
    const int kvh = h >> 2;
    const int q0  = qt * 64;
    const int tid = threadIdx.x;
    const int w   = tid >> 5;
    const int lane = tid & 31;
    const int gr  = lane >> 2;
    const int qq  = lane & 3;
    const int r0l = w * 16 + gr;
    const int r1l = r0l + 8;

    const int rowA = lane & 15;
    const int rowB = (lane & 7) + 8 * (lane >> 4);
    const int colA = 8 * (lane >> 4), colB = 8 * ((lane >> 3) & 1);
    const uint32_t qAddr = qB + (uint32_t)((w * 16 + rowA) * QS + colA) * 2;
    const uint32_t kOff  = (uint32_t)(rowB * KS + colB) * 2;
    const uint32_t vOff  = (uint32_t)((lane & 15) * VS + 8 * (lane >> 4)) * 2;

    const int sr = tid >> 4, sc = (tid & 15) * 8;
    auto stageK = [&](int kt, int buf) {
        const __half* src = g_kh + (size_t)(b * SEQ + kt * 64 + sr) * (NKV * HD) + kvh * HD + sc;
        uint32_t dst = kB0 + (uint32_t)(buf * KT) * 2 + (uint32_t)(sr * KS + sc) * 2;
#pragma unroll
        for (int it = 0; it < 8; ++it)
            cp16(dst + (uint32_t)(8 * it * KS) * 2, src + (size_t)(8 * it) * (NKV * HD));
    };
    auto stageV = [&](int kt, int buf) {
        const __half* src = g_vh + (size_t)(b * SEQ + kt * 64 + sr) * (NKV * HD) + kvh * HD + sc;
        uint32_t dst = vB0 + (uint32_t)(buf * VT) * 2 + (uint32_t)(sr * VS + sc) * 2;
#pragma unroll
        for (int it = 0; it < 8; ++it)
            cp16(dst + (uint32_t)(8 * it * VS) * 2, src + (size_t)(8 * it) * (NKV * HD));
    };

    // prologue: Q + K0 + V0; ones-column init in both V buffers
    {
        const __half* src = g_qh + (size_t)(b * SEQ + q0 + sr) * (NH * HD) + h * HD + sc;
        uint32_t dst = qB + (uint32_t)(sr * QS + sc) * 2;
#pragma unroll
        for (int it = 0; it < 8; ++it)
            cp16(dst + (uint32_t)(8 * it * QS) * 2, src + (size_t)(8 * it) * (NH * HD));
        stageK(0, 0); stageV(0, 0);
        CP_COMMIT();
        for (int idx = tid; idx < 2 * 64 * 16; idx += 128) {
            int bu = idx >> 10, r = (idx >> 4) & 63, c = idx & 15;
            Vsm[bu * VT + r * VS + 128 + c] = (c == 0) ? __float2half(1.f) : __float2half(0.f);
        }
        CP_WAIT0();
        __syncthreads();
    }

    // hoist Q fragments (loop-invariant)
    uint32_t qf[8][4];
#pragma unroll
    for (int kk = 0; kk < 8; ++kk)
        ldsm4(qf[kk], qAddr + (uint32_t)(kk * 16) * 2);

    float O[17][4];   // 16 hd tiles + 1 l tile
#pragma unroll
    for (int nt = 0; nt < 17; ++nt)
#pragma unroll
        for (int v = 0; v < 4; ++v) O[nt][v] = 0.f;

    for (int kt = 0; kt <= qt; ++kt) {
        // prefetch next K/V immediately (buffer freed by barrier at end of kt-1)
        if (kt < qt) {
            stageK(kt + 1, (kt + 1) & 1);
            stageV(kt + 1, (kt + 1) & 1);
            CP_COMMIT();
        }
        const uint32_t kAddr = kB0 + (uint32_t)((kt & 1) * KT) * 2 + kOff;
        const uint32_t vAddr = vB0 + (uint32_t)((kt & 1) * VT) * 2 + vOff;

        // S = Q K^T
        float s[8][4];
#pragma unroll
        for (int nt = 0; nt < 8; ++nt)
#pragma unroll
            for (int v = 0; v < 4; ++v) s[nt][v] = 0.f;
#pragma unroll
        for (int kk = 0; kk < 8; ++kk) {
            uint32_t bf[4][4];
#pragma unroll
            for (int p = 0; p < 4; ++p)
                ldsm4(bf[p], kAddr + (uint32_t)(p * 16 * KS + kk * 16) * 2);
#pragma unroll
            for (int nt = 0; nt < 8; ++nt)
                mma_f16(s[nt], qf[kk], &bf[nt >> 1][(nt & 1) * 2]);
        }

        // fixed-base softmax -> P fragments in registers
        if (kt == qt) {
#pragma unroll
            for (int nt = 0; nt < 8; ++nt) {
                int cb = nt * 8 + 2 * qq;
                if (cb     > r0l) s[nt][0] = -1e30f;
                if (cb + 1 > r0l) s[nt][1] = -1e30f;
                if (cb     > r1l) s[nt][2] = -1e30f;
                if (cb + 1 > r1l) s[nt][3] = -1e30f;
            }
        }
        uint32_t pa[8], pb[8];
#pragma unroll
        for (int nt = 0; nt < 8; ++nt) {
            pa[nt] = h2u(__floats2half2_rn(exp2f(s[nt][0] - SM_BIAS), exp2f(s[nt][1] - SM_BIAS)));
            pb[nt] = h2u(__floats2half2_rn(exp2f(s[nt][2] - SM_BIAS), exp2f(s[nt][3] - SM_BIAS)));
        }

        // O += P V  (+ l via ones column); P direct from registers
#pragma unroll
        for (int kk = 0; kk < 4; ++kk) {
            uint32_t af[4] = {pa[2 * kk], pb[2 * kk], pa[2 * kk + 1], pb[2 * kk + 1]};
            uint32_t bf[8][4], b8[4];
#pragma unroll
            for (int p = 0; p < 8; ++p)
                ldsm4t(bf[p], vAddr + (uint32_t)(kk * 16 * VS + p * 16) * 2);
            ldsm4t(b8, vAddr + (uint32_t)(kk * 16 * VS + 128) * 2);
#pragma unroll
            for (int nt = 0; nt < 16; ++nt)
                mma_f16(O[nt], af, &bf[nt >> 1][(nt & 1) * 2]);
            mma_f16(O[16], af, &b8[0]);
        }

        if (kt < qt) {
            CP_WAIT0();
            __syncthreads();
        }
    }

    float l0 = __shfl_sync(0xffffffffu, O[16][0], lane & ~3);
    float l1 = __shfl_sync(0xffffffffu, O[16][2], lane & ~3);
    float inv0 = 1.f / l0, inv1 = 1.f / l1;
    __half* y0 = g_yh + (size_t)(b * SEQ + q0 + r0l) * (NH * HD) + h * HD;
    __half* y1 = g_yh + (size_t)(b * SEQ + q0 + r1l) * (NH * HD) + h * HD;
#pragma unroll
    for (int nt = 0; nt < 16; ++nt) {
        *(__half2*)(y0 + nt * 8 + 2 * qq) = __floats2half2_rn(O[nt][0] * inv0, O[nt][1] * inv0);
        *(__half2*)(y1 + nt * 8 + 2 * qq) = __floats2half2_rn(O[nt][2] * inv1, O[nt][3] * inv1);
    }
}

// ---------------------------------------------------------------------------
extern "C" void kernel_launch(void* const* d_in, const int* in_sizes, int n_in,
                              void* d_out, int out_size)
{
    const float* x    = (const float*)d_in[0];
    const float* fr   = (const float*)d_in[1];
    const float* wqkv = (const float*)d_in[3];
    const float* wo   = (const float*)d_in[4];
    const float* qw   = (const float*)d_in[5];
    const float* kw   = (const float*)d_in[6];
    float* out = (float*)d_out;

    __half *yh_p, *xh_p, *wqkvh_p, *woh_p;
    cudaGetSymbolAddress((void**)&yh_p,    g_yh);
    cudaGetSymbolAddress((void**)&xh_p,    g_xh);
    cudaGetSymbolAddress((void**)&wqkvh_p, g_wqkvh);
    cudaGetSymbolAddress((void**)&woh_p,   g_woh);

    // 0) Convert inputs/weights to fp16 (single launch)
    const size_t ntot = N_X + N_W1 + N_W2;
    to_half_all<<<(unsigned)(ntot / 1024), 256>>>(x, wqkv, wo);

    cudaFuncSetAttribute(gemm_hp, cudaFuncAttributeMaxDynamicSharedMemorySize, GSMEM);
    cudaFuncSetAttribute(attn_hp, cudaFuncAttributeMaxDynamicSharedMemorySize, ASMEM);

    // 1) QKV projection + fused RMSNorm/RoPE/scale epilogue
    gemm_hp<<<dim3(EQKV / 128, TOK / 128), 128, GSMEM>>>(
        xh_p, wqkvh_p, nullptr, TOK, EQKV, DMODEL, 1, fr, qw, kw);

    // 2) Causal GQA flash attention
    attn_hp<<<dim3(SEQ / 64, NH, BATCH), 128, ASMEM>>>();

    // 3) Output projection (fp32 out)
    gemm_hp<<<dim3(DMODEL / 128, TOK / 128), 128, GSMEM>>>(
        yh_p, woh_p, out, TOK, DMODEL, DMODEL, 0, nullptr, nullptr, nullptr);
}